// round 1
// baseline (speedup 1.0000x reference)
#include <cuda_runtime.h>
#include <math.h>

#define Bc 2
#define Sc 2048
#define Dc 2048
#define Hc 16
#define HDc 128
#define Lc 10

// Scratch (static device globals — allocation-free per harness rules)
__device__ float g_q[Bc*Sc*Dc];
__device__ float g_k[Bc*Sc*Dc];
__device__ float g_v[Bc*Sc*Dc];
__device__ float g_attn[Bc*Sc*Dc];
__device__ float g_ak[Lc*Dc];
__device__ float g_av[Lc*Dc];

#define SCALE 0.08838834764831845f  // 1/sqrt(128)

// ---------------------------------------------------------------------------
// Tiled fp32 GEMM: C[M,N] = A[M,K] @ W[K,N], all row-major.
// BM=128 BN=128 BK=8, 256 threads, 8x8 micro-tile.
// ---------------------------------------------------------------------------
__global__ __launch_bounds__(256) void sgemm_kernel(
    const float* __restrict__ A, const float* __restrict__ W,
    float* __restrict__ C, int M, int N, int K)
{
    __shared__ float As[8][132];   // [k][m], padded to kill STS conflicts
    __shared__ float Bs[8][128];   // [k][n]

    const int t  = threadIdx.x;
    const int tx = t & 15;         // 0..15  -> n micro
    const int ty = t >> 4;         // 0..15  -> m micro
    const int bm = blockIdx.y * 128;
    const int bn = blockIdx.x * 128;

    const int aRow = t >> 1;             // 0..127
    const int aCol = (t & 1) * 4;        // 0 or 4
    const int bRow = t >> 5;             // 0..7
    const int bCol = (t & 31) * 4;       // 0..124

    float acc[8][8];
    #pragma unroll
    for (int i = 0; i < 8; i++)
        #pragma unroll
        for (int j = 0; j < 8; j++) acc[i][j] = 0.f;

    for (int k0 = 0; k0 < K; k0 += 8) {
        float4 a4 = *(const float4*)&A[(size_t)(bm + aRow) * K + k0 + aCol];
        As[aCol + 0][aRow] = a4.x;
        As[aCol + 1][aRow] = a4.y;
        As[aCol + 2][aRow] = a4.z;
        As[aCol + 3][aRow] = a4.w;
        *(float4*)&Bs[bRow][bCol] =
            *(const float4*)&W[(size_t)(k0 + bRow) * N + bn + bCol];
        __syncthreads();

        #pragma unroll
        for (int kk = 0; kk < 8; kk++) {
            float ar[8], br[8];
            *(float4*)&ar[0] = *(float4*)&As[kk][ty * 8 + 0];
            *(float4*)&ar[4] = *(float4*)&As[kk][ty * 8 + 4];
            *(float4*)&br[0] = *(float4*)&Bs[kk][tx * 8 + 0];
            *(float4*)&br[4] = *(float4*)&Bs[kk][tx * 8 + 4];
            #pragma unroll
            for (int i = 0; i < 8; i++)
                #pragma unroll
                for (int j = 0; j < 8; j++)
                    acc[i][j] += ar[i] * br[j];
        }
        __syncthreads();
    }

    #pragma unroll
    for (int i = 0; i < 8; i++) {
        size_t row = (size_t)(bm + ty * 8 + i) * N + bn + tx * 8;
        *(float4*)&C[row + 0] = *(float4*)&acc[i][0];
        *(float4*)&C[row + 4] = *(float4*)&acc[i][4];
    }
}

// ---------------------------------------------------------------------------
// Adapter projection: C[L,D] = A[L,D] @ W[D,D]
// ---------------------------------------------------------------------------
__global__ __launch_bounds__(256) void small_gemm_kernel(
    const float* __restrict__ A, const float* __restrict__ W,
    float* __restrict__ C)
{
    int n = blockIdx.x * blockDim.x + threadIdx.x;
    int l = blockIdx.y;
    float acc = 0.f;
    #pragma unroll 8
    for (int k = 0; k < Dc; k++)
        acc += A[l * Dc + k] * W[(size_t)k * Dc + n];
    C[l * Dc + n] = acc;
}

// ---------------------------------------------------------------------------
// RoPE in-place on (B,S,H,HD), interleaved pairs.
// ---------------------------------------------------------------------------
__global__ __launch_bounds__(256) void rope_kernel(
    float* __restrict__ d, const float* __restrict__ fc,
    const float* __restrict__ fs)
{
    int idx = blockIdx.x * blockDim.x + threadIdx.x;   // over B*S*H*(HD/2)
    int j = idx & 63;
    int s = ((idx >> 6) / Hc) % Sc;
    float2* p = (float2*)d;
    float2 v = p[idx];
    float c  = fc[s * 64 + j];
    float sn = fs[s * 64 + j];
    p[idx] = make_float2(v.x * c - v.y * sn, v.x * sn + v.y * c);
}

// ---------------------------------------------------------------------------
// Flash attention (fp32, online softmax). BM=BN=64, 256 threads.
// Grid: (S/64, H, B). Reads g_q/g_k/g_v, writes g_attn.
// ---------------------------------------------------------------------------
__global__ __launch_bounds__(256) void flash_kernel()
{
    constexpr int BM = 64, BN = 64, PAD = 65, SCP = 68;
    extern __shared__ float sm[];
    float* q_s = sm;                    // [HD][PAD] transposed
    float* k_s = q_s + HDc * PAD;       // [HD][PAD] transposed
    float* v_s = k_s + HDc * PAD;       // [BN][HD]
    float* sc  = v_s + BN * HDc;        // [BM][SCP]

    const int t = threadIdx.x;
    const int qtile = blockIdx.x, h = blockIdx.y, b = blockIdx.z;
    const int qbase = qtile * BM;

    const size_t qoff = ((size_t)(b * Sc + qbase)) * Dc + h * HDc;

    // load Q transposed: [d][m]
    for (int i = t; i < BM * HDc / 4; i += 256) {
        int row = i >> 5;
        int d4  = (i & 31) << 2;
        float4 v = *(const float4*)(g_q + qoff + (size_t)row * Dc + d4);
        q_s[(d4 + 0) * PAD + row] = v.x;
        q_s[(d4 + 1) * PAD + row] = v.y;
        q_s[(d4 + 2) * PAD + row] = v.z;
        q_s[(d4 + 3) * PAD + row] = v.w;
    }

    const int tx = t & 15, ty = t >> 4;   // QK: 4x4 micro-tile at (4ty, 4tx)
    const int r = t >> 2, qq = t & 3;     // softmax/PV: row r, col chunk 32*qq

    float m_r = -1e30f, l_r = 0.f;
    float acc[32];
    #pragma unroll
    for (int c = 0; c < 32; c++) acc[c] = 0.f;

    const int ntiles = qtile + 1;  // causal
    for (int kt = 0; kt < ntiles; kt++) {
        const int kbase = kt * BN;
        const size_t koff = ((size_t)(b * Sc + kbase)) * Dc + h * HDc;
        __syncthreads();   // prior PV reads complete before overwrite

        for (int i = t; i < BN * HDc / 4; i += 256) {
            int row = i >> 5;
            int d4  = (i & 31) << 2;
            float4 kv = *(const float4*)(g_k + koff + (size_t)row * Dc + d4);
            k_s[(d4 + 0) * PAD + row] = kv.x;
            k_s[(d4 + 1) * PAD + row] = kv.y;
            k_s[(d4 + 2) * PAD + row] = kv.z;
            k_s[(d4 + 3) * PAD + row] = kv.w;
            *(float4*)&v_s[row * HDc + d4] =
                *(const float4*)(g_v + koff + (size_t)row * Dc + d4);
        }
        __syncthreads();

        // S = Q K^T (64x64)
        float sacc[4][4];
        #pragma unroll
        for (int i = 0; i < 4; i++)
            #pragma unroll
            for (int j = 0; j < 4; j++) sacc[i][j] = 0.f;

        for (int d = 0; d < HDc; d++) {
            float qr[4], kr[4];
            #pragma unroll
            for (int i = 0; i < 4; i++) qr[i] = q_s[d * PAD + 4 * ty + i];
            #pragma unroll
            for (int j = 0; j < 4; j++) kr[j] = k_s[d * PAD + 4 * tx + j];
            #pragma unroll
            for (int i = 0; i < 4; i++)
                #pragma unroll
                for (int j = 0; j < 4; j++)
                    sacc[i][j] += qr[i] * kr[j];
        }
        #pragma unroll
        for (int i = 0; i < 4; i++) {
            int qg = qbase + 4 * ty + i;
            #pragma unroll
            for (int j = 0; j < 4; j++) {
                int kg = kbase + 4 * tx + j;
                float s = sacc[i][j] * SCALE;
                if (kg > qg) s -= 1e9f;
                sc[(4 * ty + i) * SCP + 4 * tx + j] = s;
            }
        }
        __syncthreads();

        // online softmax update (row r, elements 16*qq..+15)
        float vals[16];
        float tmax = -1e30f;
        #pragma unroll
        for (int kk = 0; kk < 16; kk++) {
            vals[kk] = sc[r * SCP + 16 * qq + kk];
            tmax = fmaxf(tmax, vals[kk]);
        }
        tmax = fmaxf(tmax, __shfl_xor_sync(0xffffffffu, tmax, 1));
        tmax = fmaxf(tmax, __shfl_xor_sync(0xffffffffu, tmax, 2));
        float new_m = fmaxf(m_r, tmax);
        float corr = expf(m_r - new_m);
        float psum = 0.f;
        #pragma unroll
        for (int kk = 0; kk < 16; kk++) {
            float p = expf(vals[kk] - new_m);
            sc[r * SCP + 16 * qq + kk] = p;
            psum += p;
        }
        psum += __shfl_xor_sync(0xffffffffu, psum, 1);
        psum += __shfl_xor_sync(0xffffffffu, psum, 2);
        l_r = l_r * corr + psum;
        m_r = new_m;
        #pragma unroll
        for (int c = 0; c < 32; c++) acc[c] *= corr;
        __syncwarp();   // quartet wrote p for row r; PV reads them

        // O += P V
        for (int n = 0; n < BN; n++) {
            float p = sc[r * SCP + n];
            const float* vrow = &v_s[n * HDc + 32 * qq];
            #pragma unroll
            for (int c4 = 0; c4 < 8; c4++) {
                float4 v4 = *(const float4*)(vrow + 4 * c4);
                acc[4 * c4 + 0] += p * v4.x;
                acc[4 * c4 + 1] += p * v4.y;
                acc[4 * c4 + 2] += p * v4.z;
                acc[4 * c4 + 3] += p * v4.w;
            }
        }
    }

    float inv = 1.f / l_r;
    size_t obase = ((size_t)(b * Sc + qbase + r)) * Dc + h * HDc + 32 * qq;
    #pragma unroll
    for (int c4 = 0; c4 < 8; c4++) {
        float4 o;
        o.x = acc[4 * c4 + 0] * inv;
        o.y = acc[4 * c4 + 1] * inv;
        o.z = acc[4 * c4 + 2] * inv;
        o.w = acc[4 * c4 + 3] * inv;
        *(float4*)(g_attn + obase + 4 * c4) = o;
    }
}

// ---------------------------------------------------------------------------
// Adapter attention: one warp per (b,s,h). out += gate[h] * softmax(q·akᵀ) av
// ---------------------------------------------------------------------------
__global__ __launch_bounds__(256) void adapter_attn_kernel(
    const float* __restrict__ gate)
{
    int gw = (blockIdx.x * blockDim.x + threadIdx.x) >> 5;
    int lane = threadIdx.x & 31;
    if (gw >= Bc * Sc * Hc) return;
    int h = gw % Hc;
    int s = (gw / Hc) % Sc;
    int b = gw / (Hc * Sc);

    size_t qoff = ((size_t)(b * Sc + s)) * Dc + h * HDc + lane * 4;
    float4 q4 = *(const float4*)(g_q + qoff);

    float scv[Lc];
    #pragma unroll
    for (int l = 0; l < Lc; l++) {
        float4 a4 = *(const float4*)(g_ak + (size_t)l * Dc + h * HDc + lane * 4);
        float p = q4.x * a4.x + q4.y * a4.y + q4.z * a4.z + q4.w * a4.w;
        #pragma unroll
        for (int o = 16; o > 0; o >>= 1)
            p += __shfl_xor_sync(0xffffffffu, p, o);
        scv[l] = p * SCALE;
    }
    float m = scv[0];
    #pragma unroll
    for (int l = 1; l < Lc; l++) m = fmaxf(m, scv[l]);
    float sum = 0.f;
    float e[Lc];
    #pragma unroll
    for (int l = 0; l < Lc; l++) { e[l] = expf(scv[l] - m); sum += e[l]; }
    float g = gate[h] / sum;

    float4 acc = make_float4(0.f, 0.f, 0.f, 0.f);
    #pragma unroll
    for (int l = 0; l < Lc; l++) {
        float4 a4 = *(const float4*)(g_av + (size_t)l * Dc + h * HDc + lane * 4);
        acc.x += e[l] * a4.x;
        acc.y += e[l] * a4.y;
        acc.z += e[l] * a4.z;
        acc.w += e[l] * a4.w;
    }
    float4 cur = *(float4*)(g_attn + qoff);
    cur.x += g * acc.x;
    cur.y += g * acc.y;
    cur.z += g * acc.z;
    cur.w += g * acc.w;
    *(float4*)(g_attn + qoff) = cur;
}

// ---------------------------------------------------------------------------
extern "C" void kernel_launch(void* const* d_in, const int* in_sizes, int n_in,
                              void* d_out, int out_size)
{
    const float* x       = (const float*)d_in[0];
    const float* wq      = (const float*)d_in[1];
    const float* wk      = (const float*)d_in[2];
    const float* wv      = (const float*)d_in[3];
    const float* wo      = (const float*)d_in[4];
    const float* adapter = (const float*)d_in[5];
    const float* gate    = (const float*)d_in[6];
    const float* fcos    = (const float*)d_in[7];
    const float* fsin    = (const float*)d_in[8];
    // d_in[9] mask: exactly causal triu(-1e9) — applied inline in flash_kernel
    float* out = (float*)d_out;

    float *q, *k, *v, *attn, *ak, *av;
    cudaGetSymbolAddress((void**)&q,    g_q);
    cudaGetSymbolAddress((void**)&k,    g_k);
    cudaGetSymbolAddress((void**)&v,    g_v);
    cudaGetSymbolAddress((void**)&attn, g_attn);
    cudaGetSymbolAddress((void**)&ak,   g_ak);
    cudaGetSymbolAddress((void**)&av,   g_av);

    const int M = Bc * Sc;   // 4096
    dim3 ggrid(Dc / 128, M / 128);

    sgemm_kernel<<<ggrid, 256>>>(x, wq, q, M, Dc, Dc);
    sgemm_kernel<<<ggrid, 256>>>(x, wk, k, M, Dc, Dc);
    sgemm_kernel<<<ggrid, 256>>>(x, wv, v, M, Dc, Dc);

    int npairs = Bc * Sc * Hc * (HDc / 2);
    rope_kernel<<<npairs / 256, 256>>>(q, fcos, fsin);
    rope_kernel<<<npairs / 256, 256>>>(k, fcos, fsin);

    small_gemm_kernel<<<dim3(Dc / 256, Lc), 256>>>(adapter, wk, ak);
    small_gemm_kernel<<<dim3(Dc / 256, Lc), 256>>>(adapter, wv, av);

    size_t smem = (size_t)(128 * 65 + 128 * 65 + 64 * 128 + 64 * 68) * 4;
    cudaFuncSetAttribute(flash_kernel,
                         cudaFuncAttributeMaxDynamicSharedMemorySize,
                         (int)smem);
    flash_kernel<<<dim3(Sc / 64, Hc, Bc), 256, smem>>>();

    adapter_attn_kernel<<<(Bc * Sc * Hc * 32) / 256, 256>>>(gate);

    sgemm_kernel<<<ggrid, 256>>>(attn, wo, out, M, Dc, Dc);
}

// round 3
// speedup vs baseline: 1.2388x; 1.2388x over previous
#include <cuda_runtime.h>
#include <cuda_bf16.h>
#include <math.h>
#include <stdint.h>

#define Bc 2
#define Sc 2048
#define Dc 2048
#define Hc 16
#define HDc 128
#define Lc 10

// Scratch (static device globals — allocation-free per harness rules)
__device__ float g_q[Bc*Sc*Dc];
__device__ float g_k[Bc*Sc*Dc];
__device__ float g_v[Bc*Sc*Dc];
__device__ float g_attn[Bc*Sc*Dc];
__device__ float g_ak[Lc*Dc];
__device__ float g_av[Lc*Dc];
__device__ float g_partial[Lc*16*Dc];
// bf16 split scratch
__device__ __nv_bfloat16 g_xh[Bc*Sc*Dc];
__device__ __nv_bfloat16 g_xl[Bc*Sc*Dc];
__device__ __nv_bfloat16 g_wth[Dc*Dc];   // W^T hi  [N][K]
__device__ __nv_bfloat16 g_wtl[Dc*Dc];   // W^T lo  [N][K]

#define SCALE 0.08838834764831845f  // 1/sqrt(128)

// ---------------------------------------------------------------------------
// mma.sync m16n8k16 bf16 (baseline PTX, works on non-'a' sm_103 target)
// ---------------------------------------------------------------------------
#define MMA16816(c, a0, a1, a2, a3, b0, b1) \
    asm volatile( \
        "mma.sync.aligned.m16n8k16.row.col.f32.bf16.bf16.f32 " \
        "{%0,%1,%2,%3}, {%4,%5,%6,%7}, {%8,%9}, {%0,%1,%2,%3};" \
        : "+f"((c)[0]), "+f"((c)[1]), "+f"((c)[2]), "+f"((c)[3]) \
        : "r"(a0), "r"(a1), "r"(a2), "r"(a3), "r"(b0), "r"(b1))

// ---------------------------------------------------------------------------
// Elementwise fp32 -> bf16 hi/lo split (4 elems per thread)
// ---------------------------------------------------------------------------
__global__ __launch_bounds__(256) void split_kernel(
    const float* __restrict__ x, __nv_bfloat16* __restrict__ h,
    __nv_bfloat16* __restrict__ l)
{
    int i = blockIdx.x * 256 + threadIdx.x;
    float4 v = ((const float4*)x)[i];
    __nv_bfloat162 h01, h23, l01, l23;
    h01.x = __float2bfloat16(v.x);
    h01.y = __float2bfloat16(v.y);
    h23.x = __float2bfloat16(v.z);
    h23.y = __float2bfloat16(v.w);
    l01.x = __float2bfloat16(v.x - __bfloat162float(h01.x));
    l01.y = __float2bfloat16(v.y - __bfloat162float(h01.y));
    l23.x = __float2bfloat16(v.z - __bfloat162float(h23.x));
    l23.y = __float2bfloat16(v.w - __bfloat162float(h23.y));
    ((__nv_bfloat162*)h)[i * 2 + 0] = h01;
    ((__nv_bfloat162*)h)[i * 2 + 1] = h23;
    ((__nv_bfloat162*)l)[i * 2 + 0] = l01;
    ((__nv_bfloat162*)l)[i * 2 + 1] = l23;
}

// ---------------------------------------------------------------------------
// Transpose + split: W[K][N] f32 -> Th/Tl[N][K] bf16
// ---------------------------------------------------------------------------
__global__ __launch_bounds__(256) void wtrans_kernel(
    const float* __restrict__ W, __nv_bfloat16* __restrict__ Th,
    __nv_bfloat16* __restrict__ Tl, int K, int N)
{
    __shared__ float tile[32][33];
    const int k0 = blockIdx.x * 32, n0 = blockIdx.y * 32;
    const int t = threadIdx.x;
    const int r = t >> 5, c = t & 31;
    #pragma unroll
    for (int i = 0; i < 4; i++)
        tile[r + i * 8][c] = W[(size_t)(k0 + r + i * 8) * N + n0 + c];
    __syncthreads();
    #pragma unroll
    for (int i = 0; i < 4; i++) {
        int n = r + i * 8;
        float v = tile[c][n];
        __nv_bfloat16 h = __float2bfloat16(v);
        Th[(size_t)(n0 + n) * K + k0 + c] = h;
        Tl[(size_t)(n0 + n) * K + k0 + c] =
            __float2bfloat16(v - __bfloat162float(h));
    }
}

// ---------------------------------------------------------------------------
// bf16x3 tensor-core GEMM: C[M,N] = A[M,K] @ W[K,N]
// Inputs pre-split: Ah/Al row-major [M][K], BhT/BlT row-major [N][K] (=W^T).
// CTA 128x128, BK=32, 8 warps (2m x 4n), warp tile 64x32.
// ---------------------------------------------------------------------------
#define SROW 40   // smem row stride in bf16 (80 B, 16B-aligned, conflict-free frags)

__global__ __launch_bounds__(256) void mma_gemm_kernel(
    const __nv_bfloat16* __restrict__ Ah, const __nv_bfloat16* __restrict__ Al,
    const __nv_bfloat16* __restrict__ BhT, const __nv_bfloat16* __restrict__ BlT,
    float* __restrict__ C, int M, int N, int K)
{
    __shared__ __align__(16) __nv_bfloat16 sAh[128 * SROW];
    __shared__ __align__(16) __nv_bfloat16 sAl[128 * SROW];
    __shared__ __align__(16) __nv_bfloat16 sBh[128 * SROW];
    __shared__ __align__(16) __nv_bfloat16 sBl[128 * SROW];

    const int t = threadIdx.x, lane = t & 31, wid = t >> 5;
    const int wm = wid & 1, wn = wid >> 1;
    const int bm = blockIdx.y * 128, bn = blockIdx.x * 128;
    const int gid = lane >> 2, tig = lane & 3;

    float acc[4][4][4];
    #pragma unroll
    for (int a = 0; a < 4; a++)
        #pragma unroll
        for (int b = 0; b < 4; b++)
            #pragma unroll
            for (int cc = 0; cc < 4; cc++) acc[a][b][cc] = 0.f;

    for (int k0 = 0; k0 < K; k0 += 32) {
        // Load tiles: 128 rows x 32 bf16 = 512 x 16B chunks per array.
        #pragma unroll
        for (int i = 0; i < 2; i++) {
            int u = t + i * 256;
            int row = u >> 2, ch = (u & 3) * 8;
            size_t ga = (size_t)(bm + row) * K + k0 + ch;
            size_t gb = (size_t)(bn + row) * K + k0 + ch;
            *(uint4*)&sAh[row * SROW + ch] = *(const uint4*)&Ah[ga];
            *(uint4*)&sAl[row * SROW + ch] = *(const uint4*)&Al[ga];
            *(uint4*)&sBh[row * SROW + ch] = *(const uint4*)&BhT[gb];
            *(uint4*)&sBl[row * SROW + ch] = *(const uint4*)&BlT[gb];
        }
        __syncthreads();

        #pragma unroll
        for (int ks = 0; ks < 2; ks++) {
            const int ak = ks * 16 + tig * 2;
            uint32_t ah[4][4], al[4][4];
            #pragma unroll
            for (int mt = 0; mt < 4; mt++) {
                const __nv_bfloat16* p = &sAh[(wm * 64 + mt * 16 + gid) * SROW + ak];
                ah[mt][0] = *(const uint32_t*)p;
                ah[mt][1] = *(const uint32_t*)(p + 8 * SROW);
                ah[mt][2] = *(const uint32_t*)(p + 8);
                ah[mt][3] = *(const uint32_t*)(p + 8 * SROW + 8);
                const __nv_bfloat16* q = &sAl[(wm * 64 + mt * 16 + gid) * SROW + ak];
                al[mt][0] = *(const uint32_t*)q;
                al[mt][1] = *(const uint32_t*)(q + 8 * SROW);
                al[mt][2] = *(const uint32_t*)(q + 8);
                al[mt][3] = *(const uint32_t*)(q + 8 * SROW + 8);
            }
            #pragma unroll
            for (int nt = 0; nt < 4; nt++) {
                const int brow = wn * 32 + nt * 8 + gid;
                const __nv_bfloat16* p = &sBh[brow * SROW + ak];
                uint32_t bh0 = *(const uint32_t*)p;
                uint32_t bh1 = *(const uint32_t*)(p + 8);
                const __nv_bfloat16* q = &sBl[brow * SROW + ak];
                uint32_t bl0 = *(const uint32_t*)q;
                uint32_t bl1 = *(const uint32_t*)(q + 8);
                #pragma unroll
                for (int mt = 0; mt < 4; mt++) {
                    MMA16816(acc[mt][nt], ah[mt][0], ah[mt][1], ah[mt][2], ah[mt][3], bh0, bh1);
                    MMA16816(acc[mt][nt], ah[mt][0], ah[mt][1], ah[mt][2], ah[mt][3], bl0, bl1);
                    MMA16816(acc[mt][nt], al[mt][0], al[mt][1], al[mt][2], al[mt][3], bh0, bh1);
                }
            }
        }
        __syncthreads();
    }

    // Epilogue
    #pragma unroll
    for (int mt = 0; mt < 4; mt++) {
        int row = bm + wm * 64 + mt * 16 + gid;
        #pragma unroll
        for (int nt = 0; nt < 4; nt++) {
            int col = bn + wn * 32 + nt * 8 + tig * 2;
            *(float2*)&C[(size_t)row * N + col] =
                make_float2(acc[mt][nt][0], acc[mt][nt][1]);
            *(float2*)&C[(size_t)(row + 8) * N + col] =
                make_float2(acc[mt][nt][2], acc[mt][nt][3]);
        }
    }
}

// ---------------------------------------------------------------------------
// Adapter projection, deterministic 2-pass k-split
// ---------------------------------------------------------------------------
__global__ __launch_bounds__(256) void adapter_proj_kernel(
    const float* __restrict__ A, const float* __restrict__ W,
    float* __restrict__ P)
{
    const int ks = blockIdx.x;   // 0..15
    const int l  = blockIdx.y;   // 0..Lc-1
    const int t  = threadIdx.x;
    float acc[8];
    #pragma unroll
    for (int i = 0; i < 8; i++) acc[i] = 0.f;
    for (int k = ks * 128; k < ks * 128 + 128; k++) {
        float a = A[l * Dc + k];
        const float* wr = &W[(size_t)k * Dc + t * 8];
        float4 w0 = *(const float4*)wr;
        float4 w1 = *(const float4*)(wr + 4);
        acc[0] += a * w0.x; acc[1] += a * w0.y;
        acc[2] += a * w0.z; acc[3] += a * w0.w;
        acc[4] += a * w1.x; acc[5] += a * w1.y;
        acc[6] += a * w1.z; acc[7] += a * w1.w;
    }
    float* o = &P[((size_t)l * 16 + ks) * Dc + t * 8];
    *(float4*)o       = make_float4(acc[0], acc[1], acc[2], acc[3]);
    *(float4*)(o + 4) = make_float4(acc[4], acc[5], acc[6], acc[7]);
}

__global__ __launch_bounds__(256) void adapter_reduce_kernel(
    const float* __restrict__ P, float* __restrict__ C)
{
    int idx = blockIdx.x * 256 + threadIdx.x;   // over Lc*Dc
    int l = idx >> 11, n = idx & 2047;
    float s = 0.f;
    #pragma unroll
    for (int ks = 0; ks < 16; ks++)
        s += P[((size_t)l * 16 + ks) * Dc + n];
    C[idx] = s;
}

// ---------------------------------------------------------------------------
// RoPE in-place on (B,S,H,HD), interleaved pairs.
// ---------------------------------------------------------------------------
__global__ __launch_bounds__(256) void rope_kernel(
    float* __restrict__ d, const float* __restrict__ fc,
    const float* __restrict__ fs)
{
    int idx = blockIdx.x * blockDim.x + threadIdx.x;   // over B*S*H*(HD/2)
    int j = idx & 63;
    int s = ((idx >> 6) / Hc) % Sc;
    float2* p = (float2*)d;
    float2 v = p[idx];
    float c  = fc[s * 64 + j];
    float sn = fs[s * 64 + j];
    p[idx] = make_float2(v.x * c - v.y * sn, v.x * sn + v.y * c);
}

// ---------------------------------------------------------------------------
// Flash attention (fp32, online softmax). BM=BN=64, 256 threads.
// ---------------------------------------------------------------------------
__global__ __launch_bounds__(256) void flash_kernel()
{
    constexpr int BM = 64, BN = 64, PAD = 65, SCP = 68;
    extern __shared__ float sm[];
    float* q_s = sm;                    // [HD][PAD] transposed
    float* k_s = q_s + HDc * PAD;       // [HD][PAD] transposed
    float* v_s = k_s + HDc * PAD;       // [BN][HD]
    float* sc  = v_s + BN * HDc;        // [BM][SCP]

    const int t = threadIdx.x;
    const int qtile = blockIdx.x, h = blockIdx.y, b = blockIdx.z;
    const int qbase = qtile * BM;

    const size_t qoff = ((size_t)(b * Sc + qbase)) * Dc + h * HDc;

    for (int i = t; i < BM * HDc / 4; i += 256) {
        int row = i >> 5;
        int d4  = (i & 31) << 2;
        float4 v = *(const float4*)(g_q + qoff + (size_t)row * Dc + d4);
        q_s[(d4 + 0) * PAD + row] = v.x;
        q_s[(d4 + 1) * PAD + row] = v.y;
        q_s[(d4 + 2) * PAD + row] = v.z;
        q_s[(d4 + 3) * PAD + row] = v.w;
    }

    const int tx = t & 15, ty = t >> 4;
    const int r = t >> 2, qq = t & 3;

    float m_r = -1e30f, l_r = 0.f;
    float acc[32];
    #pragma unroll
    for (int c = 0; c < 32; c++) acc[c] = 0.f;

    const int ntiles = qtile + 1;  // causal
    for (int kt = 0; kt < ntiles; kt++) {
        const int kbase = kt * BN;
        const size_t koff = ((size_t)(b * Sc + kbase)) * Dc + h * HDc;
        __syncthreads();

        for (int i = t; i < BN * HDc / 4; i += 256) {
            int row = i >> 5;
            int d4  = (i & 31) << 2;
            float4 kv = *(const float4*)(g_k + koff + (size_t)row * Dc + d4);
            k_s[(d4 + 0) * PAD + row] = kv.x;
            k_s[(d4 + 1) * PAD + row] = kv.y;
            k_s[(d4 + 2) * PAD + row] = kv.z;
            k_s[(d4 + 3) * PAD + row] = kv.w;
            *(float4*)&v_s[row * HDc + d4] =
                *(const float4*)(g_v + koff + (size_t)row * Dc + d4);
        }
        __syncthreads();

        float sacc[4][4];
        #pragma unroll
        for (int i = 0; i < 4; i++)
            #pragma unroll
            for (int j = 0; j < 4; j++) sacc[i][j] = 0.f;

        for (int d = 0; d < HDc; d++) {
            float qr[4], kr[4];
            #pragma unroll
            for (int i = 0; i < 4; i++) qr[i] = q_s[d * PAD + 4 * ty + i];
            #pragma unroll
            for (int j = 0; j < 4; j++) kr[j] = k_s[d * PAD + 4 * tx + j];
            #pragma unroll
            for (int i = 0; i < 4; i++)
                #pragma unroll
                for (int j = 0; j < 4; j++)
                    sacc[i][j] += qr[i] * kr[j];
        }
        #pragma unroll
        for (int i = 0; i < 4; i++) {
            int qg = qbase + 4 * ty + i;
            #pragma unroll
            for (int j = 0; j < 4; j++) {
                int kg = kbase + 4 * tx + j;
                float s = sacc[i][j] * SCALE;
                if (kg > qg) s -= 1e9f;
                sc[(4 * ty + i) * SCP + 4 * tx + j] = s;
            }
        }
        __syncthreads();

        float vals[16];
        float tmax = -1e30f;
        #pragma unroll
        for (int kk = 0; kk < 16; kk++) {
            vals[kk] = sc[r * SCP + 16 * qq + kk];
            tmax = fmaxf(tmax, vals[kk]);
        }
        tmax = fmaxf(tmax, __shfl_xor_sync(0xffffffffu, tmax, 1));
        tmax = fmaxf(tmax, __shfl_xor_sync(0xffffffffu, tmax, 2));
        float new_m = fmaxf(m_r, tmax);
        float corr = expf(m_r - new_m);
        float psum = 0.f;
        #pragma unroll
        for (int kk = 0; kk < 16; kk++) {
            float p = expf(vals[kk] - new_m);
            sc[r * SCP + 16 * qq + kk] = p;
            psum += p;
        }
        psum += __shfl_xor_sync(0xffffffffu, psum, 1);
        psum += __shfl_xor_sync(0xffffffffu, psum, 2);
        l_r = l_r * corr + psum;
        m_r = new_m;
        #pragma unroll
        for (int c = 0; c < 32; c++) acc[c] *= corr;
        __syncwarp();

        for (int n = 0; n < BN; n++) {
            float p = sc[r * SCP + n];
            const float* vrow = &v_s[n * HDc + 32 * qq];
            #pragma unroll
            for (int c4 = 0; c4 < 8; c4++) {
                float4 v4 = *(const float4*)(vrow + 4 * c4);
                acc[4 * c4 + 0] += p * v4.x;
                acc[4 * c4 + 1] += p * v4.y;
                acc[4 * c4 + 2] += p * v4.z;
                acc[4 * c4 + 3] += p * v4.w;
            }
        }
    }

    float inv = 1.f / l_r;
    size_t obase = ((size_t)(b * Sc + qbase + r)) * Dc + h * HDc + 32 * qq;
    #pragma unroll
    for (int c4 = 0; c4 < 8; c4++) {
        float4 o;
        o.x = acc[4 * c4 + 0] * inv;
        o.y = acc[4 * c4 + 1] * inv;
        o.z = acc[4 * c4 + 2] * inv;
        o.w = acc[4 * c4 + 3] * inv;
        *(float4*)(g_attn + obase + 4 * c4) = o;
    }
}

// ---------------------------------------------------------------------------
// Adapter attention: one warp per (b,s,h). out += gate[h] * softmax(q·akᵀ) av
// ---------------------------------------------------------------------------
__global__ __launch_bounds__(256) void adapter_attn_kernel(
    const float* __restrict__ gate)
{
    int gw = (blockIdx.x * blockDim.x + threadIdx.x) >> 5;
    int lane = threadIdx.x & 31;
    if (gw >= Bc * Sc * Hc) return;
    int h = gw % Hc;
    int s = (gw / Hc) % Sc;
    int b = gw / (Hc * Sc);

    size_t qoff = ((size_t)(b * Sc + s)) * Dc + h * HDc + lane * 4;
    float4 q4 = *(const float4*)(g_q + qoff);

    float scv[Lc];
    #pragma unroll
    for (int l = 0; l < Lc; l++) {
        float4 a4 = *(const float4*)(g_ak + (size_t)l * Dc + h * HDc + lane * 4);
        float p = q4.x * a4.x + q4.y * a4.y + q4.z * a4.z + q4.w * a4.w;
        #pragma unroll
        for (int o = 16; o > 0; o >>= 1)
            p += __shfl_xor_sync(0xffffffffu, p, o);
        scv[l] = p * SCALE;
    }
    float m = scv[0];
    #pragma unroll
    for (int l = 1; l < Lc; l++) m = fmaxf(m, scv[l]);
    float sum = 0.f;
    float e[Lc];
    #pragma unroll
    for (int l = 0; l < Lc; l++) { e[l] = expf(scv[l] - m); sum += e[l]; }
    float g = gate[h] / sum;

    float4 acc = make_float4(0.f, 0.f, 0.f, 0.f);
    #pragma unroll
    for (int l = 0; l < Lc; l++) {
        float4 a4 = *(const float4*)(g_av + (size_t)l * Dc + h * HDc + lane * 4);
        acc.x += e[l] * a4.x;
        acc.y += e[l] * a4.y;
        acc.z += e[l] * a4.z;
        acc.w += e[l] * a4.w;
    }
    float4 cur = *(float4*)(g_attn + qoff);
    cur.x += g * acc.x;
    cur.y += g * acc.y;
    cur.z += g * acc.z;
    cur.w += g * acc.w;
    *(float4*)(g_attn + qoff) = cur;
}

// ---------------------------------------------------------------------------
extern "C" void kernel_launch(void* const* d_in, const int* in_sizes, int n_in,
                              void* d_out, int out_size)
{
    const float* x       = (const float*)d_in[0];
    const float* wq      = (const float*)d_in[1];
    const float* wk      = (const float*)d_in[2];
    const float* wv      = (const float*)d_in[3];
    const float* wo      = (const float*)d_in[4];
    const float* adapter = (const float*)d_in[5];
    const float* gate    = (const float*)d_in[6];
    const float* fcos    = (const float*)d_in[7];
    const float* fsin    = (const float*)d_in[8];
    // d_in[9] mask: exactly causal triu(-1e9) — applied inline in flash_kernel
    float* out = (float*)d_out;

    float *q, *k, *v, *attn, *ak, *av, *part;
    __nv_bfloat16 *xh, *xl, *wth, *wtl;
    cudaGetSymbolAddress((void**)&q,    g_q);
    cudaGetSymbolAddress((void**)&k,    g_k);
    cudaGetSymbolAddress((void**)&v,    g_v);
    cudaGetSymbolAddress((void**)&attn, g_attn);
    cudaGetSymbolAddress((void**)&ak,   g_ak);
    cudaGetSymbolAddress((void**)&av,   g_av);
    cudaGetSymbolAddress((void**)&part, g_partial);
    cudaGetSymbolAddress((void**)&xh,   g_xh);
    cudaGetSymbolAddress((void**)&xl,   g_xl);
    cudaGetSymbolAddress((void**)&wth,  g_wth);
    cudaGetSymbolAddress((void**)&wtl,  g_wtl);

    const int M = Bc * Sc;   // 4096
    dim3 ggrid(Dc / 128, M / 128);   // (16, 32)
    dim3 wgrid(Dc / 32, Dc / 32);    // (64, 64)

    // split x -> bf16 hi/lo
    split_kernel<<<(M * Dc / 4) / 256, 256>>>(x, xh, xl);

    // Q/K/V projections on tensor cores
    wtrans_kernel<<<wgrid, 256>>>(wq, wth, wtl, Dc, Dc);
    mma_gemm_kernel<<<ggrid, 256>>>(xh, xl, wth, wtl, q, M, Dc, Dc);
    wtrans_kernel<<<wgrid, 256>>>(wk, wth, wtl, Dc, Dc);
    mma_gemm_kernel<<<ggrid, 256>>>(xh, xl, wth, wtl, k, M, Dc, Dc);
    wtrans_kernel<<<wgrid, 256>>>(wv, wth, wtl, Dc, Dc);
    mma_gemm_kernel<<<ggrid, 256>>>(xh, xl, wth, wtl, v, M, Dc, Dc);

    int npairs = Bc * Sc * Hc * (HDc / 2);
    rope_kernel<<<npairs / 256, 256>>>(q, fcos, fsin);
    rope_kernel<<<npairs / 256, 256>>>(k, fcos, fsin);

    adapter_proj_kernel<<<dim3(16, Lc), 256>>>(adapter, wk, part);
    adapter_reduce_kernel<<<(Lc * Dc) / 256, 256>>>(part, ak);
    adapter_proj_kernel<<<dim3(16, Lc), 256>>>(adapter, wv, part);
    adapter_reduce_kernel<<<(Lc * Dc) / 256, 256>>>(part, av);

    size_t smem = (size_t)(128 * 65 + 128 * 65 + 64 * 128 + 64 * 68) * 4;
    cudaFuncSetAttribute(flash_kernel,
                         cudaFuncAttributeMaxDynamicSharedMemorySize,
                         (int)smem);
    flash_kernel<<<dim3(Sc / 64, Hc, Bc), 256, smem>>>();

    adapter_attn_kernel<<<(Bc * Sc * Hc * 32) / 256, 256>>>(gate);

    // Output projection: split attn, transpose wo, GEMM -> out
    split_kernel<<<(M * Dc / 4) / 256, 256>>>(attn, xh, xl);
    wtrans_kernel<<<wgrid, 256>>>(wo, wth, wtl, Dc, Dc);
    mma_gemm_kernel<<<ggrid, 256>>>(xh, xl, wth, wtl, out, M, Dc, Dc);
}

// round 4
// speedup vs baseline: 3.7172x; 3.0007x over previous
#include <cuda_runtime.h>
#include <cuda_bf16.h>
#include <math.h>
#include <stdint.h>

#define Bc 2
#define Sc 2048
#define Dc 2048
#define Hc 16
#define HDc 128
#define Lc 10

// Scratch (static device globals — allocation-free per harness rules)
__device__ float g_q[Bc*Sc*Dc];
__device__ float g_k[Bc*Sc*Dc];
__device__ float g_v[Bc*Sc*Dc];
__device__ float g_attn[Bc*Sc*Dc];
__device__ float g_ak[Lc*Dc];
__device__ float g_av[Lc*Dc];
__device__ float g_partial[Lc*16*Dc];
// bf16 split scratch
__device__ __nv_bfloat16 g_xh[Bc*Sc*Dc];
__device__ __nv_bfloat16 g_xl[Bc*Sc*Dc];
__device__ __nv_bfloat16 g_wth[Dc*Dc];   // W^T hi  [N][K]
__device__ __nv_bfloat16 g_wtl[Dc*Dc];   // W^T lo  [N][K]
__device__ __nv_bfloat16 g_qh[Bc*Sc*Dc];
__device__ __nv_bfloat16 g_ql[Bc*Sc*Dc];
__device__ __nv_bfloat16 g_kh[Bc*Sc*Dc];
__device__ __nv_bfloat16 g_kl[Bc*Sc*Dc];
__device__ __nv_bfloat16 g_vth[Bc*Sc*Dc];  // [B,H,HD,S]
__device__ __nv_bfloat16 g_vtl[Bc*Sc*Dc];  // [B,H,HD,S]

#define SCALE 0.08838834764831845f  // 1/sqrt(128)

// ---------------------------------------------------------------------------
// mma.sync m16n8k16 bf16 (baseline PTX, works on non-'a' sm_103 target)
// ---------------------------------------------------------------------------
#define MMA16816(c, a0, a1, a2, a3, b0, b1) \
    asm volatile( \
        "mma.sync.aligned.m16n8k16.row.col.f32.bf16.bf16.f32 " \
        "{%0,%1,%2,%3}, {%4,%5,%6,%7}, {%8,%9}, {%0,%1,%2,%3};" \
        : "+f"((c)[0]), "+f"((c)[1]), "+f"((c)[2]), "+f"((c)[3]) \
        : "r"(a0), "r"(a1), "r"(a2), "r"(a3), "r"(b0), "r"(b1))

// ---------------------------------------------------------------------------
// Elementwise fp32 -> bf16 hi/lo split (4 elems per thread)
// ---------------------------------------------------------------------------
__global__ __launch_bounds__(256) void split_kernel(
    const float* __restrict__ x, __nv_bfloat16* __restrict__ h,
    __nv_bfloat16* __restrict__ l)
{
    int i = blockIdx.x * 256 + threadIdx.x;
    float4 v = ((const float4*)x)[i];
    __nv_bfloat162 h01, h23, l01, l23;
    h01.x = __float2bfloat16(v.x);
    h01.y = __float2bfloat16(v.y);
    h23.x = __float2bfloat16(v.z);
    h23.y = __float2bfloat16(v.w);
    l01.x = __float2bfloat16(v.x - __bfloat162float(h01.x));
    l01.y = __float2bfloat16(v.y - __bfloat162float(h01.y));
    l23.x = __float2bfloat16(v.z - __bfloat162float(h23.x));
    l23.y = __float2bfloat16(v.w - __bfloat162float(h23.y));
    ((__nv_bfloat162*)h)[i * 2 + 0] = h01;
    ((__nv_bfloat162*)h)[i * 2 + 1] = h23;
    ((__nv_bfloat162*)l)[i * 2 + 0] = l01;
    ((__nv_bfloat162*)l)[i * 2 + 1] = l23;
}

// ---------------------------------------------------------------------------
// Transpose + split: W[K][N] f32 -> Th/Tl[N][K] bf16
// ---------------------------------------------------------------------------
__global__ __launch_bounds__(256) void wtrans_kernel(
    const float* __restrict__ W, __nv_bfloat16* __restrict__ Th,
    __nv_bfloat16* __restrict__ Tl, int K, int N)
{
    __shared__ float tile[32][33];
    const int k0 = blockIdx.x * 32, n0 = blockIdx.y * 32;
    const int t = threadIdx.x;
    const int r = t >> 5, c = t & 31;
    #pragma unroll
    for (int i = 0; i < 4; i++)
        tile[r + i * 8][c] = W[(size_t)(k0 + r + i * 8) * N + n0 + c];
    __syncthreads();
    #pragma unroll
    for (int i = 0; i < 4; i++) {
        int n = r + i * 8;
        float v = tile[c][n];
        __nv_bfloat16 h = __float2bfloat16(v);
        Th[(size_t)(n0 + n) * K + k0 + c] = h;
        Tl[(size_t)(n0 + n) * K + k0 + c] =
            __float2bfloat16(v - __bfloat162float(h));
    }
}

// ---------------------------------------------------------------------------
// V transpose+split: v f32 [B,S,H,HD] -> vth/vtl bf16 [B,H,HD,S]
// grid: (S/32, HD/32, B*H), block 256 (8x32 via r,c)
// ---------------------------------------------------------------------------
__global__ __launch_bounds__(256) void vtrans_kernel(
    const float* __restrict__ v, __nv_bfloat16* __restrict__ Th,
    __nv_bfloat16* __restrict__ Tl)
{
    __shared__ float tile[32][33];
    const int s0 = blockIdx.x * 32, d0 = blockIdx.y * 32;
    const int bh = blockIdx.z;          // b*Hc + h
    const int b = bh >> 4, h = bh & 15;
    const int t = threadIdx.x;
    const int r = t >> 5, c = t & 31;
    #pragma unroll
    for (int i = 0; i < 4; i++) {
        int sl = r + i * 8;
        tile[sl][c] = v[((size_t)(b * Sc + s0 + sl)) * Dc + h * HDc + d0 + c];
    }
    __syncthreads();
    #pragma unroll
    for (int i = 0; i < 4; i++) {
        int dl = r + i * 8;
        float val = tile[c][dl];
        __nv_bfloat16 hb = __float2bfloat16(val);
        size_t o = ((size_t)(bh * HDc + d0 + dl)) * Sc + s0 + c;
        Th[o] = hb;
        Tl[o] = __float2bfloat16(val - __bfloat162float(hb));
    }
}

// ---------------------------------------------------------------------------
// bf16x3 tensor-core GEMM: C[M,N] = A[M,K] @ W[K,N]
// ---------------------------------------------------------------------------
#define SROW 40

__global__ __launch_bounds__(256) void mma_gemm_kernel(
    const __nv_bfloat16* __restrict__ Ah, const __nv_bfloat16* __restrict__ Al,
    const __nv_bfloat16* __restrict__ BhT, const __nv_bfloat16* __restrict__ BlT,
    float* __restrict__ C, int M, int N, int K)
{
    __shared__ __align__(16) __nv_bfloat16 sAh[128 * SROW];
    __shared__ __align__(16) __nv_bfloat16 sAl[128 * SROW];
    __shared__ __align__(16) __nv_bfloat16 sBh[128 * SROW];
    __shared__ __align__(16) __nv_bfloat16 sBl[128 * SROW];

    const int t = threadIdx.x, lane = t & 31, wid = t >> 5;
    const int wm = wid & 1, wn = wid >> 1;
    const int bm = blockIdx.y * 128, bn = blockIdx.x * 128;
    const int gid = lane >> 2, tig = lane & 3;

    float acc[4][4][4];
    #pragma unroll
    for (int a = 0; a < 4; a++)
        #pragma unroll
        for (int b = 0; b < 4; b++)
            #pragma unroll
            for (int cc = 0; cc < 4; cc++) acc[a][b][cc] = 0.f;

    for (int k0 = 0; k0 < K; k0 += 32) {
        #pragma unroll
        for (int i = 0; i < 2; i++) {
            int u = t + i * 256;
            int row = u >> 2, ch = (u & 3) * 8;
            size_t ga = (size_t)(bm + row) * K + k0 + ch;
            size_t gb = (size_t)(bn + row) * K + k0 + ch;
            *(uint4*)&sAh[row * SROW + ch] = *(const uint4*)&Ah[ga];
            *(uint4*)&sAl[row * SROW + ch] = *(const uint4*)&Al[ga];
            *(uint4*)&sBh[row * SROW + ch] = *(const uint4*)&BhT[gb];
            *(uint4*)&sBl[row * SROW + ch] = *(const uint4*)&BlT[gb];
        }
        __syncthreads();

        #pragma unroll
        for (int ks = 0; ks < 2; ks++) {
            const int ak = ks * 16 + tig * 2;
            uint32_t ah[4][4], al[4][4];
            #pragma unroll
            for (int mt = 0; mt < 4; mt++) {
                const __nv_bfloat16* p = &sAh[(wm * 64 + mt * 16 + gid) * SROW + ak];
                ah[mt][0] = *(const uint32_t*)p;
                ah[mt][1] = *(const uint32_t*)(p + 8 * SROW);
                ah[mt][2] = *(const uint32_t*)(p + 8);
                ah[mt][3] = *(const uint32_t*)(p + 8 * SROW + 8);
                const __nv_bfloat16* q = &sAl[(wm * 64 + mt * 16 + gid) * SROW + ak];
                al[mt][0] = *(const uint32_t*)q;
                al[mt][1] = *(const uint32_t*)(q + 8 * SROW);
                al[mt][2] = *(const uint32_t*)(q + 8);
                al[mt][3] = *(const uint32_t*)(q + 8 * SROW + 8);
            }
            #pragma unroll
            for (int nt = 0; nt < 4; nt++) {
                const int brow = wn * 32 + nt * 8 + gid;
                const __nv_bfloat16* p = &sBh[brow * SROW + ak];
                uint32_t bh0 = *(const uint32_t*)p;
                uint32_t bh1 = *(const uint32_t*)(p + 8);
                const __nv_bfloat16* q = &sBl[brow * SROW + ak];
                uint32_t bl0 = *(const uint32_t*)q;
                uint32_t bl1 = *(const uint32_t*)(q + 8);
                #pragma unroll
                for (int mt = 0; mt < 4; mt++) {
                    MMA16816(acc[mt][nt], ah[mt][0], ah[mt][1], ah[mt][2], ah[mt][3], bh0, bh1);
                    MMA16816(acc[mt][nt], ah[mt][0], ah[mt][1], ah[mt][2], ah[mt][3], bl0, bl1);
                    MMA16816(acc[mt][nt], al[mt][0], al[mt][1], al[mt][2], al[mt][3], bh0, bh1);
                }
            }
        }
        __syncthreads();
    }

    #pragma unroll
    for (int mt = 0; mt < 4; mt++) {
        int row = bm + wm * 64 + mt * 16 + gid;
        #pragma unroll
        for (int nt = 0; nt < 4; nt++) {
            int col = bn + wn * 32 + nt * 8 + tig * 2;
            *(float2*)&C[(size_t)row * N + col] =
                make_float2(acc[mt][nt][0], acc[mt][nt][1]);
            *(float2*)&C[(size_t)(row + 8) * N + col] =
                make_float2(acc[mt][nt][2], acc[mt][nt][3]);
        }
    }
}

// ---------------------------------------------------------------------------
// Flash attention on tensor cores (bf16x3). BM=128, BN=64, 8 warps.
// Grid: (S/128, H, B). Reads g_qh/l, g_kh/l, g_vth/l; writes g_attn (fp32).
// ---------------------------------------------------------------------------
#define FQS 136
#define FVS 72
#define FLASH_SMEM ((2*128*FQS + 2*64*FQS + 2*128*FVS) * 2)

__global__ __launch_bounds__(256, 1) void flash_mma_kernel()
{
    extern __shared__ __align__(16) __nv_bfloat16 fsm[];
    __nv_bfloat16* sQh = fsm;
    __nv_bfloat16* sQl = sQh + 128 * FQS;
    __nv_bfloat16* sKh = sQl + 128 * FQS;
    __nv_bfloat16* sKl = sKh + 64 * FQS;
    __nv_bfloat16* sVh = sKl + 64 * FQS;
    __nv_bfloat16* sVl = sVh + 128 * FVS;

    const int t = threadIdx.x, lane = t & 31, w = t >> 5;
    const int gid = lane >> 2, tig = lane & 3;
    const int qt = blockIdx.x, h = blockIdx.y, b = blockIdx.z;
    const int qbase = qt * 128;

    // load Q tile (hi+lo): 128 rows x 16 chunks of 8 bf16
    #pragma unroll
    for (int i = 0; i < 8; i++) {
        int u = t + i * 256;
        int row = u >> 4, c8 = (u & 15) * 8;
        size_t g = ((size_t)(b * Sc + qbase + row)) * Dc + h * HDc + c8;
        *(uint4*)&sQh[row * FQS + c8] = *(const uint4*)&g_qh[g];
        *(uint4*)&sQl[row * FQS + c8] = *(const uint4*)&g_ql[g];
    }

    const int row0 = qbase + w * 16 + gid;
    const int row1 = row0 + 8;

    float m0 = -1e30f, m1 = -1e30f, l0 = 0.f, l1 = 0.f;
    float oacc[16][4];
    #pragma unroll
    for (int i = 0; i < 16; i++)
        #pragma unroll
        for (int j = 0; j < 4; j++) oacc[i][j] = 0.f;

    const int ntk = 2 * qt + 2;
    for (int kt = 0; kt < ntk; kt++) {
        const int kbase = kt * 64;
        __syncthreads();
        #pragma unroll
        for (int i = 0; i < 4; i++) {
            int u = t + i * 256;
            int krow = u >> 4, c8 = (u & 15) * 8;
            size_t gk = ((size_t)(b * Sc + kbase + krow)) * Dc + h * HDc + c8;
            *(uint4*)&sKh[krow * FQS + c8] = *(const uint4*)&g_kh[gk];
            *(uint4*)&sKl[krow * FQS + c8] = *(const uint4*)&g_kl[gk];
            int vrow = u >> 3, v8 = (u & 7) * 8;
            size_t gv = ((size_t)((b * Hc + h) * HDc + vrow)) * Sc + kbase + v8;
            *(uint4*)&sVh[vrow * FVS + v8] = *(const uint4*)&g_vth[gv];
            *(uint4*)&sVl[vrow * FVS + v8] = *(const uint4*)&g_vtl[gv];
        }
        __syncthreads();

        // ---- S = Q K^T (warp tile 16 x 64) ----
        float sacc[8][4];
        #pragma unroll
        for (int nt = 0; nt < 8; nt++)
            #pragma unroll
            for (int j = 0; j < 4; j++) sacc[nt][j] = 0.f;

        #pragma unroll
        for (int kc = 0; kc < 8; kc++) {
            const int ak = kc * 16 + 2 * tig;
            const __nv_bfloat16* pa = &sQh[(w * 16 + gid) * FQS + ak];
            uint32_t ah0 = *(const uint32_t*)pa;
            uint32_t ah1 = *(const uint32_t*)(pa + 8 * FQS);
            uint32_t ah2 = *(const uint32_t*)(pa + 8);
            uint32_t ah3 = *(const uint32_t*)(pa + 8 * FQS + 8);
            const __nv_bfloat16* pq = &sQl[(w * 16 + gid) * FQS + ak];
            uint32_t al0 = *(const uint32_t*)pq;
            uint32_t al1 = *(const uint32_t*)(pq + 8 * FQS);
            uint32_t al2 = *(const uint32_t*)(pq + 8);
            uint32_t al3 = *(const uint32_t*)(pq + 8 * FQS + 8);
            #pragma unroll
            for (int nt = 0; nt < 8; nt++) {
                const __nv_bfloat16* pb = &sKh[(nt * 8 + gid) * FQS + ak];
                uint32_t bh0 = *(const uint32_t*)pb;
                uint32_t bh1 = *(const uint32_t*)(pb + 8);
                const __nv_bfloat16* pbl = &sKl[(nt * 8 + gid) * FQS + ak];
                uint32_t bl0 = *(const uint32_t*)pbl;
                uint32_t bl1 = *(const uint32_t*)(pbl + 8);
                MMA16816(sacc[nt], ah0, ah1, ah2, ah3, bh0, bh1);
                MMA16816(sacc[nt], ah0, ah1, ah2, ah3, bl0, bl1);
                MMA16816(sacc[nt], al0, al1, al2, al3, bh0, bh1);
            }
        }

        // ---- scale + causal mask ----
        const bool need_mask = (kt >= 2 * qt);
        #pragma unroll
        for (int nt = 0; nt < 8; nt++) {
            int c0 = kbase + nt * 8 + 2 * tig;
            float v0 = sacc[nt][0] * SCALE;
            float v1 = sacc[nt][1] * SCALE;
            float v2 = sacc[nt][2] * SCALE;
            float v3 = sacc[nt][3] * SCALE;
            if (need_mask) {
                if (c0 > row0)     v0 -= 1e9f;
                if (c0 + 1 > row0) v1 -= 1e9f;
                if (c0 > row1)     v2 -= 1e9f;
                if (c0 + 1 > row1) v3 -= 1e9f;
            }
            sacc[nt][0] = v0; sacc[nt][1] = v1;
            sacc[nt][2] = v2; sacc[nt][3] = v3;
        }

        // ---- row max ----
        float mx0 = -1e30f, mx1 = -1e30f;
        #pragma unroll
        for (int nt = 0; nt < 8; nt++) {
            mx0 = fmaxf(mx0, fmaxf(sacc[nt][0], sacc[nt][1]));
            mx1 = fmaxf(mx1, fmaxf(sacc[nt][2], sacc[nt][3]));
        }
        mx0 = fmaxf(mx0, __shfl_xor_sync(0xffffffffu, mx0, 1));
        mx0 = fmaxf(mx0, __shfl_xor_sync(0xffffffffu, mx0, 2));
        mx1 = fmaxf(mx1, __shfl_xor_sync(0xffffffffu, mx1, 1));
        mx1 = fmaxf(mx1, __shfl_xor_sync(0xffffffffu, mx1, 2));
        float nm0 = fmaxf(m0, mx0), nm1 = fmaxf(m1, mx1);
        float corr0 = __expf(m0 - nm0), corr1 = __expf(m1 - nm1);
        m0 = nm0; m1 = nm1;

        // ---- exp + split P into bf16 hi/lo fragments ----
        float rs0 = 0.f, rs1 = 0.f;
        uint32_t ph01[8], ph23[8], pl01[8], pl23[8];
        #pragma unroll
        for (int nt = 0; nt < 8; nt++) {
            float e0 = __expf(sacc[nt][0] - nm0);
            float e1 = __expf(sacc[nt][1] - nm0);
            float e2 = __expf(sacc[nt][2] - nm1);
            float e3 = __expf(sacc[nt][3] - nm1);
            rs0 += e0 + e1; rs1 += e2 + e3;
            __nv_bfloat162 h01 = __floats2bfloat162_rn(e0, e1);
            __nv_bfloat162 h23 = __floats2bfloat162_rn(e2, e3);
            __nv_bfloat162 lo01 = __floats2bfloat162_rn(
                e0 - __bfloat162float(h01.x), e1 - __bfloat162float(h01.y));
            __nv_bfloat162 lo23 = __floats2bfloat162_rn(
                e2 - __bfloat162float(h23.x), e3 - __bfloat162float(h23.y));
            ph01[nt] = *(uint32_t*)&h01;
            ph23[nt] = *(uint32_t*)&h23;
            pl01[nt] = *(uint32_t*)&lo01;
            pl23[nt] = *(uint32_t*)&lo23;
        }
        rs0 += __shfl_xor_sync(0xffffffffu, rs0, 1);
        rs0 += __shfl_xor_sync(0xffffffffu, rs0, 2);
        rs1 += __shfl_xor_sync(0xffffffffu, rs1, 1);
        rs1 += __shfl_xor_sync(0xffffffffu, rs1, 2);
        l0 = l0 * corr0 + rs0;
        l1 = l1 * corr1 + rs1;

        // ---- rescale O ----
        #pragma unroll
        for (int nto = 0; nto < 16; nto++) {
            oacc[nto][0] *= corr0; oacc[nto][1] *= corr0;
            oacc[nto][2] *= corr1; oacc[nto][3] *= corr1;
        }

        // ---- O += P V ----
        #pragma unroll
        for (int j = 0; j < 4; j++) {
            uint32_t a0h = ph01[2 * j],     a1h = ph23[2 * j];
            uint32_t a2h = ph01[2 * j + 1], a3h = ph23[2 * j + 1];
            uint32_t a0l = pl01[2 * j],     a1l = pl23[2 * j];
            uint32_t a2l = pl01[2 * j + 1], a3l = pl23[2 * j + 1];
            #pragma unroll
            for (int nto = 0; nto < 16; nto++) {
                const __nv_bfloat16* pv = &sVh[(nto * 8 + gid) * FVS + j * 16 + 2 * tig];
                uint32_t vh0 = *(const uint32_t*)pv;
                uint32_t vh1 = *(const uint32_t*)(pv + 8);
                const __nv_bfloat16* pvl = &sVl[(nto * 8 + gid) * FVS + j * 16 + 2 * tig];
                uint32_t vl0 = *(const uint32_t*)pvl;
                uint32_t vl1 = *(const uint32_t*)(pvl + 8);
                MMA16816(oacc[nto], a0h, a1h, a2h, a3h, vh0, vh1);
                MMA16816(oacc[nto], a0h, a1h, a2h, a3h, vl0, vl1);
                MMA16816(oacc[nto], a0l, a1l, a2l, a3l, vh0, vh1);
            }
        }
    }

    float i0 = 1.f / l0, i1 = 1.f / l1;
    #pragma unroll
    for (int nto = 0; nto < 16; nto++) {
        int col = h * HDc + nto * 8 + 2 * tig;
        *(float2*)&g_attn[((size_t)(b * Sc + row0)) * Dc + col] =
            make_float2(oacc[nto][0] * i0, oacc[nto][1] * i0);
        *(float2*)&g_attn[((size_t)(b * Sc + row1)) * Dc + col] =
            make_float2(oacc[nto][2] * i1, oacc[nto][3] * i1);
    }
}

// ---------------------------------------------------------------------------
// Adapter projection, deterministic 2-pass k-split
// ---------------------------------------------------------------------------
__global__ __launch_bounds__(256) void adapter_proj_kernel(
    const float* __restrict__ A, const float* __restrict__ W,
    float* __restrict__ P)
{
    const int ks = blockIdx.x;
    const int l  = blockIdx.y;
    const int t  = threadIdx.x;
    float acc[8];
    #pragma unroll
    for (int i = 0; i < 8; i++) acc[i] = 0.f;
    for (int k = ks * 128; k < ks * 128 + 128; k++) {
        float a = A[l * Dc + k];
        const float* wr = &W[(size_t)k * Dc + t * 8];
        float4 w0 = *(const float4*)wr;
        float4 w1 = *(const float4*)(wr + 4);
        acc[0] += a * w0.x; acc[1] += a * w0.y;
        acc[2] += a * w0.z; acc[3] += a * w0.w;
        acc[4] += a * w1.x; acc[5] += a * w1.y;
        acc[6] += a * w1.z; acc[7] += a * w1.w;
    }
    float* o = &P[((size_t)l * 16 + ks) * Dc + t * 8];
    *(float4*)o       = make_float4(acc[0], acc[1], acc[2], acc[3]);
    *(float4*)(o + 4) = make_float4(acc[4], acc[5], acc[6], acc[7]);
}

__global__ __launch_bounds__(256) void adapter_reduce_kernel(
    const float* __restrict__ P, float* __restrict__ C)
{
    int idx = blockIdx.x * 256 + threadIdx.x;
    int l = idx >> 11, n = idx & 2047;
    float s = 0.f;
    #pragma unroll
    for (int ks = 0; ks < 16; ks++)
        s += P[((size_t)l * 16 + ks) * Dc + n];
    C[idx] = s;
}

// ---------------------------------------------------------------------------
// RoPE in-place on (B,S,H,HD), interleaved pairs.
// ---------------------------------------------------------------------------
__global__ __launch_bounds__(256) void rope_kernel(
    float* __restrict__ d, const float* __restrict__ fc,
    const float* __restrict__ fs)
{
    int idx = blockIdx.x * blockDim.x + threadIdx.x;
    int j = idx & 63;
    int s = ((idx >> 6) / Hc) % Sc;
    float2* p = (float2*)d;
    float2 v = p[idx];
    float c  = fc[s * 64 + j];
    float sn = fs[s * 64 + j];
    p[idx] = make_float2(v.x * c - v.y * sn, v.x * sn + v.y * c);
}

// ---------------------------------------------------------------------------
// Adapter attention: one warp per (b,s,h). out += gate[h] * softmax(q·akᵀ) av
// ---------------------------------------------------------------------------
__global__ __launch_bounds__(256) void adapter_attn_kernel(
    const float* __restrict__ gate)
{
    int gw = (blockIdx.x * blockDim.x + threadIdx.x) >> 5;
    int lane = threadIdx.x & 31;
    if (gw >= Bc * Sc * Hc) return;
    int h = gw % Hc;
    int s = (gw / Hc) % Sc;
    int b = gw / (Hc * Sc);

    size_t qoff = ((size_t)(b * Sc + s)) * Dc + h * HDc + lane * 4;
    float4 q4 = *(const float4*)(g_q + qoff);

    float scv[Lc];
    #pragma unroll
    for (int l = 0; l < Lc; l++) {
        float4 a4 = *(const float4*)(g_ak + (size_t)l * Dc + h * HDc + lane * 4);
        float p = q4.x * a4.x + q4.y * a4.y + q4.z * a4.z + q4.w * a4.w;
        #pragma unroll
        for (int o = 16; o > 0; o >>= 1)
            p += __shfl_xor_sync(0xffffffffu, p, o);
        scv[l] = p * SCALE;
    }
    float m = scv[0];
    #pragma unroll
    for (int l = 1; l < Lc; l++) m = fmaxf(m, scv[l]);
    float sum = 0.f;
    float e[Lc];
    #pragma unroll
    for (int l = 0; l < Lc; l++) { e[l] = expf(scv[l] - m); sum += e[l]; }
    float g = gate[h] / sum;

    float4 acc = make_float4(0.f, 0.f, 0.f, 0.f);
    #pragma unroll
    for (int l = 0; l < Lc; l++) {
        float4 a4 = *(const float4*)(g_av + (size_t)l * Dc + h * HDc + lane * 4);
        acc.x += e[l] * a4.x;
        acc.y += e[l] * a4.y;
        acc.z += e[l] * a4.z;
        acc.w += e[l] * a4.w;
    }
    float4 cur = *(float4*)(g_attn + qoff);
    cur.x += g * acc.x;
    cur.y += g * acc.y;
    cur.z += g * acc.z;
    cur.w += g * acc.w;
    *(float4*)(g_attn + qoff) = cur;
}

// ---------------------------------------------------------------------------
extern "C" void kernel_launch(void* const* d_in, const int* in_sizes, int n_in,
                              void* d_out, int out_size)
{
    const float* x       = (const float*)d_in[0];
    const float* wq      = (const float*)d_in[1];
    const float* wk      = (const float*)d_in[2];
    const float* wv      = (const float*)d_in[3];
    const float* wo      = (const float*)d_in[4];
    const float* adapter = (const float*)d_in[5];
    const float* gate    = (const float*)d_in[6];
    const float* fcos    = (const float*)d_in[7];
    const float* fsin    = (const float*)d_in[8];
    float* out = (float*)d_out;

    float *q, *k, *v, *attn, *ak, *av, *part;
    __nv_bfloat16 *xh, *xl, *wth, *wtl, *qh, *ql, *kh, *kl, *vth, *vtl;
    cudaGetSymbolAddress((void**)&q,    g_q);
    cudaGetSymbolAddress((void**)&k,    g_k);
    cudaGetSymbolAddress((void**)&v,    g_v);
    cudaGetSymbolAddress((void**)&attn, g_attn);
    cudaGetSymbolAddress((void**)&ak,   g_ak);
    cudaGetSymbolAddress((void**)&av,   g_av);
    cudaGetSymbolAddress((void**)&part, g_partial);
    cudaGetSymbolAddress((void**)&xh,   g_xh);
    cudaGetSymbolAddress((void**)&xl,   g_xl);
    cudaGetSymbolAddress((void**)&wth,  g_wth);
    cudaGetSymbolAddress((void**)&wtl,  g_wtl);
    cudaGetSymbolAddress((void**)&qh,   g_qh);
    cudaGetSymbolAddress((void**)&ql,   g_ql);
    cudaGetSymbolAddress((void**)&kh,   g_kh);
    cudaGetSymbolAddress((void**)&kl,   g_kl);
    cudaGetSymbolAddress((void**)&vth,  g_vth);
    cudaGetSymbolAddress((void**)&vtl,  g_vtl);

    const int M = Bc * Sc;   // 4096
    dim3 ggrid(Dc / 128, M / 128);
    dim3 wgrid(Dc / 32, Dc / 32);

    // split x -> bf16 hi/lo
    split_kernel<<<(M * Dc / 4) / 256, 256>>>(x, xh, xl);

    // Q/K/V projections on tensor cores
    wtrans_kernel<<<wgrid, 256>>>(wq, wth, wtl, Dc, Dc);
    mma_gemm_kernel<<<ggrid, 256>>>(xh, xl, wth, wtl, q, M, Dc, Dc);
    wtrans_kernel<<<wgrid, 256>>>(wk, wth, wtl, Dc, Dc);
    mma_gemm_kernel<<<ggrid, 256>>>(xh, xl, wth, wtl, k, M, Dc, Dc);
    wtrans_kernel<<<wgrid, 256>>>(wv, wth, wtl, Dc, Dc);
    mma_gemm_kernel<<<ggrid, 256>>>(xh, xl, wth, wtl, v, M, Dc, Dc);

    int npairs = Bc * Sc * Hc * (HDc / 2);
    rope_kernel<<<npairs / 256, 256>>>(q, fcos, fsin);
    rope_kernel<<<npairs / 256, 256>>>(k, fcos, fsin);

    // bf16 splits for flash
    split_kernel<<<(M * Dc / 4) / 256, 256>>>(q, qh, ql);
    split_kernel<<<(M * Dc / 4) / 256, 256>>>(k, kh, kl);
    vtrans_kernel<<<dim3(Sc / 32, HDc / 32, Bc * Hc), 256>>>(v, vth, vtl);

    adapter_proj_kernel<<<dim3(16, Lc), 256>>>(adapter, wk, part);
    adapter_reduce_kernel<<<(Lc * Dc) / 256, 256>>>(part, ak);
    adapter_proj_kernel<<<dim3(16, Lc), 256>>>(adapter, wv, part);
    adapter_reduce_kernel<<<(Lc * Dc) / 256, 256>>>(part, av);

    cudaFuncSetAttribute(flash_mma_kernel,
                         cudaFuncAttributeMaxDynamicSharedMemorySize,
                         FLASH_SMEM);
    flash_mma_kernel<<<dim3(Sc / 128, Hc, Bc), 256, FLASH_SMEM>>>();

    adapter_attn_kernel<<<(Bc * Sc * Hc * 32) / 256, 256>>>(gate);

    // Output projection
    split_kernel<<<(M * Dc / 4) / 256, 256>>>(attn, xh, xl);
    wtrans_kernel<<<wgrid, 256>>>(wo, wth, wtl, Dc, Dc);
    mma_gemm_kernel<<<ggrid, 256>>>(xh, xl, wth, wtl, out, M, Dc, Dc);
}

// round 5
// speedup vs baseline: 4.4260x; 1.1907x over previous
#include <cuda_runtime.h>
#include <cuda_bf16.h>
#include <math.h>
#include <stdint.h>

#define Bc 2
#define Sc 2048
#define Dc 2048
#define Hc 16
#define HDc 128
#define Lc 10

// Scratch (static device globals — allocation-free per harness rules)
__device__ float g_q[Bc*Sc*Dc];
__device__ float g_k[Bc*Sc*Dc];
__device__ float g_v[Bc*Sc*Dc];
__device__ float g_attn[Bc*Sc*Dc];
__device__ float g_ak[Lc*Dc];
__device__ float g_av[Lc*Dc];
__device__ float g_partial[Lc*16*Dc];
// bf16 split scratch
__device__ __nv_bfloat16 g_xh[Bc*Sc*Dc];
__device__ __nv_bfloat16 g_xl[Bc*Sc*Dc];
__device__ __nv_bfloat16 g_wth[Dc*Dc];   // W^T hi  [N][K]
__device__ __nv_bfloat16 g_wtl[Dc*Dc];   // W^T lo  [N][K]
__device__ __nv_bfloat16 g_qh[Bc*Sc*Dc];
__device__ __nv_bfloat16 g_ql[Bc*Sc*Dc];
__device__ __nv_bfloat16 g_kh[Bc*Sc*Dc];
__device__ __nv_bfloat16 g_kl[Bc*Sc*Dc];
__device__ __nv_bfloat16 g_vth[Bc*Sc*Dc];  // [B,H,HD,S]
__device__ __nv_bfloat16 g_vtl[Bc*Sc*Dc];  // [B,H,HD,S]

#define SCALE 0.08838834764831845f  // 1/sqrt(128)

// ---------------------------------------------------------------------------
// mma.sync m16n8k16 bf16 + cp.async helpers
// ---------------------------------------------------------------------------
#define MMA16816(c, a0, a1, a2, a3, b0, b1) \
    asm volatile( \
        "mma.sync.aligned.m16n8k16.row.col.f32.bf16.bf16.f32 " \
        "{%0,%1,%2,%3}, {%4,%5,%6,%7}, {%8,%9}, {%0,%1,%2,%3};" \
        : "+f"((c)[0]), "+f"((c)[1]), "+f"((c)[2]), "+f"((c)[3]) \
        : "r"(a0), "r"(a1), "r"(a2), "r"(a3), "r"(b0), "r"(b1))

__device__ __forceinline__ uint32_t smem_u32(const void* p) {
    uint32_t a;
    asm("{ .reg .u64 t; cvta.to.shared.u64 t, %1; cvt.u32.u64 %0, t; }"
        : "=r"(a) : "l"(p));
    return a;
}
#define CPA16(saddr, gptr) \
    asm volatile("cp.async.cg.shared.global [%0], [%1], 16;" \
                 :: "r"(saddr), "l"(gptr))
#define CPA_COMMIT() asm volatile("cp.async.commit_group;")
#define CPA_WAIT(n)  asm volatile("cp.async.wait_group %0;" :: "n"(n))

// ---------------------------------------------------------------------------
// Elementwise fp32 -> bf16 hi/lo split (4 elems per thread)
// ---------------------------------------------------------------------------
__global__ __launch_bounds__(256) void split_kernel(
    const float* __restrict__ x, __nv_bfloat16* __restrict__ h,
    __nv_bfloat16* __restrict__ l)
{
    int i = blockIdx.x * 256 + threadIdx.x;
    float4 v = ((const float4*)x)[i];
    __nv_bfloat162 h01, h23, l01, l23;
    h01.x = __float2bfloat16(v.x);
    h01.y = __float2bfloat16(v.y);
    h23.x = __float2bfloat16(v.z);
    h23.y = __float2bfloat16(v.w);
    l01.x = __float2bfloat16(v.x - __bfloat162float(h01.x));
    l01.y = __float2bfloat16(v.y - __bfloat162float(h01.y));
    l23.x = __float2bfloat16(v.z - __bfloat162float(h23.x));
    l23.y = __float2bfloat16(v.w - __bfloat162float(h23.y));
    ((__nv_bfloat162*)h)[i * 2 + 0] = h01;
    ((__nv_bfloat162*)h)[i * 2 + 1] = h23;
    ((__nv_bfloat162*)l)[i * 2 + 0] = l01;
    ((__nv_bfloat162*)l)[i * 2 + 1] = l23;
}

// ---------------------------------------------------------------------------
// Fused RoPE + bf16 split. Reads fp32 d, rotates pair, optionally writes
// back fp32, always writes bf16 hi/lo.
// ---------------------------------------------------------------------------
__global__ __launch_bounds__(256) void rope_split_kernel(
    float* __restrict__ d, const float* __restrict__ fc,
    const float* __restrict__ fs, __nv_bfloat16* __restrict__ ph,
    __nv_bfloat16* __restrict__ pl, int writeback)
{
    int idx = blockIdx.x * blockDim.x + threadIdx.x;   // over B*S*H*(HD/2)
    int j = idx & 63;
    int s = ((idx >> 6) / Hc) % Sc;
    float2 v = ((const float2*)d)[idx];
    float c  = fc[s * 64 + j];
    float sn = fs[s * 64 + j];
    float o0 = v.x * c - v.y * sn;
    float o1 = v.x * sn + v.y * c;
    if (writeback) ((float2*)d)[idx] = make_float2(o0, o1);
    __nv_bfloat162 h2, l2;
    h2.x = __float2bfloat16(o0);
    h2.y = __float2bfloat16(o1);
    l2.x = __float2bfloat16(o0 - __bfloat162float(h2.x));
    l2.y = __float2bfloat16(o1 - __bfloat162float(h2.y));
    ((__nv_bfloat162*)ph)[idx] = h2;
    ((__nv_bfloat162*)pl)[idx] = l2;
}

// ---------------------------------------------------------------------------
// Transpose + split: W[K][N] f32 -> Th/Tl[N][K] bf16
// ---------------------------------------------------------------------------
__global__ __launch_bounds__(256) void wtrans_kernel(
    const float* __restrict__ W, __nv_bfloat16* __restrict__ Th,
    __nv_bfloat16* __restrict__ Tl, int K, int N)
{
    __shared__ float tile[32][33];
    const int k0 = blockIdx.x * 32, n0 = blockIdx.y * 32;
    const int t = threadIdx.x;
    const int r = t >> 5, c = t & 31;
    #pragma unroll
    for (int i = 0; i < 4; i++)
        tile[r + i * 8][c] = W[(size_t)(k0 + r + i * 8) * N + n0 + c];
    __syncthreads();
    #pragma unroll
    for (int i = 0; i < 4; i++) {
        int n = r + i * 8;
        float v = tile[c][n];
        __nv_bfloat16 h = __float2bfloat16(v);
        Th[(size_t)(n0 + n) * K + k0 + c] = h;
        Tl[(size_t)(n0 + n) * K + k0 + c] =
            __float2bfloat16(v - __bfloat162float(h));
    }
}

// ---------------------------------------------------------------------------
// V transpose+split: v f32 [B,S,H,HD] -> vth/vtl bf16 [B,H,HD,S]
// ---------------------------------------------------------------------------
__global__ __launch_bounds__(256) void vtrans_kernel(
    const float* __restrict__ v, __nv_bfloat16* __restrict__ Th,
    __nv_bfloat16* __restrict__ Tl)
{
    __shared__ float tile[32][33];
    const int s0 = blockIdx.x * 32, d0 = blockIdx.y * 32;
    const int bh = blockIdx.z;
    const int b = bh >> 4, h = bh & 15;
    const int t = threadIdx.x;
    const int r = t >> 5, c = t & 31;
    #pragma unroll
    for (int i = 0; i < 4; i++) {
        int sl = r + i * 8;
        tile[sl][c] = v[((size_t)(b * Sc + s0 + sl)) * Dc + h * HDc + d0 + c];
    }
    __syncthreads();
    #pragma unroll
    for (int i = 0; i < 4; i++) {
        int dl = r + i * 8;
        float val = tile[c][dl];
        __nv_bfloat16 hb = __float2bfloat16(val);
        size_t o = ((size_t)(bh * HDc + d0 + dl)) * Sc + s0 + c;
        Th[o] = hb;
        Tl[o] = __float2bfloat16(val - __bfloat162float(hb));
    }
}

// ---------------------------------------------------------------------------
// bf16x3 tensor-core GEMM, 2-stage cp.async pipeline.
// C[M,N] = A[M,K] @ W[K,N]; Ah/Al [M][K], BhT/BlT [N][K].
// CTA 128x128, BK=32, 8 warps (2m x 4n).
// ---------------------------------------------------------------------------
#define SROW 40
#define STG_ELEMS (4 * 128 * SROW)            // 20480 bf16 per stage
#define GEMM_SMEM (2 * STG_ELEMS * 2)         // 81920 bytes

__global__ __launch_bounds__(256, 1) void mma_gemm_kernel(
    const __nv_bfloat16* __restrict__ Ah, const __nv_bfloat16* __restrict__ Al,
    const __nv_bfloat16* __restrict__ BhT, const __nv_bfloat16* __restrict__ BlT,
    float* __restrict__ C, int M, int N, int K)
{
    extern __shared__ __align__(16) __nv_bfloat16 dsm[];
    const uint32_t sb = smem_u32(dsm);

    const int t = threadIdx.x, lane = t & 31, wid = t >> 5;
    const int wm = wid & 1, wn = wid >> 1;
    const int bm = blockIdx.y * 128, bn = blockIdx.x * 128;
    const int gid = lane >> 2, tig = lane & 3;

    // per-thread load coords (2 chunks of 16B per array per stage)
    const int lrow0 = t >> 2, lch0 = (t & 3) * 8;
    const int lrow1 = (t + 256) >> 2, lch1 = ((t + 256) & 3) * 8;

    float acc[4][4][4];
    #pragma unroll
    for (int a = 0; a < 4; a++)
        #pragma unroll
        for (int b = 0; b < 4; b++)
            #pragma unroll
            for (int cc = 0; cc < 4; cc++) acc[a][b][cc] = 0.f;

    const int nst = K >> 5;

    // ---- issue loads for a stage ----
    #define LOAD_STAGE(stg, k0) do {                                        \
        uint32_t base = sb + (stg) * STG_ELEMS * 2;                         \
        size_t ga0 = (size_t)(bm + lrow0) * K + (k0) + lch0;                \
        size_t gb0 = (size_t)(bn + lrow0) * K + (k0) + lch0;                \
        size_t ga1 = (size_t)(bm + lrow1) * K + (k0) + lch1;                \
        size_t gb1 = (size_t)(bn + lrow1) * K + (k0) + lch1;                \
        CPA16(base + (0 * 5120 + lrow0 * SROW + lch0) * 2, &Ah[ga0]);       \
        CPA16(base + (1 * 5120 + lrow0 * SROW + lch0) * 2, &Al[ga0]);       \
        CPA16(base + (2 * 5120 + lrow0 * SROW + lch0) * 2, &BhT[gb0]);      \
        CPA16(base + (3 * 5120 + lrow0 * SROW + lch0) * 2, &BlT[gb0]);      \
        CPA16(base + (0 * 5120 + lrow1 * SROW + lch1) * 2, &Ah[ga1]);       \
        CPA16(base + (1 * 5120 + lrow1 * SROW + lch1) * 2, &Al[ga1]);       \
        CPA16(base + (2 * 5120 + lrow1 * SROW + lch1) * 2, &BhT[gb1]);      \
        CPA16(base + (3 * 5120 + lrow1 * SROW + lch1) * 2, &BlT[gb1]);      \
    } while (0)

    LOAD_STAGE(0, 0);
    CPA_COMMIT();

    for (int it = 0; it < nst; it++) {
        if (it + 1 < nst) {
            LOAD_STAGE((it + 1) & 1, (it + 1) * 32);
            CPA_COMMIT();
            CPA_WAIT(1);
        } else {
            CPA_WAIT(0);
        }
        __syncthreads();

        const __nv_bfloat16* sAh = dsm + (it & 1) * STG_ELEMS;
        const __nv_bfloat16* sAl = sAh + 5120;
        const __nv_bfloat16* sBh = sAh + 10240;
        const __nv_bfloat16* sBl = sAh + 15360;

        #pragma unroll
        for (int ks = 0; ks < 2; ks++) {
            const int ak = ks * 16 + tig * 2;
            uint32_t ah[4][4], al[4][4];
            #pragma unroll
            for (int mt = 0; mt < 4; mt++) {
                const __nv_bfloat16* p = &sAh[(wm * 64 + mt * 16 + gid) * SROW + ak];
                ah[mt][0] = *(const uint32_t*)p;
                ah[mt][1] = *(const uint32_t*)(p + 8 * SROW);
                ah[mt][2] = *(const uint32_t*)(p + 8);
                ah[mt][3] = *(const uint32_t*)(p + 8 * SROW + 8);
                const __nv_bfloat16* q = &sAl[(wm * 64 + mt * 16 + gid) * SROW + ak];
                al[mt][0] = *(const uint32_t*)q;
                al[mt][1] = *(const uint32_t*)(q + 8 * SROW);
                al[mt][2] = *(const uint32_t*)(q + 8);
                al[mt][3] = *(const uint32_t*)(q + 8 * SROW + 8);
            }
            #pragma unroll
            for (int nt = 0; nt < 4; nt++) {
                const int brow = wn * 32 + nt * 8 + gid;
                const __nv_bfloat16* p = &sBh[brow * SROW + ak];
                uint32_t bh0 = *(const uint32_t*)p;
                uint32_t bh1 = *(const uint32_t*)(p + 8);
                const __nv_bfloat16* q = &sBl[brow * SROW + ak];
                uint32_t bl0 = *(const uint32_t*)q;
                uint32_t bl1 = *(const uint32_t*)(q + 8);
                #pragma unroll
                for (int mt = 0; mt < 4; mt++) {
                    MMA16816(acc[mt][nt], ah[mt][0], ah[mt][1], ah[mt][2], ah[mt][3], bh0, bh1);
                    MMA16816(acc[mt][nt], ah[mt][0], ah[mt][1], ah[mt][2], ah[mt][3], bl0, bl1);
                    MMA16816(acc[mt][nt], al[mt][0], al[mt][1], al[mt][2], al[mt][3], bh0, bh1);
                }
            }
        }
        __syncthreads();
    }

    #pragma unroll
    for (int mt = 0; mt < 4; mt++) {
        int row = bm + wm * 64 + mt * 16 + gid;
        #pragma unroll
        for (int nt = 0; nt < 4; nt++) {
            int col = bn + wn * 32 + nt * 8 + tig * 2;
            *(float2*)&C[(size_t)row * N + col] =
                make_float2(acc[mt][nt][0], acc[mt][nt][1]);
            *(float2*)&C[(size_t)(row + 8) * N + col] =
                make_float2(acc[mt][nt][2], acc[mt][nt][3]);
        }
    }
}

// ---------------------------------------------------------------------------
// Flash attention on tensor cores (bf16x3). BM=128, BN=64, 8 warps.
// ---------------------------------------------------------------------------
#define FQS 136
#define FVS 72
#define FLASH_SMEM ((2*128*FQS + 2*64*FQS + 2*128*FVS) * 2)

__global__ __launch_bounds__(256, 1) void flash_mma_kernel()
{
    extern __shared__ __align__(16) __nv_bfloat16 fsm[];
    __nv_bfloat16* sQh = fsm;
    __nv_bfloat16* sQl = sQh + 128 * FQS;
    __nv_bfloat16* sKh = sQl + 128 * FQS;
    __nv_bfloat16* sKl = sKh + 64 * FQS;
    __nv_bfloat16* sVh = sKl + 64 * FQS;
    __nv_bfloat16* sVl = sVh + 128 * FVS;
    const uint32_t uKh = smem_u32(sKh), uKl = smem_u32(sKl);
    const uint32_t uVh = smem_u32(sVh), uVl = smem_u32(sVl);

    const int t = threadIdx.x, lane = t & 31, w = t >> 5;
    const int gid = lane >> 2, tig = lane & 3;
    const int qt = blockIdx.x, h = blockIdx.y, b = blockIdx.z;
    const int qbase = qt * 128;

    #pragma unroll
    for (int i = 0; i < 8; i++) {
        int u = t + i * 256;
        int row = u >> 4, c8 = (u & 15) * 8;
        size_t g = ((size_t)(b * Sc + qbase + row)) * Dc + h * HDc + c8;
        *(uint4*)&sQh[row * FQS + c8] = *(const uint4*)&g_qh[g];
        *(uint4*)&sQl[row * FQS + c8] = *(const uint4*)&g_ql[g];
    }

    const int row0 = qbase + w * 16 + gid;
    const int row1 = row0 + 8;

    float m0 = -1e30f, m1 = -1e30f, l0 = 0.f, l1 = 0.f;
    float oacc[16][4];
    #pragma unroll
    for (int i = 0; i < 16; i++)
        #pragma unroll
        for (int j = 0; j < 4; j++) oacc[i][j] = 0.f;

    const int ntk = 2 * qt + 2;
    for (int kt = 0; kt < ntk; kt++) {
        const int kbase = kt * 64;
        __syncthreads();
        #pragma unroll
        for (int i = 0; i < 4; i++) {
            int u = t + i * 256;
            int krow = u >> 4, c8 = (u & 15) * 8;
            size_t gk = ((size_t)(b * Sc + kbase + krow)) * Dc + h * HDc + c8;
            CPA16(uKh + (krow * FQS + c8) * 2, &g_kh[gk]);
            CPA16(uKl + (krow * FQS + c8) * 2, &g_kl[gk]);
            int vrow = u >> 3, v8 = (u & 7) * 8;
            size_t gv = ((size_t)((b * Hc + h) * HDc + vrow)) * Sc + kbase + v8;
            CPA16(uVh + (vrow * FVS + v8) * 2, &g_vth[gv]);
            CPA16(uVl + (vrow * FVS + v8) * 2, &g_vtl[gv]);
        }
        CPA_COMMIT();
        CPA_WAIT(0);
        __syncthreads();

        // ---- S = Q K^T ----
        float sacc[8][4];
        #pragma unroll
        for (int nt = 0; nt < 8; nt++)
            #pragma unroll
            for (int j = 0; j < 4; j++) sacc[nt][j] = 0.f;

        #pragma unroll
        for (int kc = 0; kc < 8; kc++) {
            const int ak = kc * 16 + 2 * tig;
            const __nv_bfloat16* pa = &sQh[(w * 16 + gid) * FQS + ak];
            uint32_t ah0 = *(const uint32_t*)pa;
            uint32_t ah1 = *(const uint32_t*)(pa + 8 * FQS);
            uint32_t ah2 = *(const uint32_t*)(pa + 8);
            uint32_t ah3 = *(const uint32_t*)(pa + 8 * FQS + 8);
            const __nv_bfloat16* pq = &sQl[(w * 16 + gid) * FQS + ak];
            uint32_t al0 = *(const uint32_t*)pq;
            uint32_t al1 = *(const uint32_t*)(pq + 8 * FQS);
            uint32_t al2 = *(const uint32_t*)(pq + 8);
            uint32_t al3 = *(const uint32_t*)(pq + 8 * FQS + 8);
            #pragma unroll
            for (int nt = 0; nt < 8; nt++) {
                const __nv_bfloat16* pb = &sKh[(nt * 8 + gid) * FQS + ak];
                uint32_t bh0 = *(const uint32_t*)pb;
                uint32_t bh1 = *(const uint32_t*)(pb + 8);
                const __nv_bfloat16* pbl = &sKl[(nt * 8 + gid) * FQS + ak];
                uint32_t bl0 = *(const uint32_t*)pbl;
                uint32_t bl1 = *(const uint32_t*)(pbl + 8);
                MMA16816(sacc[nt], ah0, ah1, ah2, ah3, bh0, bh1);
                MMA16816(sacc[nt], ah0, ah1, ah2, ah3, bl0, bl1);
                MMA16816(sacc[nt], al0, al1, al2, al3, bh0, bh1);
            }
        }

        const bool need_mask = (kt >= 2 * qt);
        #pragma unroll
        for (int nt = 0; nt < 8; nt++) {
            int c0 = kbase + nt * 8 + 2 * tig;
            float v0 = sacc[nt][0] * SCALE;
            float v1 = sacc[nt][1] * SCALE;
            float v2 = sacc[nt][2] * SCALE;
            float v3 = sacc[nt][3] * SCALE;
            if (need_mask) {
                if (c0 > row0)     v0 -= 1e9f;
                if (c0 + 1 > row0) v1 -= 1e9f;
                if (c0 > row1)     v2 -= 1e9f;
                if (c0 + 1 > row1) v3 -= 1e9f;
            }
            sacc[nt][0] = v0; sacc[nt][1] = v1;
            sacc[nt][2] = v2; sacc[nt][3] = v3;
        }

        float mx0 = -1e30f, mx1 = -1e30f;
        #pragma unroll
        for (int nt = 0; nt < 8; nt++) {
            mx0 = fmaxf(mx0, fmaxf(sacc[nt][0], sacc[nt][1]));
            mx1 = fmaxf(mx1, fmaxf(sacc[nt][2], sacc[nt][3]));
        }
        mx0 = fmaxf(mx0, __shfl_xor_sync(0xffffffffu, mx0, 1));
        mx0 = fmaxf(mx0, __shfl_xor_sync(0xffffffffu, mx0, 2));
        mx1 = fmaxf(mx1, __shfl_xor_sync(0xffffffffu, mx1, 1));
        mx1 = fmaxf(mx1, __shfl_xor_sync(0xffffffffu, mx1, 2));
        float nm0 = fmaxf(m0, mx0), nm1 = fmaxf(m1, mx1);
        float corr0 = __expf(m0 - nm0), corr1 = __expf(m1 - nm1);
        m0 = nm0; m1 = nm1;

        float rs0 = 0.f, rs1 = 0.f;
        uint32_t ph01[8], ph23[8], pl01[8], pl23[8];
        #pragma unroll
        for (int nt = 0; nt < 8; nt++) {
            float e0 = __expf(sacc[nt][0] - nm0);
            float e1 = __expf(sacc[nt][1] - nm0);
            float e2 = __expf(sacc[nt][2] - nm1);
            float e3 = __expf(sacc[nt][3] - nm1);
            rs0 += e0 + e1; rs1 += e2 + e3;
            __nv_bfloat162 h01 = __floats2bfloat162_rn(e0, e1);
            __nv_bfloat162 h23 = __floats2bfloat162_rn(e2, e3);
            __nv_bfloat162 lo01 = __floats2bfloat162_rn(
                e0 - __bfloat162float(h01.x), e1 - __bfloat162float(h01.y));
            __nv_bfloat162 lo23 = __floats2bfloat162_rn(
                e2 - __bfloat162float(h23.x), e3 - __bfloat162float(h23.y));
            ph01[nt] = *(uint32_t*)&h01;
            ph23[nt] = *(uint32_t*)&h23;
            pl01[nt] = *(uint32_t*)&lo01;
            pl23[nt] = *(uint32_t*)&lo23;
        }
        rs0 += __shfl_xor_sync(0xffffffffu, rs0, 1);
        rs0 += __shfl_xor_sync(0xffffffffu, rs0, 2);
        rs1 += __shfl_xor_sync(0xffffffffu, rs1, 1);
        rs1 += __shfl_xor_sync(0xffffffffu, rs1, 2);
        l0 = l0 * corr0 + rs0;
        l1 = l1 * corr1 + rs1;

        #pragma unroll
        for (int nto = 0; nto < 16; nto++) {
            oacc[nto][0] *= corr0; oacc[nto][1] *= corr0;
            oacc[nto][2] *= corr1; oacc[nto][3] *= corr1;
        }

        #pragma unroll
        for (int j = 0; j < 4; j++) {
            uint32_t a0h = ph01[2 * j],     a1h = ph23[2 * j];
            uint32_t a2h = ph01[2 * j + 1], a3h = ph23[2 * j + 1];
            uint32_t a0l = pl01[2 * j],     a1l = pl23[2 * j];
            uint32_t a2l = pl01[2 * j + 1], a3l = pl23[2 * j + 1];
            #pragma unroll
            for (int nto = 0; nto < 16; nto++) {
                const __nv_bfloat16* pv = &sVh[(nto * 8 + gid) * FVS + j * 16 + 2 * tig];
                uint32_t vh0 = *(const uint32_t*)pv;
                uint32_t vh1 = *(const uint32_t*)(pv + 8);
                const __nv_bfloat16* pvl = &sVl[(nto * 8 + gid) * FVS + j * 16 + 2 * tig];
                uint32_t vl0 = *(const uint32_t*)pvl;
                uint32_t vl1 = *(const uint32_t*)(pvl + 8);
                MMA16816(oacc[nto], a0h, a1h, a2h, a3h, vh0, vh1);
                MMA16816(oacc[nto], a0h, a1h, a2h, a3h, vl0, vl1);
                MMA16816(oacc[nto], a0l, a1l, a2l, a3l, vh0, vh1);
            }
        }
    }

    float i0 = 1.f / l0, i1 = 1.f / l1;
    #pragma unroll
    for (int nto = 0; nto < 16; nto++) {
        int col = h * HDc + nto * 8 + 2 * tig;
        *(float2*)&g_attn[((size_t)(b * Sc + row0)) * Dc + col] =
            make_float2(oacc[nto][0] * i0, oacc[nto][1] * i0);
        *(float2*)&g_attn[((size_t)(b * Sc + row1)) * Dc + col] =
            make_float2(oacc[nto][2] * i1, oacc[nto][3] * i1);
    }
}

// ---------------------------------------------------------------------------
// Adapter projection, deterministic 2-pass k-split
// ---------------------------------------------------------------------------
__global__ __launch_bounds__(256) void adapter_proj_kernel(
    const float* __restrict__ A, const float* __restrict__ W,
    float* __restrict__ P)
{
    const int ks = blockIdx.x;
    const int l  = blockIdx.y;
    const int t  = threadIdx.x;
    float acc[8];
    #pragma unroll
    for (int i = 0; i < 8; i++) acc[i] = 0.f;
    for (int k = ks * 128; k < ks * 128 + 128; k++) {
        float a = A[l * Dc + k];
        const float* wr = &W[(size_t)k * Dc + t * 8];
        float4 w0 = *(const float4*)wr;
        float4 w1 = *(const float4*)(wr + 4);
        acc[0] += a * w0.x; acc[1] += a * w0.y;
        acc[2] += a * w0.z; acc[3] += a * w0.w;
        acc[4] += a * w1.x; acc[5] += a * w1.y;
        acc[6] += a * w1.z; acc[7] += a * w1.w;
    }
    float* o = &P[((size_t)l * 16 + ks) * Dc + t * 8];
    *(float4*)o       = make_float4(acc[0], acc[1], acc[2], acc[3]);
    *(float4*)(o + 4) = make_float4(acc[4], acc[5], acc[6], acc[7]);
}

__global__ __launch_bounds__(256) void adapter_reduce_kernel(
    const float* __restrict__ P, float* __restrict__ C)
{
    int idx = blockIdx.x * 256 + threadIdx.x;
    int l = idx >> 11, n = idx & 2047;
    float s = 0.f;
    #pragma unroll
    for (int ks = 0; ks < 16; ks++)
        s += P[((size_t)l * 16 + ks) * Dc + n];
    C[idx] = s;
}

// ---------------------------------------------------------------------------
// Adapter attention: one warp per (b,s,h). out += gate[h] * softmax(q·akᵀ) av
// ---------------------------------------------------------------------------
__global__ __launch_bounds__(256) void adapter_attn_kernel(
    const float* __restrict__ gate)
{
    int gw = (blockIdx.x * blockDim.x + threadIdx.x) >> 5;
    int lane = threadIdx.x & 31;
    if (gw >= Bc * Sc * Hc) return;
    int h = gw % Hc;
    int s = (gw / Hc) % Sc;
    int b = gw / (Hc * Sc);

    size_t qoff = ((size_t)(b * Sc + s)) * Dc + h * HDc + lane * 4;
    float4 q4 = *(const float4*)(g_q + qoff);

    float scv[Lc];
    #pragma unroll
    for (int l = 0; l < Lc; l++) {
        float4 a4 = *(const float4*)(g_ak + (size_t)l * Dc + h * HDc + lane * 4);
        float p = q4.x * a4.x + q4.y * a4.y + q4.z * a4.z + q4.w * a4.w;
        #pragma unroll
        for (int o = 16; o > 0; o >>= 1)
            p += __shfl_xor_sync(0xffffffffu, p, o);
        scv[l] = p * SCALE;
    }
    float m = scv[0];
    #pragma unroll
    for (int l = 1; l < Lc; l++) m = fmaxf(m, scv[l]);
    float sum = 0.f;
    float e[Lc];
    #pragma unroll
    for (int l = 0; l < Lc; l++) { e[l] = expf(scv[l] - m); sum += e[l]; }
    float g = gate[h] / sum;

    float4 acc = make_float4(0.f, 0.f, 0.f, 0.f);
    #pragma unroll
    for (int l = 0; l < Lc; l++) {
        float4 a4 = *(const float4*)(g_av + (size_t)l * Dc + h * HDc + lane * 4);
        acc.x += e[l] * a4.x;
        acc.y += e[l] * a4.y;
        acc.z += e[l] * a4.z;
        acc.w += e[l] * a4.w;
    }
    float4 cur = *(float4*)(g_attn + qoff);
    cur.x += g * acc.x;
    cur.y += g * acc.y;
    cur.z += g * acc.z;
    cur.w += g * acc.w;
    *(float4*)(g_attn + qoff) = cur;
}

// ---------------------------------------------------------------------------
extern "C" void kernel_launch(void* const* d_in, const int* in_sizes, int n_in,
                              void* d_out, int out_size)
{
    const float* x       = (const float*)d_in[0];
    const float* wq      = (const float*)d_in[1];
    const float* wk      = (const float*)d_in[2];
    const float* wv      = (const float*)d_in[3];
    const float* wo      = (const float*)d_in[4];
    const float* adapter = (const float*)d_in[5];
    const float* gate    = (const float*)d_in[6];
    const float* fcos    = (const float*)d_in[7];
    const float* fsin    = (const float*)d_in[8];
    float* out = (float*)d_out;

    float *q, *k, *v, *attn, *ak, *av, *part;
    __nv_bfloat16 *xh, *xl, *wth, *wtl, *qh, *ql, *kh, *kl, *vth, *vtl;
    cudaGetSymbolAddress((void**)&q,    g_q);
    cudaGetSymbolAddress((void**)&k,    g_k);
    cudaGetSymbolAddress((void**)&v,    g_v);
    cudaGetSymbolAddress((void**)&attn, g_attn);
    cudaGetSymbolAddress((void**)&ak,   g_ak);
    cudaGetSymbolAddress((void**)&av,   g_av);
    cudaGetSymbolAddress((void**)&part, g_partial);
    cudaGetSymbolAddress((void**)&xh,   g_xh);
    cudaGetSymbolAddress((void**)&xl,   g_xl);
    cudaGetSymbolAddress((void**)&wth,  g_wth);
    cudaGetSymbolAddress((void**)&wtl,  g_wtl);
    cudaGetSymbolAddress((void**)&qh,   g_qh);
    cudaGetSymbolAddress((void**)&ql,   g_ql);
    cudaGetSymbolAddress((void**)&kh,   g_kh);
    cudaGetSymbolAddress((void**)&kl,   g_kl);
    cudaGetSymbolAddress((void**)&vth,  g_vth);
    cudaGetSymbolAddress((void**)&vtl,  g_vtl);

    const int M = Bc * Sc;   // 4096
    dim3 ggrid(Dc / 128, M / 128);
    dim3 wgrid(Dc / 32, Dc / 32);

    cudaFuncSetAttribute(mma_gemm_kernel,
                         cudaFuncAttributeMaxDynamicSharedMemorySize,
                         GEMM_SMEM);

    // split x -> bf16 hi/lo
    split_kernel<<<(M * Dc / 4) / 256, 256>>>(x, xh, xl);

    // Q/K/V projections on tensor cores
    wtrans_kernel<<<wgrid, 256>>>(wq, wth, wtl, Dc, Dc);
    mma_gemm_kernel<<<ggrid, 256, GEMM_SMEM>>>(xh, xl, wth, wtl, q, M, Dc, Dc);
    wtrans_kernel<<<wgrid, 256>>>(wk, wth, wtl, Dc, Dc);
    mma_gemm_kernel<<<ggrid, 256, GEMM_SMEM>>>(xh, xl, wth, wtl, k, M, Dc, Dc);
    wtrans_kernel<<<wgrid, 256>>>(wv, wth, wtl, Dc, Dc);
    mma_gemm_kernel<<<ggrid, 256, GEMM_SMEM>>>(xh, xl, wth, wtl, v, M, Dc, Dc);

    // fused RoPE + split (q keeps fp32 for adapter path; k does not)
    int npairs = Bc * Sc * Hc * (HDc / 2);
    rope_split_kernel<<<npairs / 256, 256>>>(q, fcos, fsin, qh, ql, 1);
    rope_split_kernel<<<npairs / 256, 256>>>(k, fcos, fsin, kh, kl, 0);
    vtrans_kernel<<<dim3(Sc / 32, HDc / 32, Bc * Hc), 256>>>(v, vth, vtl);

    adapter_proj_kernel<<<dim3(16, Lc), 256>>>(adapter, wk, part);
    adapter_reduce_kernel<<<(Lc * Dc) / 256, 256>>>(part, ak);
    adapter_proj_kernel<<<dim3(16, Lc), 256>>>(adapter, wv, part);
    adapter_reduce_kernel<<<(Lc * Dc) / 256, 256>>>(part, av);

    cudaFuncSetAttribute(flash_mma_kernel,
                         cudaFuncAttributeMaxDynamicSharedMemorySize,
                         FLASH_SMEM);
    flash_mma_kernel<<<dim3(Sc / 128, Hc, Bc), 256, FLASH_SMEM>>>();

    adapter_attn_kernel<<<(Bc * Sc * Hc * 32) / 256, 256>>>(gate);

    // Output projection
    split_kernel<<<(M * Dc / 4) / 256, 256>>>(attn, xh, xl);
    wtrans_kernel<<<wgrid, 256>>>(wo, wth, wtl, Dc, Dc);
    mma_gemm_kernel<<<ggrid, 256, GEMM_SMEM>>>(xh, xl, wth, wtl, out, M, Dc, Dc);
}

// round 6
// speedup vs baseline: 4.7346x; 1.0697x over previous
#include <cuda_runtime.h>
#include <cuda_bf16.h>
#include <math.h>
#include <stdint.h>

#define Bc 2
#define Sc 2048
#define Dc 2048
#define Hc 16
#define HDc 128
#define Lc 10

// Scratch (static device globals — allocation-free per harness rules)
__device__ float g_q[Bc*Sc*Dc];
__device__ float g_k[Bc*Sc*Dc];
__device__ float g_v[Bc*Sc*Dc];
__device__ float g_attn[Bc*Sc*Dc];
__device__ float g_ak[Lc*Dc];
__device__ float g_av[Lc*Dc];
__device__ float g_partial[Lc*16*Dc];
// bf16 split scratch
__device__ __nv_bfloat16 g_xh[Bc*Sc*Dc];
__device__ __nv_bfloat16 g_xl[Bc*Sc*Dc];
__device__ __nv_bfloat16 g_wth[3*Dc*Dc];   // stacked W^T hi [3*D rows][K]
__device__ __nv_bfloat16 g_wtl[3*Dc*Dc];   // stacked W^T lo
__device__ __nv_bfloat16 g_qh[Bc*Sc*Dc];
__device__ __nv_bfloat16 g_ql[Bc*Sc*Dc];
__device__ __nv_bfloat16 g_kh[Bc*Sc*Dc];
__device__ __nv_bfloat16 g_kl[Bc*Sc*Dc];
__device__ __nv_bfloat16 g_vth[Bc*Sc*Dc];  // [B,H,HD,S]
__device__ __nv_bfloat16 g_vtl[Bc*Sc*Dc];  // [B,H,HD,S]

#define SCALE 0.08838834764831845f  // 1/sqrt(128)

// ---------------------------------------------------------------------------
// mma.sync + ldmatrix + cp.async helpers (baseline PTX, ok on plain sm_103)
// ---------------------------------------------------------------------------
#define MMA16816(c, a0, a1, a2, a3, b0, b1) \
    asm volatile( \
        "mma.sync.aligned.m16n8k16.row.col.f32.bf16.bf16.f32 " \
        "{%0,%1,%2,%3}, {%4,%5,%6,%7}, {%8,%9}, {%0,%1,%2,%3};" \
        : "+f"((c)[0]), "+f"((c)[1]), "+f"((c)[2]), "+f"((c)[3]) \
        : "r"(a0), "r"(a1), "r"(a2), "r"(a3), "r"(b0), "r"(b1))

#define LDSM4(r0, r1, r2, r3, addr) \
    asm volatile("ldmatrix.sync.aligned.m8n8.x4.shared.b16 {%0,%1,%2,%3}, [%4];" \
                 : "=r"(r0), "=r"(r1), "=r"(r2), "=r"(r3) : "r"(addr))

__device__ __forceinline__ uint32_t smem_u32(const void* p) {
    uint32_t a;
    asm("{ .reg .u64 t; cvta.to.shared.u64 t, %1; cvt.u32.u64 %0, t; }"
        : "=r"(a) : "l"(p));
    return a;
}
#define CPA16(saddr, gptr) \
    asm volatile("cp.async.cg.shared.global [%0], [%1], 16;" \
                 :: "r"(saddr), "l"(gptr))
#define CPA_COMMIT() asm volatile("cp.async.commit_group;")
#define CPA_WAIT(n)  asm volatile("cp.async.wait_group %0;" :: "n"(n))

// ---------------------------------------------------------------------------
// Elementwise fp32 -> bf16 hi/lo split
// ---------------------------------------------------------------------------
__global__ __launch_bounds__(256) void split_kernel(
    const float* __restrict__ x, __nv_bfloat16* __restrict__ h,
    __nv_bfloat16* __restrict__ l)
{
    int i = blockIdx.x * 256 + threadIdx.x;
    float4 v = ((const float4*)x)[i];
    __nv_bfloat162 h01, h23, l01, l23;
    h01.x = __float2bfloat16(v.x);
    h01.y = __float2bfloat16(v.y);
    h23.x = __float2bfloat16(v.z);
    h23.y = __float2bfloat16(v.w);
    l01.x = __float2bfloat16(v.x - __bfloat162float(h01.x));
    l01.y = __float2bfloat16(v.y - __bfloat162float(h01.y));
    l23.x = __float2bfloat16(v.z - __bfloat162float(h23.x));
    l23.y = __float2bfloat16(v.w - __bfloat162float(h23.y));
    ((__nv_bfloat162*)h)[i * 2 + 0] = h01;
    ((__nv_bfloat162*)h)[i * 2 + 1] = h23;
    ((__nv_bfloat162*)l)[i * 2 + 0] = l01;
    ((__nv_bfloat162*)l)[i * 2 + 1] = l23;
}

// ---------------------------------------------------------------------------
// Fused RoPE + bf16 split.
// ---------------------------------------------------------------------------
__global__ __launch_bounds__(256) void rope_split_kernel(
    float* __restrict__ d, const float* __restrict__ fc,
    const float* __restrict__ fs, __nv_bfloat16* __restrict__ ph,
    __nv_bfloat16* __restrict__ pl, int writeback)
{
    int idx = blockIdx.x * blockDim.x + threadIdx.x;
    int j = idx & 63;
    int s = ((idx >> 6) / Hc) % Sc;
    float2 v = ((const float2*)d)[idx];
    float c  = fc[s * 64 + j];
    float sn = fs[s * 64 + j];
    float o0 = v.x * c - v.y * sn;
    float o1 = v.x * sn + v.y * c;
    if (writeback) ((float2*)d)[idx] = make_float2(o0, o1);
    __nv_bfloat162 h2, l2;
    h2.x = __float2bfloat16(o0);
    h2.y = __float2bfloat16(o1);
    l2.x = __float2bfloat16(o0 - __bfloat162float(h2.x));
    l2.y = __float2bfloat16(o1 - __bfloat162float(h2.y));
    ((__nv_bfloat162*)ph)[idx] = h2;
    ((__nv_bfloat162*)pl)[idx] = l2;
}

// ---------------------------------------------------------------------------
// Transpose + split: W[K][N] f32 -> Th/Tl[N][K] bf16
// ---------------------------------------------------------------------------
__global__ __launch_bounds__(256) void wtrans_kernel(
    const float* __restrict__ W, __nv_bfloat16* __restrict__ Th,
    __nv_bfloat16* __restrict__ Tl, int K, int N)
{
    __shared__ float tile[32][33];
    const int k0 = blockIdx.x * 32, n0 = blockIdx.y * 32;
    const int t = threadIdx.x;
    const int r = t >> 5, c = t & 31;
    #pragma unroll
    for (int i = 0; i < 4; i++)
        tile[r + i * 8][c] = W[(size_t)(k0 + r + i * 8) * N + n0 + c];
    __syncthreads();
    #pragma unroll
    for (int i = 0; i < 4; i++) {
        int n = r + i * 8;
        float v = tile[c][n];
        __nv_bfloat16 h = __float2bfloat16(v);
        Th[(size_t)(n0 + n) * K + k0 + c] = h;
        Tl[(size_t)(n0 + n) * K + k0 + c] =
            __float2bfloat16(v - __bfloat162float(h));
    }
}

// ---------------------------------------------------------------------------
// V transpose+split: v f32 [B,S,H,HD] -> vth/vtl bf16 [B,H,HD,S]
// ---------------------------------------------------------------------------
__global__ __launch_bounds__(256) void vtrans_kernel(
    const float* __restrict__ v, __nv_bfloat16* __restrict__ Th,
    __nv_bfloat16* __restrict__ Tl)
{
    __shared__ float tile[32][33];
    const int s0 = blockIdx.x * 32, d0 = blockIdx.y * 32;
    const int bh = blockIdx.z;
    const int b = bh >> 4, h = bh & 15;
    const int t = threadIdx.x;
    const int r = t >> 5, c = t & 31;
    #pragma unroll
    for (int i = 0; i < 4; i++) {
        int sl = r + i * 8;
        tile[sl][c] = v[((size_t)(b * Sc + s0 + sl)) * Dc + h * HDc + d0 + c];
    }
    __syncthreads();
    #pragma unroll
    for (int i = 0; i < 4; i++) {
        int dl = r + i * 8;
        float val = tile[c][dl];
        __nv_bfloat16 hb = __float2bfloat16(val);
        size_t o = ((size_t)(bh * HDc + d0 + dl)) * Sc + s0 + c;
        Th[o] = hb;
        Tl[o] = __float2bfloat16(val - __bfloat162float(hb));
    }
}

// ---------------------------------------------------------------------------
// bf16x3 tensor-core GEMM, 3-stage cp.async + ldmatrix.
// C[M,N] = A[M,K] @ W[K,N]; output CTA-routed across C0/C1/C2 by bn>>11.
// CTA 128x128, BK=32, 8 warps (2m x 4n).
// ---------------------------------------------------------------------------
#define SROW 40
#define STG_ELEMS (4 * 128 * SROW)            // 20480 bf16 per stage
#define NSTAGE 3
#define GEMM_SMEM (NSTAGE * STG_ELEMS * 2)    // 122880 bytes

__global__ __launch_bounds__(256, 1) void mma_gemm_kernel(
    const __nv_bfloat16* __restrict__ Ah, const __nv_bfloat16* __restrict__ Al,
    const __nv_bfloat16* __restrict__ BhT, const __nv_bfloat16* __restrict__ BlT,
    float* __restrict__ C0, float* __restrict__ C1, float* __restrict__ C2,
    int M, int N, int K)
{
    extern __shared__ __align__(16) __nv_bfloat16 dsm[];
    const uint32_t sb = smem_u32(dsm);

    const int t = threadIdx.x, lane = t & 31, wid = t >> 5;
    const int wm = wid & 1, wn = wid >> 1;
    const int bm = blockIdx.y * 128, bn = blockIdx.x * 128;
    const int gid = lane >> 2, tig = lane & 3;

    const int seg = bn >> 11;
    float* C = (seg == 0) ? C0 : (seg == 1) ? C1 : C2;
    const int cn = bn & 2047;

    // cp.async coords
    const int lrow0 = t >> 2, lch0 = (t & 3) * 8;
    const int lrow1 = (t + 256) >> 2, lch1 = ((t + 256) & 3) * 8;

    // ldmatrix per-lane element offsets within a stage
    const int aoffE = (wm * 64 + (lane & 15)) * SROW + ((lane >> 4) & 1) * 8;
    const int boffE = (wn * 32 + ((lane >> 4) & 1) * 8 + (lane & 7)) * SROW
                    + ((lane >> 3) & 1) * 8;

    float acc[4][4][4];
    #pragma unroll
    for (int a = 0; a < 4; a++)
        #pragma unroll
        for (int b = 0; b < 4; b++)
            #pragma unroll
            for (int cc = 0; cc < 4; cc++) acc[a][b][cc] = 0.f;

    const int nst = K >> 5;

    #define LOAD_STAGE(stg, k0) do {                                        \
        uint32_t base = sb + (stg) * STG_ELEMS * 2;                         \
        size_t ga0 = (size_t)(bm + lrow0) * K + (k0) + lch0;                \
        size_t gb0 = (size_t)(bn + lrow0) * K + (k0) + lch0;                \
        size_t ga1 = (size_t)(bm + lrow1) * K + (k0) + lch1;                \
        size_t gb1 = (size_t)(bn + lrow1) * K + (k0) + lch1;                \
        CPA16(base + (0 * 5120 + lrow0 * SROW + lch0) * 2, &Ah[ga0]);       \
        CPA16(base + (1 * 5120 + lrow0 * SROW + lch0) * 2, &Al[ga0]);       \
        CPA16(base + (2 * 5120 + lrow0 * SROW + lch0) * 2, &BhT[gb0]);      \
        CPA16(base + (3 * 5120 + lrow0 * SROW + lch0) * 2, &BlT[gb0]);      \
        CPA16(base + (0 * 5120 + lrow1 * SROW + lch1) * 2, &Ah[ga1]);       \
        CPA16(base + (1 * 5120 + lrow1 * SROW + lch1) * 2, &Al[ga1]);       \
        CPA16(base + (2 * 5120 + lrow1 * SROW + lch1) * 2, &BhT[gb1]);      \
        CPA16(base + (3 * 5120 + lrow1 * SROW + lch1) * 2, &BlT[gb1]);      \
    } while (0)

    LOAD_STAGE(0, 0);
    CPA_COMMIT();
    LOAD_STAGE(1, 32);
    CPA_COMMIT();

    for (int it = 0; it < nst; it++) {
        if (it == nst - 1) { CPA_WAIT(0); } else { CPA_WAIT(1); }
        __syncthreads();

        const uint32_t base = sb + (it % NSTAGE) * STG_ELEMS * 2;

        #pragma unroll
        for (int ks = 0; ks < 2; ks++) {
            uint32_t ah[4][4], al[4][4];
            #pragma unroll
            for (int mt = 0; mt < 4; mt++) {
                uint32_t aaddr = base + (aoffE + mt * 16 * SROW + ks * 16) * 2;
                LDSM4(ah[mt][0], ah[mt][1], ah[mt][2], ah[mt][3], aaddr);
                LDSM4(al[mt][0], al[mt][1], al[mt][2], al[mt][3],
                      aaddr + 5120 * 2);
            }
            #pragma unroll
            for (int ntp = 0; ntp < 2; ntp++) {
                uint32_t baddr = base +
                    (10240 + boffE + ntp * 16 * SROW + ks * 16) * 2;
                uint32_t bh0, bh1, bh2, bh3, bl0, bl1, bl2, bl3;
                LDSM4(bh0, bh1, bh2, bh3, baddr);
                LDSM4(bl0, bl1, bl2, bl3, baddr + 5120 * 2);
                #pragma unroll
                for (int mt = 0; mt < 4; mt++) {
                    MMA16816(acc[mt][2 * ntp], ah[mt][0], ah[mt][1], ah[mt][2], ah[mt][3], bh0, bh1);
                    MMA16816(acc[mt][2 * ntp], ah[mt][0], ah[mt][1], ah[mt][2], ah[mt][3], bl0, bl1);
                    MMA16816(acc[mt][2 * ntp], al[mt][0], al[mt][1], al[mt][2], al[mt][3], bh0, bh1);
                    MMA16816(acc[mt][2 * ntp + 1], ah[mt][0], ah[mt][1], ah[mt][2], ah[mt][3], bh2, bh3);
                    MMA16816(acc[mt][2 * ntp + 1], ah[mt][0], ah[mt][1], ah[mt][2], ah[mt][3], bl2, bl3);
                    MMA16816(acc[mt][2 * ntp + 1], al[mt][0], al[mt][1], al[mt][2], al[mt][3], bh2, bh3);
                }
            }
        }
        __syncthreads();
        if (it + 2 < nst) {
            LOAD_STAGE((it + 2) % NSTAGE, (it + 2) * 32);
            CPA_COMMIT();
        }
    }

    #pragma unroll
    for (int mt = 0; mt < 4; mt++) {
        int row = bm + wm * 64 + mt * 16 + gid;
        #pragma unroll
        for (int nt = 0; nt < 4; nt++) {
            int col = cn + wn * 32 + nt * 8 + tig * 2;
            *(float2*)&C[(size_t)row * Dc + col] =
                make_float2(acc[mt][nt][0], acc[mt][nt][1]);
            *(float2*)&C[(size_t)(row + 8) * Dc + col] =
                make_float2(acc[mt][nt][2], acc[mt][nt][3]);
        }
    }
}

// ---------------------------------------------------------------------------
// Flash attention on tensor cores (bf16x3) + ldmatrix. BM=128, BN=64.
// ---------------------------------------------------------------------------
#define FQS 136
#define FVS 72
#define FLASH_SMEM ((2*128*FQS + 2*64*FQS + 2*128*FVS) * 2)

__global__ __launch_bounds__(256, 1) void flash_mma_kernel()
{
    extern __shared__ __align__(16) __nv_bfloat16 fsm[];
    __nv_bfloat16* sQh = fsm;
    __nv_bfloat16* sQl = sQh + 128 * FQS;
    __nv_bfloat16* sKh = sQl + 128 * FQS;
    __nv_bfloat16* sKl = sKh + 64 * FQS;
    __nv_bfloat16* sVh = sKl + 64 * FQS;
    __nv_bfloat16* sVl = sVh + 128 * FVS;
    const uint32_t uQh = smem_u32(sQh), uQl = smem_u32(sQl);
    const uint32_t uKh = smem_u32(sKh), uKl = smem_u32(sKl);
    const uint32_t uVh = smem_u32(sVh), uVl = smem_u32(sVl);

    const int t = threadIdx.x, lane = t & 31, w = t >> 5;
    const int gid = lane >> 2, tig = lane & 3;
    const int qt = blockIdx.x, h = blockIdx.y, b = blockIdx.z;
    const int qbase = qt * 128;

    // ldmatrix per-lane element offsets
    const int qaoffE = (w * 16 + (lane & 15)) * FQS + ((lane >> 4) & 1) * 8;
    const int kboffE = (((lane >> 4) & 1) * 8 + (lane & 7)) * FQS
                     + ((lane >> 3) & 1) * 8;
    const int vboffE = (((lane >> 4) & 1) * 8 + (lane & 7)) * FVS
                     + ((lane >> 3) & 1) * 8;

    #pragma unroll
    for (int i = 0; i < 8; i++) {
        int u = t + i * 256;
        int row = u >> 4, c8 = (u & 15) * 8;
        size_t g = ((size_t)(b * Sc + qbase + row)) * Dc + h * HDc + c8;
        *(uint4*)&sQh[row * FQS + c8] = *(const uint4*)&g_qh[g];
        *(uint4*)&sQl[row * FQS + c8] = *(const uint4*)&g_ql[g];
    }

    const int row0 = qbase + w * 16 + gid;
    const int row1 = row0 + 8;

    float m0 = -1e30f, m1 = -1e30f, l0 = 0.f, l1 = 0.f;
    float oacc[16][4];
    #pragma unroll
    for (int i = 0; i < 16; i++)
        #pragma unroll
        for (int j = 0; j < 4; j++) oacc[i][j] = 0.f;

    const int ntk = 2 * qt + 2;
    for (int kt = 0; kt < ntk; kt++) {
        const int kbase = kt * 64;
        __syncthreads();
        #pragma unroll
        for (int i = 0; i < 4; i++) {
            int u = t + i * 256;
            int krow = u >> 4, c8 = (u & 15) * 8;
            size_t gk = ((size_t)(b * Sc + kbase + krow)) * Dc + h * HDc + c8;
            CPA16(uKh + (krow * FQS + c8) * 2, &g_kh[gk]);
            CPA16(uKl + (krow * FQS + c8) * 2, &g_kl[gk]);
            int vrow = u >> 3, v8 = (u & 7) * 8;
            size_t gv = ((size_t)((b * Hc + h) * HDc + vrow)) * Sc + kbase + v8;
            CPA16(uVh + (vrow * FVS + v8) * 2, &g_vth[gv]);
            CPA16(uVl + (vrow * FVS + v8) * 2, &g_vtl[gv]);
        }
        CPA_COMMIT();
        CPA_WAIT(0);
        __syncthreads();

        // ---- S = Q K^T ----
        float sacc[8][4];
        #pragma unroll
        for (int nt = 0; nt < 8; nt++)
            #pragma unroll
            for (int j = 0; j < 4; j++) sacc[nt][j] = 0.f;

        #pragma unroll
        for (int kc = 0; kc < 8; kc++) {
            uint32_t ah0, ah1, ah2, ah3, al0, al1, al2, al3;
            LDSM4(ah0, ah1, ah2, ah3, uQh + (qaoffE + kc * 16) * 2);
            LDSM4(al0, al1, al2, al3, uQl + (qaoffE + kc * 16) * 2);
            #pragma unroll
            for (int ntp = 0; ntp < 4; ntp++) {
                uint32_t kaddr = (kboffE + ntp * 16 * FQS + kc * 16) * 2;
                uint32_t bh0, bh1, bh2, bh3, bl0, bl1, bl2, bl3;
                LDSM4(bh0, bh1, bh2, bh3, uKh + kaddr);
                LDSM4(bl0, bl1, bl2, bl3, uKl + kaddr);
                MMA16816(sacc[2 * ntp], ah0, ah1, ah2, ah3, bh0, bh1);
                MMA16816(sacc[2 * ntp], ah0, ah1, ah2, ah3, bl0, bl1);
                MMA16816(sacc[2 * ntp], al0, al1, al2, al3, bh0, bh1);
                MMA16816(sacc[2 * ntp + 1], ah0, ah1, ah2, ah3, bh2, bh3);
                MMA16816(sacc[2 * ntp + 1], ah0, ah1, ah2, ah3, bl2, bl3);
                MMA16816(sacc[2 * ntp + 1], al0, al1, al2, al3, bh2, bh3);
            }
        }

        const bool need_mask = (kt >= 2 * qt);
        #pragma unroll
        for (int nt = 0; nt < 8; nt++) {
            int c0 = kbase + nt * 8 + 2 * tig;
            float v0 = sacc[nt][0] * SCALE;
            float v1 = sacc[nt][1] * SCALE;
            float v2 = sacc[nt][2] * SCALE;
            float v3 = sacc[nt][3] * SCALE;
            if (need_mask) {
                if (c0 > row0)     v0 -= 1e9f;
                if (c0 + 1 > row0) v1 -= 1e9f;
                if (c0 > row1)     v2 -= 1e9f;
                if (c0 + 1 > row1) v3 -= 1e9f;
            }
            sacc[nt][0] = v0; sacc[nt][1] = v1;
            sacc[nt][2] = v2; sacc[nt][3] = v3;
        }

        float mx0 = -1e30f, mx1 = -1e30f;
        #pragma unroll
        for (int nt = 0; nt < 8; nt++) {
            mx0 = fmaxf(mx0, fmaxf(sacc[nt][0], sacc[nt][1]));
            mx1 = fmaxf(mx1, fmaxf(sacc[nt][2], sacc[nt][3]));
        }
        mx0 = fmaxf(mx0, __shfl_xor_sync(0xffffffffu, mx0, 1));
        mx0 = fmaxf(mx0, __shfl_xor_sync(0xffffffffu, mx0, 2));
        mx1 = fmaxf(mx1, __shfl_xor_sync(0xffffffffu, mx1, 1));
        mx1 = fmaxf(mx1, __shfl_xor_sync(0xffffffffu, mx1, 2));
        float nm0 = fmaxf(m0, mx0), nm1 = fmaxf(m1, mx1);
        float corr0 = __expf(m0 - nm0), corr1 = __expf(m1 - nm1);
        m0 = nm0; m1 = nm1;

        float rs0 = 0.f, rs1 = 0.f;
        uint32_t ph01[8], ph23[8], pl01[8], pl23[8];
        #pragma unroll
        for (int nt = 0; nt < 8; nt++) {
            float e0 = __expf(sacc[nt][0] - nm0);
            float e1 = __expf(sacc[nt][1] - nm0);
            float e2 = __expf(sacc[nt][2] - nm1);
            float e3 = __expf(sacc[nt][3] - nm1);
            rs0 += e0 + e1; rs1 += e2 + e3;
            __nv_bfloat162 h01 = __floats2bfloat162_rn(e0, e1);
            __nv_bfloat162 h23 = __floats2bfloat162_rn(e2, e3);
            __nv_bfloat162 lo01 = __floats2bfloat162_rn(
                e0 - __bfloat162float(h01.x), e1 - __bfloat162float(h01.y));
            __nv_bfloat162 lo23 = __floats2bfloat162_rn(
                e2 - __bfloat162float(h23.x), e3 - __bfloat162float(h23.y));
            ph01[nt] = *(uint32_t*)&h01;
            ph23[nt] = *(uint32_t*)&h23;
            pl01[nt] = *(uint32_t*)&lo01;
            pl23[nt] = *(uint32_t*)&lo23;
        }
        rs0 += __shfl_xor_sync(0xffffffffu, rs0, 1);
        rs0 += __shfl_xor_sync(0xffffffffu, rs0, 2);
        rs1 += __shfl_xor_sync(0xffffffffu, rs1, 1);
        rs1 += __shfl_xor_sync(0xffffffffu, rs1, 2);
        l0 = l0 * corr0 + rs0;
        l1 = l1 * corr1 + rs1;

        #pragma unroll
        for (int nto = 0; nto < 16; nto++) {
            oacc[nto][0] *= corr0; oacc[nto][1] *= corr0;
            oacc[nto][2] *= corr1; oacc[nto][3] *= corr1;
        }

        // ---- O += P V ----
        #pragma unroll
        for (int j = 0; j < 4; j++) {
            uint32_t a0h = ph01[2 * j],     a1h = ph23[2 * j];
            uint32_t a2h = ph01[2 * j + 1], a3h = ph23[2 * j + 1];
            uint32_t a0l = pl01[2 * j],     a1l = pl23[2 * j];
            uint32_t a2l = pl01[2 * j + 1], a3l = pl23[2 * j + 1];
            #pragma unroll
            for (int ntp = 0; ntp < 8; ntp++) {
                uint32_t vaddr = (vboffE + ntp * 16 * FVS + j * 16) * 2;
                uint32_t vh0, vh1, vh2, vh3, vl0, vl1, vl2, vl3;
                LDSM4(vh0, vh1, vh2, vh3, uVh + vaddr);
                LDSM4(vl0, vl1, vl2, vl3, uVl + vaddr);
                MMA16816(oacc[2 * ntp], a0h, a1h, a2h, a3h, vh0, vh1);
                MMA16816(oacc[2 * ntp], a0h, a1h, a2h, a3h, vl0, vl1);
                MMA16816(oacc[2 * ntp], a0l, a1l, a2l, a3l, vh0, vh1);
                MMA16816(oacc[2 * ntp + 1], a0h, a1h, a2h, a3h, vh2, vh3);
                MMA16816(oacc[2 * ntp + 1], a0h, a1h, a2h, a3h, vl2, vl3);
                MMA16816(oacc[2 * ntp + 1], a0l, a1l, a2l, a3l, vh2, vh3);
            }
        }
    }

    float i0 = 1.f / l0, i1 = 1.f / l1;
    #pragma unroll
    for (int nto = 0; nto < 16; nto++) {
        int col = h * HDc + nto * 8 + 2 * tig;
        *(float2*)&g_attn[((size_t)(b * Sc + row0)) * Dc + col] =
            make_float2(oacc[nto][0] * i0, oacc[nto][1] * i0);
        *(float2*)&g_attn[((size_t)(b * Sc + row1)) * Dc + col] =
            make_float2(oacc[nto][2] * i1, oacc[nto][3] * i1);
    }
}

// ---------------------------------------------------------------------------
// Adapter projection, deterministic 2-pass k-split
// ---------------------------------------------------------------------------
__global__ __launch_bounds__(256) void adapter_proj_kernel(
    const float* __restrict__ A, const float* __restrict__ W,
    float* __restrict__ P)
{
    const int ks = blockIdx.x;
    const int l  = blockIdx.y;
    const int t  = threadIdx.x;
    float acc[8];
    #pragma unroll
    for (int i = 0; i < 8; i++) acc[i] = 0.f;
    for (int k = ks * 128; k < ks * 128 + 128; k++) {
        float a = A[l * Dc + k];
        const float* wr = &W[(size_t)k * Dc + t * 8];
        float4 w0 = *(const float4*)wr;
        float4 w1 = *(const float4*)(wr + 4);
        acc[0] += a * w0.x; acc[1] += a * w0.y;
        acc[2] += a * w0.z; acc[3] += a * w0.w;
        acc[4] += a * w1.x; acc[5] += a * w1.y;
        acc[6] += a * w1.z; acc[7] += a * w1.w;
    }
    float* o = &P[((size_t)l * 16 + ks) * Dc + t * 8];
    *(float4*)o       = make_float4(acc[0], acc[1], acc[2], acc[3]);
    *(float4*)(o + 4) = make_float4(acc[4], acc[5], acc[6], acc[7]);
}

__global__ __launch_bounds__(256) void adapter_reduce_kernel(
    const float* __restrict__ P, float* __restrict__ C)
{
    int idx = blockIdx.x * 256 + threadIdx.x;
    int l = idx >> 11, n = idx & 2047;
    float s = 0.f;
    #pragma unroll
    for (int ks = 0; ks < 16; ks++)
        s += P[((size_t)l * 16 + ks) * Dc + n];
    C[idx] = s;
}

// ---------------------------------------------------------------------------
// Adapter attention: one warp per (b,s,h). out += gate[h] * softmax(q·akᵀ) av
// ---------------------------------------------------------------------------
__global__ __launch_bounds__(256) void adapter_attn_kernel(
    const float* __restrict__ gate)
{
    int gw = (blockIdx.x * blockDim.x + threadIdx.x) >> 5;
    int lane = threadIdx.x & 31;
    if (gw >= Bc * Sc * Hc) return;
    int h = gw % Hc;
    int s = (gw / Hc) % Sc;
    int b = gw / (Hc * Sc);

    size_t qoff = ((size_t)(b * Sc + s)) * Dc + h * HDc + lane * 4;
    float4 q4 = *(const float4*)(g_q + qoff);

    float scv[Lc];
    #pragma unroll
    for (int l = 0; l < Lc; l++) {
        float4 a4 = *(const float4*)(g_ak + (size_t)l * Dc + h * HDc + lane * 4);
        float p = q4.x * a4.x + q4.y * a4.y + q4.z * a4.z + q4.w * a4.w;
        #pragma unroll
        for (int o = 16; o > 0; o >>= 1)
            p += __shfl_xor_sync(0xffffffffu, p, o);
        scv[l] = p * SCALE;
    }
    float m = scv[0];
    #pragma unroll
    for (int l = 1; l < Lc; l++) m = fmaxf(m, scv[l]);
    float sum = 0.f;
    float e[Lc];
    #pragma unroll
    for (int l = 0; l < Lc; l++) { e[l] = expf(scv[l] - m); sum += e[l]; }
    float g = gate[h] / sum;

    float4 acc = make_float4(0.f, 0.f, 0.f, 0.f);
    #pragma unroll
    for (int l = 0; l < Lc; l++) {
        float4 a4 = *(const float4*)(g_av + (size_t)l * Dc + h * HDc + lane * 4);
        acc.x += e[l] * a4.x;
        acc.y += e[l] * a4.y;
        acc.z += e[l] * a4.z;
        acc.w += e[l] * a4.w;
    }
    float4 cur = *(float4*)(g_attn + qoff);
    cur.x += g * acc.x;
    cur.y += g * acc.y;
    cur.z += g * acc.z;
    cur.w += g * acc.w;
    *(float4*)(g_attn + qoff) = cur;
}

// ---------------------------------------------------------------------------
extern "C" void kernel_launch(void* const* d_in, const int* in_sizes, int n_in,
                              void* d_out, int out_size)
{
    const float* x       = (const float*)d_in[0];
    const float* wq      = (const float*)d_in[1];
    const float* wk      = (const float*)d_in[2];
    const float* wv      = (const float*)d_in[3];
    const float* wo      = (const float*)d_in[4];
    const float* adapter = (const float*)d_in[5];
    const float* gate    = (const float*)d_in[6];
    const float* fcos    = (const float*)d_in[7];
    const float* fsin    = (const float*)d_in[8];
    float* out = (float*)d_out;

    float *q, *k, *v, *attn, *ak, *av, *part;
    __nv_bfloat16 *xh, *xl, *wth, *wtl, *qh, *ql, *kh, *kl, *vth, *vtl;
    cudaGetSymbolAddress((void**)&q,    g_q);
    cudaGetSymbolAddress((void**)&k,    g_k);
    cudaGetSymbolAddress((void**)&v,    g_v);
    cudaGetSymbolAddress((void**)&attn, g_attn);
    cudaGetSymbolAddress((void**)&ak,   g_ak);
    cudaGetSymbolAddress((void**)&av,   g_av);
    cudaGetSymbolAddress((void**)&part, g_partial);
    cudaGetSymbolAddress((void**)&xh,   g_xh);
    cudaGetSymbolAddress((void**)&xl,   g_xl);
    cudaGetSymbolAddress((void**)&wth,  g_wth);
    cudaGetSymbolAddress((void**)&wtl,  g_wtl);
    cudaGetSymbolAddress((void**)&qh,   g_qh);
    cudaGetSymbolAddress((void**)&ql,   g_ql);
    cudaGetSymbolAddress((void**)&kh,   g_kh);
    cudaGetSymbolAddress((void**)&kl,   g_kl);
    cudaGetSymbolAddress((void**)&vth,  g_vth);
    cudaGetSymbolAddress((void**)&vtl,  g_vtl);

    const int M = Bc * Sc;   // 4096
    dim3 wgrid(Dc / 32, Dc / 32);

    cudaFuncSetAttribute(mma_gemm_kernel,
                         cudaFuncAttributeMaxDynamicSharedMemorySize,
                         GEMM_SMEM);

    // split x -> bf16 hi/lo
    split_kernel<<<(M * Dc / 4) / 256, 256>>>(x, xh, xl);

    // stacked W^T for fused QKV projection
    wtrans_kernel<<<wgrid, 256>>>(wq, wth,               wtl,               Dc, Dc);
    wtrans_kernel<<<wgrid, 256>>>(wk, wth + (size_t)Dc*Dc,   wtl + (size_t)Dc*Dc,   Dc, Dc);
    wtrans_kernel<<<wgrid, 256>>>(wv, wth + (size_t)2*Dc*Dc, wtl + (size_t)2*Dc*Dc, Dc, Dc);

    // fused QKV GEMM: N = 6144, CTA-routed outputs
    mma_gemm_kernel<<<dim3(3 * Dc / 128, M / 128), 256, GEMM_SMEM>>>(
        xh, xl, wth, wtl, q, k, v, M, 3 * Dc, Dc);

    // fused RoPE + split (q keeps fp32 for adapter path; k does not)
    int npairs = Bc * Sc * Hc * (HDc / 2);
    rope_split_kernel<<<npairs / 256, 256>>>(q, fcos, fsin, qh, ql, 1);
    rope_split_kernel<<<npairs / 256, 256>>>(k, fcos, fsin, kh, kl, 0);
    vtrans_kernel<<<dim3(Sc / 32, HDc / 32, Bc * Hc), 256>>>(v, vth, vtl);

    adapter_proj_kernel<<<dim3(16, Lc), 256>>>(adapter, wk, part);
    adapter_reduce_kernel<<<(Lc * Dc) / 256, 256>>>(part, ak);
    adapter_proj_kernel<<<dim3(16, Lc), 256>>>(adapter, wv, part);
    adapter_reduce_kernel<<<(Lc * Dc) / 256, 256>>>(part, av);

    cudaFuncSetAttribute(flash_mma_kernel,
                         cudaFuncAttributeMaxDynamicSharedMemorySize,
                         FLASH_SMEM);
    flash_mma_kernel<<<dim3(Sc / 128, Hc, Bc), 256, FLASH_SMEM>>>();

    adapter_attn_kernel<<<(Bc * Sc * Hc * 32) / 256, 256>>>(gate);

    // Output projection
    split_kernel<<<(M * Dc / 4) / 256, 256>>>(attn, xh, xl);
    wtrans_kernel<<<wgrid, 256>>>(wo, wth, wtl, Dc, Dc);
    mma_gemm_kernel<<<dim3(Dc / 128, M / 128), 256, GEMM_SMEM>>>(
        xh, xl, wth, wtl, out, out, out, M, Dc, Dc);
}

// round 7
// speedup vs baseline: 4.8151x; 1.0170x over previous
#include <cuda_runtime.h>
#include <cuda_bf16.h>
#include <math.h>
#include <stdint.h>

#define Bc 2
#define Sc 2048
#define Dc 2048
#define Hc 16
#define HDc 128
#define Lc 10

// Scratch (static device globals — allocation-free per harness rules)
__device__ float g_q[Bc*Sc*Dc];
__device__ float g_k[Bc*Sc*Dc];
__device__ float g_v[Bc*Sc*Dc];
__device__ float g_attn[Bc*Sc*Dc];
__device__ float g_ak[Lc*Dc];
__device__ float g_av[Lc*Dc];
__device__ float g_partial[Lc*16*Dc];
// bf16 split scratch
__device__ __nv_bfloat16 g_xh[Bc*Sc*Dc];
__device__ __nv_bfloat16 g_xl[Bc*Sc*Dc];
__device__ __nv_bfloat16 g_wth[3*Dc*Dc];   // stacked W^T hi [3*D rows][K]
__device__ __nv_bfloat16 g_wtl[3*Dc*Dc];   // stacked W^T lo
__device__ __nv_bfloat16 g_qh[Bc*Sc*Dc];
__device__ __nv_bfloat16 g_ql[Bc*Sc*Dc];
__device__ __nv_bfloat16 g_kh[Bc*Sc*Dc];
__device__ __nv_bfloat16 g_kl[Bc*Sc*Dc];
__device__ __nv_bfloat16 g_vth[Bc*Sc*Dc];  // [B,H,HD,S]
__device__ __nv_bfloat16 g_vtl[Bc*Sc*Dc];  // [B,H,HD,S]

#define SCALE 0.08838834764831845f  // 1/sqrt(128)

// ---------------------------------------------------------------------------
// mma.sync + ldmatrix + cp.async helpers
// ---------------------------------------------------------------------------
#define MMA16816(c, a0, a1, a2, a3, b0, b1) \
    asm volatile( \
        "mma.sync.aligned.m16n8k16.row.col.f32.bf16.bf16.f32 " \
        "{%0,%1,%2,%3}, {%4,%5,%6,%7}, {%8,%9}, {%0,%1,%2,%3};" \
        : "+f"((c)[0]), "+f"((c)[1]), "+f"((c)[2]), "+f"((c)[3]) \
        : "r"(a0), "r"(a1), "r"(a2), "r"(a3), "r"(b0), "r"(b1))

#define LDSM4(r0, r1, r2, r3, addr) \
    asm volatile("ldmatrix.sync.aligned.m8n8.x4.shared.b16 {%0,%1,%2,%3}, [%4];" \
                 : "=r"(r0), "=r"(r1), "=r"(r2), "=r"(r3) : "r"(addr))

__device__ __forceinline__ uint32_t smem_u32(const void* p) {
    uint32_t a;
    asm("{ .reg .u64 t; cvta.to.shared.u64 t, %1; cvt.u32.u64 %0, t; }"
        : "=r"(a) : "l"(p));
    return a;
}
#define CPA16(saddr, gptr) \
    asm volatile("cp.async.cg.shared.global [%0], [%1], 16;" \
                 :: "r"(saddr), "l"(gptr))
#define CPA_COMMIT() asm volatile("cp.async.commit_group;")
#define CPA_WAIT(n)  asm volatile("cp.async.wait_group %0;" :: "n"(n))

// ---------------------------------------------------------------------------
// Elementwise fp32 -> bf16 hi/lo split
// ---------------------------------------------------------------------------
__global__ __launch_bounds__(256) void split_kernel(
    const float* __restrict__ x, __nv_bfloat16* __restrict__ h,
    __nv_bfloat16* __restrict__ l)
{
    int i = blockIdx.x * 256 + threadIdx.x;
    float4 v = ((const float4*)x)[i];
    __nv_bfloat162 h01, h23, l01, l23;
    h01.x = __float2bfloat16(v.x);
    h01.y = __float2bfloat16(v.y);
    h23.x = __float2bfloat16(v.z);
    h23.y = __float2bfloat16(v.w);
    l01.x = __float2bfloat16(v.x - __bfloat162float(h01.x));
    l01.y = __float2bfloat16(v.y - __bfloat162float(h01.y));
    l23.x = __float2bfloat16(v.z - __bfloat162float(h23.x));
    l23.y = __float2bfloat16(v.w - __bfloat162float(h23.y));
    ((__nv_bfloat162*)h)[i * 2 + 0] = h01;
    ((__nv_bfloat162*)h)[i * 2 + 1] = h23;
    ((__nv_bfloat162*)l)[i * 2 + 0] = l01;
    ((__nv_bfloat162*)l)[i * 2 + 1] = l23;
}

// ---------------------------------------------------------------------------
// Fused RoPE + bf16 split.
// ---------------------------------------------------------------------------
__global__ __launch_bounds__(256) void rope_split_kernel(
    float* __restrict__ d, const float* __restrict__ fc,
    const float* __restrict__ fs, __nv_bfloat16* __restrict__ ph,
    __nv_bfloat16* __restrict__ pl, int writeback)
{
    int idx = blockIdx.x * blockDim.x + threadIdx.x;
    int j = idx & 63;
    int s = ((idx >> 6) / Hc) % Sc;
    float2 v = ((const float2*)d)[idx];
    float c  = fc[s * 64 + j];
    float sn = fs[s * 64 + j];
    float o0 = v.x * c - v.y * sn;
    float o1 = v.x * sn + v.y * c;
    if (writeback) ((float2*)d)[idx] = make_float2(o0, o1);
    __nv_bfloat162 h2, l2;
    h2.x = __float2bfloat16(o0);
    h2.y = __float2bfloat16(o1);
    l2.x = __float2bfloat16(o0 - __bfloat162float(h2.x));
    l2.y = __float2bfloat16(o1 - __bfloat162float(h2.y));
    ((__nv_bfloat162*)ph)[idx] = h2;
    ((__nv_bfloat162*)pl)[idx] = l2;
}

// ---------------------------------------------------------------------------
// Transpose + split, 3 weights in one launch: W[K][N] f32 -> Th/Tl[N][K] bf16
// blockIdx.z selects the weight / output segment.
// ---------------------------------------------------------------------------
__global__ __launch_bounds__(256) void wtrans3_kernel(
    const float* __restrict__ W0, const float* __restrict__ W1,
    const float* __restrict__ W2, __nv_bfloat16* __restrict__ Th,
    __nv_bfloat16* __restrict__ Tl)
{
    __shared__ float tile[32][33];
    const int z = blockIdx.z;
    const float* W = (z == 0) ? W0 : (z == 1) ? W1 : W2;
    __nv_bfloat16* Tho = Th + (size_t)z * Dc * Dc;
    __nv_bfloat16* Tlo = Tl + (size_t)z * Dc * Dc;
    const int k0 = blockIdx.x * 32, n0 = blockIdx.y * 32;
    const int t = threadIdx.x;
    const int r = t >> 5, c = t & 31;
    #pragma unroll
    for (int i = 0; i < 4; i++)
        tile[r + i * 8][c] = W[(size_t)(k0 + r + i * 8) * Dc + n0 + c];
    __syncthreads();
    #pragma unroll
    for (int i = 0; i < 4; i++) {
        int n = r + i * 8;
        float v = tile[c][n];
        __nv_bfloat16 h = __float2bfloat16(v);
        Tho[(size_t)(n0 + n) * Dc + k0 + c] = h;
        Tlo[(size_t)(n0 + n) * Dc + k0 + c] =
            __float2bfloat16(v - __bfloat162float(h));
    }
}

// ---------------------------------------------------------------------------
// V transpose+split: v f32 [B,S,H,HD] -> vth/vtl bf16 [B,H,HD,S]
// ---------------------------------------------------------------------------
__global__ __launch_bounds__(256) void vtrans_kernel(
    const float* __restrict__ v, __nv_bfloat16* __restrict__ Th,
    __nv_bfloat16* __restrict__ Tl)
{
    __shared__ float tile[32][33];
    const int s0 = blockIdx.x * 32, d0 = blockIdx.y * 32;
    const int bh = blockIdx.z;
    const int b = bh >> 4, h = bh & 15;
    const int t = threadIdx.x;
    const int r = t >> 5, c = t & 31;
    #pragma unroll
    for (int i = 0; i < 4; i++) {
        int sl = r + i * 8;
        tile[sl][c] = v[((size_t)(b * Sc + s0 + sl)) * Dc + h * HDc + d0 + c];
    }
    __syncthreads();
    #pragma unroll
    for (int i = 0; i < 4; i++) {
        int dl = r + i * 8;
        float val = tile[c][dl];
        __nv_bfloat16 hb = __float2bfloat16(val);
        size_t o = ((size_t)(bh * HDc + d0 + dl)) * Sc + s0 + c;
        Th[o] = hb;
        Tl[o] = __float2bfloat16(val - __bfloat162float(hb));
    }
}

// ---------------------------------------------------------------------------
// bf16x3 tensor-core GEMM, 3-stage cp.async + ldmatrix.
// ---------------------------------------------------------------------------
#define SROW 40
#define STG_ELEMS (4 * 128 * SROW)
#define NSTAGE 3
#define GEMM_SMEM (NSTAGE * STG_ELEMS * 2)

__global__ __launch_bounds__(256, 1) void mma_gemm_kernel(
    const __nv_bfloat16* __restrict__ Ah, const __nv_bfloat16* __restrict__ Al,
    const __nv_bfloat16* __restrict__ BhT, const __nv_bfloat16* __restrict__ BlT,
    float* __restrict__ C0, float* __restrict__ C1, float* __restrict__ C2,
    int M, int N, int K)
{
    extern __shared__ __align__(16) __nv_bfloat16 dsm[];
    const uint32_t sb = smem_u32(dsm);

    const int t = threadIdx.x, lane = t & 31, wid = t >> 5;
    const int wm = wid & 1, wn = wid >> 1;
    const int bm = blockIdx.y * 128, bn = blockIdx.x * 128;
    const int gid = lane >> 2, tig = lane & 3;

    const int seg = bn >> 11;
    float* C = (seg == 0) ? C0 : (seg == 1) ? C1 : C2;
    const int cn = bn & 2047;

    const int lrow0 = t >> 2, lch0 = (t & 3) * 8;
    const int lrow1 = (t + 256) >> 2, lch1 = ((t + 256) & 3) * 8;

    const int aoffE = (wm * 64 + (lane & 15)) * SROW + ((lane >> 4) & 1) * 8;
    const int boffE = (wn * 32 + ((lane >> 4) & 1) * 8 + (lane & 7)) * SROW
                    + ((lane >> 3) & 1) * 8;

    float acc[4][4][4];
    #pragma unroll
    for (int a = 0; a < 4; a++)
        #pragma unroll
        for (int b = 0; b < 4; b++)
            #pragma unroll
            for (int cc = 0; cc < 4; cc++) acc[a][b][cc] = 0.f;

    const int nst = K >> 5;

    #define LOAD_STAGE(stg, k0) do {                                        \
        uint32_t base = sb + (stg) * STG_ELEMS * 2;                         \
        size_t ga0 = (size_t)(bm + lrow0) * K + (k0) + lch0;                \
        size_t gb0 = (size_t)(bn + lrow0) * K + (k0) + lch0;                \
        size_t ga1 = (size_t)(bm + lrow1) * K + (k0) + lch1;                \
        size_t gb1 = (size_t)(bn + lrow1) * K + (k0) + lch1;                \
        CPA16(base + (0 * 5120 + lrow0 * SROW + lch0) * 2, &Ah[ga0]);       \
        CPA16(base + (1 * 5120 + lrow0 * SROW + lch0) * 2, &Al[ga0]);       \
        CPA16(base + (2 * 5120 + lrow0 * SROW + lch0) * 2, &BhT[gb0]);      \
        CPA16(base + (3 * 5120 + lrow0 * SROW + lch0) * 2, &BlT[gb0]);      \
        CPA16(base + (0 * 5120 + lrow1 * SROW + lch1) * 2, &Ah[ga1]);       \
        CPA16(base + (1 * 5120 + lrow1 * SROW + lch1) * 2, &Al[ga1]);       \
        CPA16(base + (2 * 5120 + lrow1 * SROW + lch1) * 2, &BhT[gb1]);      \
        CPA16(base + (3 * 5120 + lrow1 * SROW + lch1) * 2, &BlT[gb1]);      \
    } while (0)

    LOAD_STAGE(0, 0);
    CPA_COMMIT();
    LOAD_STAGE(1, 32);
    CPA_COMMIT();

    for (int it = 0; it < nst; it++) {
        if (it == nst - 1) { CPA_WAIT(0); } else { CPA_WAIT(1); }
        __syncthreads();

        const uint32_t base = sb + (it % NSTAGE) * STG_ELEMS * 2;

        #pragma unroll
        for (int ks = 0; ks < 2; ks++) {
            uint32_t ah[4][4], al[4][4];
            #pragma unroll
            for (int mt = 0; mt < 4; mt++) {
                uint32_t aaddr = base + (aoffE + mt * 16 * SROW + ks * 16) * 2;
                LDSM4(ah[mt][0], ah[mt][1], ah[mt][2], ah[mt][3], aaddr);
                LDSM4(al[mt][0], al[mt][1], al[mt][2], al[mt][3],
                      aaddr + 5120 * 2);
            }
            #pragma unroll
            for (int ntp = 0; ntp < 2; ntp++) {
                uint32_t baddr = base +
                    (10240 + boffE + ntp * 16 * SROW + ks * 16) * 2;
                uint32_t bh0, bh1, bh2, bh3, bl0, bl1, bl2, bl3;
                LDSM4(bh0, bh1, bh2, bh3, baddr);
                LDSM4(bl0, bl1, bl2, bl3, baddr + 5120 * 2);
                #pragma unroll
                for (int mt = 0; mt < 4; mt++) {
                    MMA16816(acc[mt][2 * ntp], ah[mt][0], ah[mt][1], ah[mt][2], ah[mt][3], bh0, bh1);
                    MMA16816(acc[mt][2 * ntp], ah[mt][0], ah[mt][1], ah[mt][2], ah[mt][3], bl0, bl1);
                    MMA16816(acc[mt][2 * ntp], al[mt][0], al[mt][1], al[mt][2], al[mt][3], bh0, bh1);
                    MMA16816(acc[mt][2 * ntp + 1], ah[mt][0], ah[mt][1], ah[mt][2], ah[mt][3], bh2, bh3);
                    MMA16816(acc[mt][2 * ntp + 1], ah[mt][0], ah[mt][1], ah[mt][2], ah[mt][3], bl2, bl3);
                    MMA16816(acc[mt][2 * ntp + 1], al[mt][0], al[mt][1], al[mt][2], al[mt][3], bh2, bh3);
                }
            }
        }
        __syncthreads();
        if (it + 2 < nst) {
            LOAD_STAGE((it + 2) % NSTAGE, (it + 2) * 32);
            CPA_COMMIT();
        }
    }

    #pragma unroll
    for (int mt = 0; mt < 4; mt++) {
        int row = bm + wm * 64 + mt * 16 + gid;
        #pragma unroll
        for (int nt = 0; nt < 4; nt++) {
            int col = cn + wn * 32 + nt * 8 + tig * 2;
            *(float2*)&C[(size_t)row * Dc + col] =
                make_float2(acc[mt][nt][0], acc[mt][nt][1]);
            *(float2*)&C[(size_t)(row + 8) * Dc + col] =
                make_float2(acc[mt][nt][2], acc[mt][nt][3]);
        }
    }
}

// ---------------------------------------------------------------------------
// Flash attention on tensor cores (bf16x3), ldmatrix, 2-stage K/V pipeline.
// BM=128, BN=64, 8 warps. Grid: (S/128, H, B).
// ---------------------------------------------------------------------------
#define FQS 136
#define FVS 72
#define FQ_ELEMS (2 * 128 * FQS)              // 34816 (Qh+Ql)
#define FKV_ELEMS (2 * 64 * FQS + 2 * 128 * FVS)  // 35840 per stage
#define FLASH_SMEM ((FQ_ELEMS + 2 * FKV_ELEMS) * 2)   // 212992 bytes

__global__ __launch_bounds__(256, 1) void flash_mma_kernel()
{
    extern __shared__ __align__(16) __nv_bfloat16 fsm[];
    __nv_bfloat16* sQh = fsm;
    __nv_bfloat16* sQl = sQh + 128 * FQS;
    const uint32_t uQh = smem_u32(sQh), uQl = smem_u32(sQl);
    // stage s base (elements): FQ_ELEMS + s*FKV_ELEMS
    // within stage: Kh @0, Kl @8704, Vh @17408, Vl @26624
    const uint32_t uS0 = uQh + FQ_ELEMS * 2;

    const int t = threadIdx.x, lane = t & 31, w = t >> 5;
    const int gid = lane >> 2, tig = lane & 3;
    const int qt = blockIdx.x, h = blockIdx.y, b = blockIdx.z;
    const int qbase = qt * 128;

    const int qaoffE = (w * 16 + (lane & 15)) * FQS + ((lane >> 4) & 1) * 8;
    const int kboffE = (((lane >> 4) & 1) * 8 + (lane & 7)) * FQS
                     + ((lane >> 3) & 1) * 8;
    const int vboffE = (((lane >> 4) & 1) * 8 + (lane & 7)) * FVS
                     + ((lane >> 3) & 1) * 8;

    #pragma unroll
    for (int i = 0; i < 8; i++) {
        int u = t + i * 256;
        int row = u >> 4, c8 = (u & 15) * 8;
        size_t g = ((size_t)(b * Sc + qbase + row)) * Dc + h * HDc + c8;
        *(uint4*)&sQh[row * FQS + c8] = *(const uint4*)&g_qh[g];
        *(uint4*)&sQl[row * FQS + c8] = *(const uint4*)&g_ql[g];
    }

    const int row0 = qbase + w * 16 + gid;
    const int row1 = row0 + 8;

    float m0 = -1e30f, m1 = -1e30f, l0 = 0.f, l1 = 0.f;
    float oacc[16][4];
    #pragma unroll
    for (int i = 0; i < 16; i++)
        #pragma unroll
        for (int j = 0; j < 4; j++) oacc[i][j] = 0.f;

    const int ntk = 2 * qt + 2;

    #define LOAD_KV(kt_) do {                                               \
        const uint32_t sb2 = uS0 + ((kt_) & 1) * FKV_ELEMS * 2;             \
        const int kb_ = (kt_) * 64;                                         \
        _Pragma("unroll")                                                   \
        for (int i = 0; i < 4; i++) {                                       \
            int u = t + i * 256;                                            \
            int krow = u >> 4, c8 = (u & 15) * 8;                           \
            size_t gk = ((size_t)(b * Sc + kb_ + krow)) * Dc + h * HDc + c8;\
            CPA16(sb2 + (krow * FQS + c8) * 2, &g_kh[gk]);                  \
            CPA16(sb2 + (8704 + krow * FQS + c8) * 2, &g_kl[gk]);           \
            int vrow = u >> 3, v8 = (u & 7) * 8;                            \
            size_t gv = ((size_t)((b * Hc + h) * HDc + vrow)) * Sc + kb_ + v8;\
            CPA16(sb2 + (17408 + vrow * FVS + v8) * 2, &g_vth[gv]);         \
            CPA16(sb2 + (26624 + vrow * FVS + v8) * 2, &g_vtl[gv]);         \
        }                                                                   \
        CPA_COMMIT();                                                       \
    } while (0)

    LOAD_KV(0);

    for (int kt = 0; kt < ntk; kt++) {
        const int kbase = kt * 64;
        if (kt + 1 < ntk) {
            LOAD_KV(kt + 1);
            CPA_WAIT(1);
        } else {
            CPA_WAIT(0);
        }
        __syncthreads();

        const uint32_t sb2 = uS0 + (kt & 1) * FKV_ELEMS * 2;
        const uint32_t uKh2 = sb2, uKl2 = sb2 + 8704 * 2;
        const uint32_t uVh2 = sb2 + 17408 * 2, uVl2 = sb2 + 26624 * 2;

        // ---- S = Q K^T ----
        float sacc[8][4];
        #pragma unroll
        for (int nt = 0; nt < 8; nt++)
            #pragma unroll
            for (int j = 0; j < 4; j++) sacc[nt][j] = 0.f;

        #pragma unroll
        for (int kc = 0; kc < 8; kc++) {
            uint32_t ah0, ah1, ah2, ah3, al0, al1, al2, al3;
            LDSM4(ah0, ah1, ah2, ah3, uQh + (qaoffE + kc * 16) * 2);
            LDSM4(al0, al1, al2, al3, uQl + (qaoffE + kc * 16) * 2);
            #pragma unroll
            for (int ntp = 0; ntp < 4; ntp++) {
                uint32_t kaddr = (kboffE + ntp * 16 * FQS + kc * 16) * 2;
                uint32_t bh0, bh1, bh2, bh3, bl0, bl1, bl2, bl3;
                LDSM4(bh0, bh1, bh2, bh3, uKh2 + kaddr);
                LDSM4(bl0, bl1, bl2, bl3, uKl2 + kaddr);
                MMA16816(sacc[2 * ntp], ah0, ah1, ah2, ah3, bh0, bh1);
                MMA16816(sacc[2 * ntp], ah0, ah1, ah2, ah3, bl0, bl1);
                MMA16816(sacc[2 * ntp], al0, al1, al2, al3, bh0, bh1);
                MMA16816(sacc[2 * ntp + 1], ah0, ah1, ah2, ah3, bh2, bh3);
                MMA16816(sacc[2 * ntp + 1], ah0, ah1, ah2, ah3, bl2, bl3);
                MMA16816(sacc[2 * ntp + 1], al0, al1, al2, al3, bh2, bh3);
            }
        }

        const bool need_mask = (kt >= 2 * qt);
        #pragma unroll
        for (int nt = 0; nt < 8; nt++) {
            int c0 = kbase + nt * 8 + 2 * tig;
            float v0 = sacc[nt][0] * SCALE;
            float v1 = sacc[nt][1] * SCALE;
            float v2 = sacc[nt][2] * SCALE;
            float v3 = sacc[nt][3] * SCALE;
            if (need_mask) {
                if (c0 > row0)     v0 -= 1e9f;
                if (c0 + 1 > row0) v1 -= 1e9f;
                if (c0 > row1)     v2 -= 1e9f;
                if (c0 + 1 > row1) v3 -= 1e9f;
            }
            sacc[nt][0] = v0; sacc[nt][1] = v1;
            sacc[nt][2] = v2; sacc[nt][3] = v3;
        }

        float mx0 = -1e30f, mx1 = -1e30f;
        #pragma unroll
        for (int nt = 0; nt < 8; nt++) {
            mx0 = fmaxf(mx0, fmaxf(sacc[nt][0], sacc[nt][1]));
            mx1 = fmaxf(mx1, fmaxf(sacc[nt][2], sacc[nt][3]));
        }
        mx0 = fmaxf(mx0, __shfl_xor_sync(0xffffffffu, mx0, 1));
        mx0 = fmaxf(mx0, __shfl_xor_sync(0xffffffffu, mx0, 2));
        mx1 = fmaxf(mx1, __shfl_xor_sync(0xffffffffu, mx1, 1));
        mx1 = fmaxf(mx1, __shfl_xor_sync(0xffffffffu, mx1, 2));
        float nm0 = fmaxf(m0, mx0), nm1 = fmaxf(m1, mx1);
        float corr0 = __expf(m0 - nm0), corr1 = __expf(m1 - nm1);
        m0 = nm0; m1 = nm1;

        float rs0 = 0.f, rs1 = 0.f;
        uint32_t ph01[8], ph23[8], pl01[8], pl23[8];
        #pragma unroll
        for (int nt = 0; nt < 8; nt++) {
            float e0 = __expf(sacc[nt][0] - nm0);
            float e1 = __expf(sacc[nt][1] - nm0);
            float e2 = __expf(sacc[nt][2] - nm1);
            float e3 = __expf(sacc[nt][3] - nm1);
            rs0 += e0 + e1; rs1 += e2 + e3;
            __nv_bfloat162 h01 = __floats2bfloat162_rn(e0, e1);
            __nv_bfloat162 h23 = __floats2bfloat162_rn(e2, e3);
            __nv_bfloat162 lo01 = __floats2bfloat162_rn(
                e0 - __bfloat162float(h01.x), e1 - __bfloat162float(h01.y));
            __nv_bfloat162 lo23 = __floats2bfloat162_rn(
                e2 - __bfloat162float(h23.x), e3 - __bfloat162float(h23.y));
            ph01[nt] = *(uint32_t*)&h01;
            ph23[nt] = *(uint32_t*)&h23;
            pl01[nt] = *(uint32_t*)&lo01;
            pl23[nt] = *(uint32_t*)&lo23;
        }
        rs0 += __shfl_xor_sync(0xffffffffu, rs0, 1);
        rs0 += __shfl_xor_sync(0xffffffffu, rs0, 2);
        rs1 += __shfl_xor_sync(0xffffffffu, rs1, 1);
        rs1 += __shfl_xor_sync(0xffffffffu, rs1, 2);
        l0 = l0 * corr0 + rs0;
        l1 = l1 * corr1 + rs1;

        #pragma unroll
        for (int nto = 0; nto < 16; nto++) {
            oacc[nto][0] *= corr0; oacc[nto][1] *= corr0;
            oacc[nto][2] *= corr1; oacc[nto][3] *= corr1;
        }

        // ---- O += P V ----
        #pragma unroll
        for (int j = 0; j < 4; j++) {
            uint32_t a0h = ph01[2 * j],     a1h = ph23[2 * j];
            uint32_t a2h = ph01[2 * j + 1], a3h = ph23[2 * j + 1];
            uint32_t a0l = pl01[2 * j],     a1l = pl23[2 * j];
            uint32_t a2l = pl01[2 * j + 1], a3l = pl23[2 * j + 1];
            #pragma unroll
            for (int ntp = 0; ntp < 8; ntp++) {
                uint32_t vaddr = (vboffE + ntp * 16 * FVS + j * 16) * 2;
                uint32_t vh0, vh1, vh2, vh3, vl0, vl1, vl2, vl3;
                LDSM4(vh0, vh1, vh2, vh3, uVh2 + vaddr);
                LDSM4(vl0, vl1, vl2, vl3, uVl2 + vaddr);
                MMA16816(oacc[2 * ntp], a0h, a1h, a2h, a3h, vh0, vh1);
                MMA16816(oacc[2 * ntp], a0h, a1h, a2h, a3h, vl0, vl1);
                MMA16816(oacc[2 * ntp], a0l, a1l, a2l, a3l, vh0, vh1);
                MMA16816(oacc[2 * ntp + 1], a0h, a1h, a2h, a3h, vh2, vh3);
                MMA16816(oacc[2 * ntp + 1], a0h, a1h, a2h, a3h, vl2, vl3);
                MMA16816(oacc[2 * ntp + 1], a0l, a1l, a2l, a3l, vh2, vh3);
            }
        }
        __syncthreads();
    }

    float i0 = 1.f / l0, i1 = 1.f / l1;
    #pragma unroll
    for (int nto = 0; nto < 16; nto++) {
        int col = h * HDc + nto * 8 + 2 * tig;
        *(float2*)&g_attn[((size_t)(b * Sc + row0)) * Dc + col] =
            make_float2(oacc[nto][0] * i0, oacc[nto][1] * i0);
        *(float2*)&g_attn[((size_t)(b * Sc + row1)) * Dc + col] =
            make_float2(oacc[nto][2] * i1, oacc[nto][3] * i1);
    }
}

// ---------------------------------------------------------------------------
// Adapter projection, deterministic 2-pass k-split
// ---------------------------------------------------------------------------
__global__ __launch_bounds__(256) void adapter_proj_kernel(
    const float* __restrict__ A, const float* __restrict__ W,
    float* __restrict__ P)
{
    const int ks = blockIdx.x;
    const int l  = blockIdx.y;
    const int t  = threadIdx.x;
    float acc[8];
    #pragma unroll
    for (int i = 0; i < 8; i++) acc[i] = 0.f;
    for (int k = ks * 128; k < ks * 128 + 128; k++) {
        float a = A[l * Dc + k];
        const float* wr = &W[(size_t)k * Dc + t * 8];
        float4 w0 = *(const float4*)wr;
        float4 w1 = *(const float4*)(wr + 4);
        acc[0] += a * w0.x; acc[1] += a * w0.y;
        acc[2] += a * w0.z; acc[3] += a * w0.w;
        acc[4] += a * w1.x; acc[5] += a * w1.y;
        acc[6] += a * w1.z; acc[7] += a * w1.w;
    }
    float* o = &P[((size_t)l * 16 + ks) * Dc + t * 8];
    *(float4*)o       = make_float4(acc[0], acc[1], acc[2], acc[3]);
    *(float4*)(o + 4) = make_float4(acc[4], acc[5], acc[6], acc[7]);
}

__global__ __launch_bounds__(256) void adapter_reduce_kernel(
    const float* __restrict__ P, float* __restrict__ C)
{
    int idx = blockIdx.x * 256 + threadIdx.x;
    int l = idx >> 11, n = idx & 2047;
    float s = 0.f;
    #pragma unroll
    for (int ks = 0; ks < 16; ks++)
        s += P[((size_t)l * 16 + ks) * Dc + n];
    C[idx] = s;
}

// ---------------------------------------------------------------------------
// Adapter attention: one warp per (b,s,h). out += gate[h] * softmax(q·akᵀ) av
// ---------------------------------------------------------------------------
__global__ __launch_bounds__(256) void adapter_attn_kernel(
    const float* __restrict__ gate)
{
    int gw = (blockIdx.x * blockDim.x + threadIdx.x) >> 5;
    int lane = threadIdx.x & 31;
    if (gw >= Bc * Sc * Hc) return;
    int h = gw % Hc;
    int s = (gw / Hc) % Sc;
    int b = gw / (Hc * Sc);

    size_t qoff = ((size_t)(b * Sc + s)) * Dc + h * HDc + lane * 4;
    float4 q4 = *(const float4*)(g_q + qoff);

    float scv[Lc];
    #pragma unroll
    for (int l = 0; l < Lc; l++) {
        float4 a4 = *(const float4*)(g_ak + (size_t)l * Dc + h * HDc + lane * 4);
        float p = q4.x * a4.x + q4.y * a4.y + q4.z * a4.z + q4.w * a4.w;
        #pragma unroll
        for (int o = 16; o > 0; o >>= 1)
            p += __shfl_xor_sync(0xffffffffu, p, o);
        scv[l] = p * SCALE;
    }
    float m = scv[0];
    #pragma unroll
    for (int l = 1; l < Lc; l++) m = fmaxf(m, scv[l]);
    float sum = 0.f;
    float e[Lc];
    #pragma unroll
    for (int l = 0; l < Lc; l++) { e[l] = expf(scv[l] - m); sum += e[l]; }
    float g = gate[h] / sum;

    float4 acc = make_float4(0.f, 0.f, 0.f, 0.f);
    #pragma unroll
    for (int l = 0; l < Lc; l++) {
        float4 a4 = *(const float4*)(g_av + (size_t)l * Dc + h * HDc + lane * 4);
        acc.x += e[l] * a4.x;
        acc.y += e[l] * a4.y;
        acc.z += e[l] * a4.z;
        acc.w += e[l] * a4.w;
    }
    float4 cur = *(float4*)(g_attn + qoff);
    cur.x += g * acc.x;
    cur.y += g * acc.y;
    cur.z += g * acc.z;
    cur.w += g * acc.w;
    *(float4*)(g_attn + qoff) = cur;
}

// ---------------------------------------------------------------------------
extern "C" void kernel_launch(void* const* d_in, const int* in_sizes, int n_in,
                              void* d_out, int out_size)
{
    const float* x       = (const float*)d_in[0];
    const float* wq      = (const float*)d_in[1];
    const float* wk      = (const float*)d_in[2];
    const float* wv      = (const float*)d_in[3];
    const float* wo      = (const float*)d_in[4];
    const float* adapter = (const float*)d_in[5];
    const float* gate    = (const float*)d_in[6];
    const float* fcos    = (const float*)d_in[7];
    const float* fsin    = (const float*)d_in[8];
    float* out = (float*)d_out;

    float *q, *k, *v, *attn, *ak, *av, *part;
    __nv_bfloat16 *xh, *xl, *wth, *wtl, *qh, *ql, *kh, *kl, *vth, *vtl;
    cudaGetSymbolAddress((void**)&q,    g_q);
    cudaGetSymbolAddress((void**)&k,    g_k);
    cudaGetSymbolAddress((void**)&v,    g_v);
    cudaGetSymbolAddress((void**)&attn, g_attn);
    cudaGetSymbolAddress((void**)&ak,   g_ak);
    cudaGetSymbolAddress((void**)&av,   g_av);
    cudaGetSymbolAddress((void**)&part, g_partial);
    cudaGetSymbolAddress((void**)&xh,   g_xh);
    cudaGetSymbolAddress((void**)&xl,   g_xl);
    cudaGetSymbolAddress((void**)&wth,  g_wth);
    cudaGetSymbolAddress((void**)&wtl,  g_wtl);
    cudaGetSymbolAddress((void**)&qh,   g_qh);
    cudaGetSymbolAddress((void**)&ql,   g_ql);
    cudaGetSymbolAddress((void**)&kh,   g_kh);
    cudaGetSymbolAddress((void**)&kl,   g_kl);
    cudaGetSymbolAddress((void**)&vth,  g_vth);
    cudaGetSymbolAddress((void**)&vtl,  g_vtl);

    const int M = Bc * Sc;   // 4096

    cudaFuncSetAttribute(mma_gemm_kernel,
                         cudaFuncAttributeMaxDynamicSharedMemorySize,
                         GEMM_SMEM);
    cudaFuncSetAttribute(flash_mma_kernel,
                         cudaFuncAttributeMaxDynamicSharedMemorySize,
                         FLASH_SMEM);

    // split x -> bf16 hi/lo
    split_kernel<<<(M * Dc / 4) / 256, 256>>>(x, xh, xl);

    // stacked W^T for fused QKV projection (one launch)
    wtrans3_kernel<<<dim3(Dc / 32, Dc / 32, 3), 256>>>(wq, wk, wv, wth, wtl);

    // fused QKV GEMM: N = 6144, CTA-routed outputs
    mma_gemm_kernel<<<dim3(3 * Dc / 128, M / 128), 256, GEMM_SMEM>>>(
        xh, xl, wth, wtl, q, k, v, M, 3 * Dc, Dc);

    // fused RoPE + split (q keeps fp32 for adapter path; k does not)
    int npairs = Bc * Sc * Hc * (HDc / 2);
    rope_split_kernel<<<npairs / 256, 256>>>(q, fcos, fsin, qh, ql, 1);
    rope_split_kernel<<<npairs / 256, 256>>>(k, fcos, fsin, kh, kl, 0);
    vtrans_kernel<<<dim3(Sc / 32, HDc / 32, Bc * Hc), 256>>>(v, vth, vtl);

    adapter_proj_kernel<<<dim3(16, Lc), 256>>>(adapter, wk, part);
    adapter_reduce_kernel<<<(Lc * Dc) / 256, 256>>>(part, ak);
    adapter_proj_kernel<<<dim3(16, Lc), 256>>>(adapter, wv, part);
    adapter_reduce_kernel<<<(Lc * Dc) / 256, 256>>>(part, av);

    flash_mma_kernel<<<dim3(Sc / 128, Hc, Bc), 256, FLASH_SMEM>>>();

    adapter_attn_kernel<<<(Bc * Sc * Hc * 32) / 256, 256>>>(gate);

    // Output projection
    split_kernel<<<(M * Dc / 4) / 256, 256>>>(attn, xh, xl);
    wtrans3_kernel<<<dim3(Dc / 32, Dc / 32, 1), 256>>>(wo, wo, wo, wth, wtl);
    mma_gemm_kernel<<<dim3(Dc / 128, M / 128), 256, GEMM_SMEM>>>(
        xh, xl, wth, wtl, out, out, out, M, Dc, Dc);
}

// round 8
// speedup vs baseline: 5.3366x; 1.1083x over previous
#include <cuda_runtime.h>
#include <cuda_bf16.h>
#include <math.h>
#include <stdint.h>

#define Bc 2
#define Sc 2048
#define Dc 2048
#define Hc 16
#define HDc 128
#define Lc 10

// Scratch (static device globals — allocation-free per harness rules)
__device__ float g_v[Bc*Sc*Dc];
__device__ float g_attn[Bc*Sc*Dc];
__device__ float g_ak[Lc*Dc];
__device__ float g_av[Lc*Dc];
__device__ float g_partial[Lc*16*Dc];
// bf16 split scratch
__device__ __nv_bfloat16 g_xh[Bc*Sc*Dc];   // x split; later attn split
__device__ __nv_bfloat16 g_xl[Bc*Sc*Dc];
__device__ __nv_bfloat16 g_wth[3*Dc*Dc];   // stacked W^T hi [3*D rows][K]
__device__ __nv_bfloat16 g_wtl[3*Dc*Dc];   // stacked W^T lo
__device__ __nv_bfloat16 g_qh[Bc*Sc*Dc];
__device__ __nv_bfloat16 g_ql[Bc*Sc*Dc];
__device__ __nv_bfloat16 g_kh[Bc*Sc*Dc];
__device__ __nv_bfloat16 g_kl[Bc*Sc*Dc];
__device__ __nv_bfloat16 g_vth[Bc*Sc*Dc];  // [B,H,HD,S]
__device__ __nv_bfloat16 g_vtl[Bc*Sc*Dc];  // [B,H,HD,S]

#define SCALE 0.08838834764831845f  // 1/sqrt(128)

// ---------------------------------------------------------------------------
// mma.sync + ldmatrix + cp.async helpers
// ---------------------------------------------------------------------------
#define MMA16816(c, a0, a1, a2, a3, b0, b1) \
    asm volatile( \
        "mma.sync.aligned.m16n8k16.row.col.f32.bf16.bf16.f32 " \
        "{%0,%1,%2,%3}, {%4,%5,%6,%7}, {%8,%9}, {%0,%1,%2,%3};" \
        : "+f"((c)[0]), "+f"((c)[1]), "+f"((c)[2]), "+f"((c)[3]) \
        : "r"(a0), "r"(a1), "r"(a2), "r"(a3), "r"(b0), "r"(b1))

#define LDSM4(r0, r1, r2, r3, addr) \
    asm volatile("ldmatrix.sync.aligned.m8n8.x4.shared.b16 {%0,%1,%2,%3}, [%4];" \
                 : "=r"(r0), "=r"(r1), "=r"(r2), "=r"(r3) : "r"(addr))

__device__ __forceinline__ uint32_t smem_u32(const void* p) {
    uint32_t a;
    asm("{ .reg .u64 t; cvta.to.shared.u64 t, %1; cvt.u32.u64 %0, t; }"
        : "=r"(a) : "l"(p));
    return a;
}
#define CPA16(saddr, gptr) \
    asm volatile("cp.async.cg.shared.global [%0], [%1], 16;" \
                 :: "r"(saddr), "l"(gptr))
#define CPA_COMMIT() asm volatile("cp.async.commit_group;")
#define CPA_WAIT(n)  asm volatile("cp.async.wait_group %0;" :: "n"(n))

__device__ __forceinline__ __nv_bfloat162 bsplit_hi(float a, float b) {
    __nv_bfloat162 r;
    r.x = __float2bfloat16(a);
    r.y = __float2bfloat16(b);
    return r;
}
__device__ __forceinline__ __nv_bfloat162 bsplit_lo(float a, float b,
                                                    __nv_bfloat162 h) {
    __nv_bfloat162 r;
    r.x = __float2bfloat16(a - __bfloat162float(h.x));
    r.y = __float2bfloat16(b - __bfloat162float(h.y));
    return r;
}

// ---------------------------------------------------------------------------
// Elementwise fp32 -> bf16 hi/lo split (x only)
// ---------------------------------------------------------------------------
__global__ __launch_bounds__(256) void split_kernel(
    const float* __restrict__ x, __nv_bfloat16* __restrict__ h,
    __nv_bfloat16* __restrict__ l)
{
    int i = blockIdx.x * 256 + threadIdx.x;
    float4 v = ((const float4*)x)[i];
    __nv_bfloat162 h01 = bsplit_hi(v.x, v.y);
    __nv_bfloat162 h23 = bsplit_hi(v.z, v.w);
    ((__nv_bfloat162*)h)[i * 2 + 0] = h01;
    ((__nv_bfloat162*)h)[i * 2 + 1] = h23;
    ((__nv_bfloat162*)l)[i * 2 + 0] = bsplit_lo(v.x, v.y, h01);
    ((__nv_bfloat162*)l)[i * 2 + 1] = bsplit_lo(v.z, v.w, h23);
}

// ---------------------------------------------------------------------------
// Transpose + split, up to 3 weights in one launch (blockIdx.z selects)
// ---------------------------------------------------------------------------
__global__ __launch_bounds__(256) void wtrans3_kernel(
    const float* __restrict__ W0, const float* __restrict__ W1,
    const float* __restrict__ W2, __nv_bfloat16* __restrict__ Th,
    __nv_bfloat16* __restrict__ Tl)
{
    __shared__ float tile[32][33];
    const int z = blockIdx.z;
    const float* W = (z == 0) ? W0 : (z == 1) ? W1 : W2;
    __nv_bfloat16* Tho = Th + (size_t)z * Dc * Dc;
    __nv_bfloat16* Tlo = Tl + (size_t)z * Dc * Dc;
    const int k0 = blockIdx.x * 32, n0 = blockIdx.y * 32;
    const int t = threadIdx.x;
    const int r = t >> 5, c = t & 31;
    #pragma unroll
    for (int i = 0; i < 4; i++)
        tile[r + i * 8][c] = W[(size_t)(k0 + r + i * 8) * Dc + n0 + c];
    __syncthreads();
    #pragma unroll
    for (int i = 0; i < 4; i++) {
        int n = r + i * 8;
        float v = tile[c][n];
        __nv_bfloat16 h = __float2bfloat16(v);
        Tho[(size_t)(n0 + n) * Dc + k0 + c] = h;
        Tlo[(size_t)(n0 + n) * Dc + k0 + c] =
            __float2bfloat16(v - __bfloat162float(h));
    }
}

// ---------------------------------------------------------------------------
// V transpose+split: v f32 [B,S,H,HD] -> vth/vtl bf16 [B,H,HD,S]
// ---------------------------------------------------------------------------
__global__ __launch_bounds__(256) void vtrans_kernel(
    const float* __restrict__ v, __nv_bfloat16* __restrict__ Th,
    __nv_bfloat16* __restrict__ Tl)
{
    __shared__ float tile[32][33];
    const int s0 = blockIdx.x * 32, d0 = blockIdx.y * 32;
    const int bh = blockIdx.z;
    const int b = bh >> 4, h = bh & 15;
    const int t = threadIdx.x;
    const int r = t >> 5, c = t & 31;
    #pragma unroll
    for (int i = 0; i < 4; i++) {
        int sl = r + i * 8;
        tile[sl][c] = v[((size_t)(b * Sc + s0 + sl)) * Dc + h * HDc + d0 + c];
    }
    __syncthreads();
    #pragma unroll
    for (int i = 0; i < 4; i++) {
        int dl = r + i * 8;
        float val = tile[c][dl];
        __nv_bfloat16 hb = __float2bfloat16(val);
        size_t o = ((size_t)(bh * HDc + d0 + dl)) * Sc + s0 + c;
        Th[o] = hb;
        Tl[o] = __float2bfloat16(val - __bfloat162float(hb));
    }
}

// ---------------------------------------------------------------------------
// bf16x3 tensor-core GEMM, BK=64, 2-stage cp.async + ldmatrix.
// mode 0 (QKV): N=6144; seg 0/1 -> RoPE + bf16 split to qh/ql | kh/kl;
//               seg 2 -> fp32 V.
// mode 1 (WO):  N=2048; plain fp32 to oC.
// ---------------------------------------------------------------------------
#define SROW2 72
#define STG2 36864                         // elems per stage (4 * 128 * 72)
#define GEMM_SMEM (2 * STG2 * 2)           // 147456 bytes

__global__ __launch_bounds__(256, 1) void mma_gemm_kernel(
    const __nv_bfloat16* __restrict__ Ah, const __nv_bfloat16* __restrict__ Al,
    const __nv_bfloat16* __restrict__ BhT, const __nv_bfloat16* __restrict__ BlT,
    const float* __restrict__ fc, const float* __restrict__ fs,
    __nv_bfloat16* __restrict__ oQh, __nv_bfloat16* __restrict__ oQl,
    __nv_bfloat16* __restrict__ oKh, __nv_bfloat16* __restrict__ oKl,
    float* __restrict__ oV, float* __restrict__ oC,
    int mode, int K)
{
    extern __shared__ __align__(16) __nv_bfloat16 dsm[];
    const uint32_t sb = smem_u32(dsm);

    const int t = threadIdx.x, lane = t & 31, wid = t >> 5;
    const int wm = wid & 1, wn = wid >> 1;
    const int bm = blockIdx.y * 128, bn = blockIdx.x * 128;
    const int gid = lane >> 2, tig = lane & 3;

    const int aoffE = (wm * 64 + (lane & 15)) * SROW2 + ((lane >> 4) & 1) * 8;
    const int boffE = (wn * 32 + ((lane >> 4) & 1) * 8 + (lane & 7)) * SROW2
                    + ((lane >> 3) & 1) * 8;

    float acc[4][4][4];
    #pragma unroll
    for (int a = 0; a < 4; a++)
        #pragma unroll
        for (int b = 0; b < 4; b++)
            #pragma unroll
            for (int cc = 0; cc < 4; cc++) acc[a][b][cc] = 0.f;

    const int nst = K >> 6;

    #define LOAD_STAGE2(stg, k0) do {                                       \
        uint32_t base = sb + (stg) * STG2 * 2;                              \
        _Pragma("unroll")                                                   \
        for (int jj = 0; jj < 4; jj++) {                                    \
            int u = t + jj * 256;                                           \
            int row = u >> 3, ch = (u & 7) * 8;                             \
            size_t ga = (size_t)(bm + row) * K + (k0) + ch;                 \
            size_t gb = (size_t)(bn + row) * K + (k0) + ch;                 \
            CPA16(base + (row * SROW2 + ch) * 2, &Ah[ga]);                  \
            CPA16(base + (9216 + row * SROW2 + ch) * 2, &Al[ga]);           \
            CPA16(base + (18432 + row * SROW2 + ch) * 2, &BhT[gb]);         \
            CPA16(base + (27648 + row * SROW2 + ch) * 2, &BlT[gb]);         \
        }                                                                   \
        CPA_COMMIT();                                                       \
    } while (0)

    LOAD_STAGE2(0, 0);
    LOAD_STAGE2(1, 64);

    for (int it = 0; it < nst; it++) {
        if (it == nst - 1) { CPA_WAIT(0); } else { CPA_WAIT(1); }
        __syncthreads();

        const uint32_t base = sb + (it & 1) * STG2 * 2;

        #pragma unroll
        for (int ks = 0; ks < 4; ks++) {
            uint32_t ah[4][4], al[4][4];
            #pragma unroll
            for (int mt = 0; mt < 4; mt++) {
                uint32_t aaddr = base + (aoffE + mt * 16 * SROW2 + ks * 16) * 2;
                LDSM4(ah[mt][0], ah[mt][1], ah[mt][2], ah[mt][3], aaddr);
                LDSM4(al[mt][0], al[mt][1], al[mt][2], al[mt][3],
                      aaddr + 9216 * 2);
            }
            #pragma unroll
            for (int ntp = 0; ntp < 2; ntp++) {
                uint32_t baddr = base +
                    (18432 + boffE + ntp * 16 * SROW2 + ks * 16) * 2;
                uint32_t bh0, bh1, bh2, bh3, bl0, bl1, bl2, bl3;
                LDSM4(bh0, bh1, bh2, bh3, baddr);
                LDSM4(bl0, bl1, bl2, bl3, baddr + 9216 * 2);
                #pragma unroll
                for (int mt = 0; mt < 4; mt++) {
                    MMA16816(acc[mt][2 * ntp], ah[mt][0], ah[mt][1], ah[mt][2], ah[mt][3], bh0, bh1);
                    MMA16816(acc[mt][2 * ntp], ah[mt][0], ah[mt][1], ah[mt][2], ah[mt][3], bl0, bl1);
                    MMA16816(acc[mt][2 * ntp], al[mt][0], al[mt][1], al[mt][2], al[mt][3], bh0, bh1);
                    MMA16816(acc[mt][2 * ntp + 1], ah[mt][0], ah[mt][1], ah[mt][2], ah[mt][3], bh2, bh3);
                    MMA16816(acc[mt][2 * ntp + 1], ah[mt][0], ah[mt][1], ah[mt][2], ah[mt][3], bl2, bl3);
                    MMA16816(acc[mt][2 * ntp + 1], al[mt][0], al[mt][1], al[mt][2], al[mt][3], bh2, bh3);
                }
            }
        }
        __syncthreads();
        if (it + 2 < nst) {
            LOAD_STAGE2((it + 2) & 1, (it + 2) * 64);
        }
    }

    // ---- epilogue ----
    #pragma unroll
    for (int mt = 0; mt < 4; mt++) {
        int row = bm + wm * 64 + mt * 16 + gid;
        #pragma unroll
        for (int nt = 0; nt < 4; nt++) {
            int colg = bn + wn * 32 + nt * 8 + tig * 2;
            float a0 = acc[mt][nt][0], a1 = acc[mt][nt][1];
            float a2 = acc[mt][nt][2], a3 = acc[mt][nt][3];
            if (mode == 1) {
                *(float2*)&oC[(size_t)row * Dc + colg] = make_float2(a0, a1);
                *(float2*)&oC[(size_t)(row + 8) * Dc + colg] = make_float2(a2, a3);
            } else {
                int seg = colg >> 11;
                int d = colg & 2047;
                if (seg == 2) {
                    *(float2*)&oV[(size_t)row * Dc + d] = make_float2(a0, a1);
                    *(float2*)&oV[(size_t)(row + 8) * Dc + d] = make_float2(a2, a3);
                } else {
                    int s0 = row & 2047, s1 = (row + 8) & 2047;
                    int j = (d & 127) >> 1;
                    float c0 = fc[s0 * 64 + j], n0 = fs[s0 * 64 + j];
                    float c1 = fc[s1 * 64 + j], n1 = fs[s1 * 64 + j];
                    float r00 = a0 * c0 - a1 * n0, r01 = a0 * n0 + a1 * c0;
                    float r10 = a2 * c1 - a3 * n1, r11 = a2 * n1 + a3 * c1;
                    __nv_bfloat16* dH = (seg == 0) ? oQh : oKh;
                    __nv_bfloat16* dL = (seg == 0) ? oQl : oKl;
                    size_t o0 = ((size_t)row * Dc + d) >> 1;
                    size_t o1 = ((size_t)(row + 8) * Dc + d) >> 1;
                    __nv_bfloat162 h0 = bsplit_hi(r00, r01);
                    __nv_bfloat162 h1 = bsplit_hi(r10, r11);
                    ((__nv_bfloat162*)dH)[o0] = h0;
                    ((__nv_bfloat162*)dH)[o1] = h1;
                    ((__nv_bfloat162*)dL)[o0] = bsplit_lo(r00, r01, h0);
                    ((__nv_bfloat162*)dL)[o1] = bsplit_lo(r10, r11, h1);
                }
            }
        }
    }
}

// ---------------------------------------------------------------------------
// Flash attention (bf16x3), ldmatrix, 2-stage K/V pipeline.
// Epilogue: adds pre-computed adapter contribution (g_attn) and writes the
// bf16 hi/lo split of the result directly to g_xh/g_xl for the WO GEMM.
// ---------------------------------------------------------------------------
#define FQS 136
#define FVS 72
#define FQ_ELEMS (2 * 128 * FQS)
#define FKV_ELEMS (2 * 64 * FQS + 2 * 128 * FVS)
#define FLASH_SMEM ((FQ_ELEMS + 2 * FKV_ELEMS) * 2)

__global__ __launch_bounds__(256, 1) void flash_mma_kernel()
{
    extern __shared__ __align__(16) __nv_bfloat16 fsm[];
    __nv_bfloat16* sQh = fsm;
    __nv_bfloat16* sQl = sQh + 128 * FQS;
    const uint32_t uQh = smem_u32(sQh), uQl = smem_u32(sQl);
    const uint32_t uS0 = uQh + FQ_ELEMS * 2;

    const int t = threadIdx.x, lane = t & 31, w = t >> 5;
    const int gid = lane >> 2, tig = lane & 3;
    const int qt = gridDim.x - 1 - blockIdx.x;   // longest first
    const int h = blockIdx.y, b = blockIdx.z;
    const int qbase = qt * 128;

    const int qaoffE = (w * 16 + (lane & 15)) * FQS + ((lane >> 4) & 1) * 8;
    const int kboffE = (((lane >> 4) & 1) * 8 + (lane & 7)) * FQS
                     + ((lane >> 3) & 1) * 8;
    const int vboffE = (((lane >> 4) & 1) * 8 + (lane & 7)) * FVS
                     + ((lane >> 3) & 1) * 8;

    #pragma unroll
    for (int i = 0; i < 8; i++) {
        int u = t + i * 256;
        int row = u >> 4, c8 = (u & 15) * 8;
        size_t g = ((size_t)(b * Sc + qbase + row)) * Dc + h * HDc + c8;
        *(uint4*)&sQh[row * FQS + c8] = *(const uint4*)&g_qh[g];
        *(uint4*)&sQl[row * FQS + c8] = *(const uint4*)&g_ql[g];
    }

    const int row0 = qbase + w * 16 + gid;
    const int row1 = row0 + 8;

    float m0 = -1e30f, m1 = -1e30f, l0 = 0.f, l1 = 0.f;
    float oacc[16][4];
    #pragma unroll
    for (int i = 0; i < 16; i++)
        #pragma unroll
        for (int j = 0; j < 4; j++) oacc[i][j] = 0.f;

    const int ntk = 2 * qt + 2;

    #define LOAD_KV(kt_) do {                                               \
        const uint32_t sb2 = uS0 + ((kt_) & 1) * FKV_ELEMS * 2;             \
        const int kb_ = (kt_) * 64;                                         \
        _Pragma("unroll")                                                   \
        for (int i = 0; i < 4; i++) {                                       \
            int u = t + i * 256;                                            \
            int krow = u >> 4, c8 = (u & 15) * 8;                           \
            size_t gk = ((size_t)(b * Sc + kb_ + krow)) * Dc + h * HDc + c8;\
            CPA16(sb2 + (krow * FQS + c8) * 2, &g_kh[gk]);                  \
            CPA16(sb2 + (8704 + krow * FQS + c8) * 2, &g_kl[gk]);           \
            int vrow = u >> 3, v8 = (u & 7) * 8;                            \
            size_t gv = ((size_t)((b * Hc + h) * HDc + vrow)) * Sc + kb_ + v8;\
            CPA16(sb2 + (17408 + vrow * FVS + v8) * 2, &g_vth[gv]);         \
            CPA16(sb2 + (26624 + vrow * FVS + v8) * 2, &g_vtl[gv]);         \
        }                                                                   \
        CPA_COMMIT();                                                       \
    } while (0)

    LOAD_KV(0);

    for (int kt = 0; kt < ntk; kt++) {
        const int kbase = kt * 64;
        if (kt + 1 < ntk) {
            LOAD_KV(kt + 1);
            CPA_WAIT(1);
        } else {
            CPA_WAIT(0);
        }
        __syncthreads();

        const uint32_t sb2 = uS0 + (kt & 1) * FKV_ELEMS * 2;
        const uint32_t uKh2 = sb2, uKl2 = sb2 + 8704 * 2;
        const uint32_t uVh2 = sb2 + 17408 * 2, uVl2 = sb2 + 26624 * 2;

        float sacc[8][4];
        #pragma unroll
        for (int nt = 0; nt < 8; nt++)
            #pragma unroll
            for (int j = 0; j < 4; j++) sacc[nt][j] = 0.f;

        #pragma unroll
        for (int kc = 0; kc < 8; kc++) {
            uint32_t ah0, ah1, ah2, ah3, al0, al1, al2, al3;
            LDSM4(ah0, ah1, ah2, ah3, uQh + (qaoffE + kc * 16) * 2);
            LDSM4(al0, al1, al2, al3, uQl + (qaoffE + kc * 16) * 2);
            #pragma unroll
            for (int ntp = 0; ntp < 4; ntp++) {
                uint32_t kaddr = (kboffE + ntp * 16 * FQS + kc * 16) * 2;
                uint32_t bh0, bh1, bh2, bh3, bl0, bl1, bl2, bl3;
                LDSM4(bh0, bh1, bh2, bh3, uKh2 + kaddr);
                LDSM4(bl0, bl1, bl2, bl3, uKl2 + kaddr);
                MMA16816(sacc[2 * ntp], ah0, ah1, ah2, ah3, bh0, bh1);
                MMA16816(sacc[2 * ntp], ah0, ah1, ah2, ah3, bl0, bl1);
                MMA16816(sacc[2 * ntp], al0, al1, al2, al3, bh0, bh1);
                MMA16816(sacc[2 * ntp + 1], ah0, ah1, ah2, ah3, bh2, bh3);
                MMA16816(sacc[2 * ntp + 1], ah0, ah1, ah2, ah3, bl2, bl3);
                MMA16816(sacc[2 * ntp + 1], al0, al1, al2, al3, bh2, bh3);
            }
        }

        const bool need_mask = (kt >= 2 * qt);
        #pragma unroll
        for (int nt = 0; nt < 8; nt++) {
            int c0 = kbase + nt * 8 + 2 * tig;
            float v0 = sacc[nt][0] * SCALE;
            float v1 = sacc[nt][1] * SCALE;
            float v2 = sacc[nt][2] * SCALE;
            float v3 = sacc[nt][3] * SCALE;
            if (need_mask) {
                if (c0 > row0)     v0 -= 1e9f;
                if (c0 + 1 > row0) v1 -= 1e9f;
                if (c0 > row1)     v2 -= 1e9f;
                if (c0 + 1 > row1) v3 -= 1e9f;
            }
            sacc[nt][0] = v0; sacc[nt][1] = v1;
            sacc[nt][2] = v2; sacc[nt][3] = v3;
        }

        float mx0 = -1e30f, mx1 = -1e30f;
        #pragma unroll
        for (int nt = 0; nt < 8; nt++) {
            mx0 = fmaxf(mx0, fmaxf(sacc[nt][0], sacc[nt][1]));
            mx1 = fmaxf(mx1, fmaxf(sacc[nt][2], sacc[nt][3]));
        }
        mx0 = fmaxf(mx0, __shfl_xor_sync(0xffffffffu, mx0, 1));
        mx0 = fmaxf(mx0, __shfl_xor_sync(0xffffffffu, mx0, 2));
        mx1 = fmaxf(mx1, __shfl_xor_sync(0xffffffffu, mx1, 1));
        mx1 = fmaxf(mx1, __shfl_xor_sync(0xffffffffu, mx1, 2));
        float nm0 = fmaxf(m0, mx0), nm1 = fmaxf(m1, mx1);
        float corr0 = __expf(m0 - nm0), corr1 = __expf(m1 - nm1);
        m0 = nm0; m1 = nm1;

        float rs0 = 0.f, rs1 = 0.f;
        uint32_t ph01[8], ph23[8], pl01[8], pl23[8];
        #pragma unroll
        for (int nt = 0; nt < 8; nt++) {
            float e0 = __expf(sacc[nt][0] - nm0);
            float e1 = __expf(sacc[nt][1] - nm0);
            float e2 = __expf(sacc[nt][2] - nm1);
            float e3 = __expf(sacc[nt][3] - nm1);
            rs0 += e0 + e1; rs1 += e2 + e3;
            __nv_bfloat162 h01 = __floats2bfloat162_rn(e0, e1);
            __nv_bfloat162 h23 = __floats2bfloat162_rn(e2, e3);
            __nv_bfloat162 lo01 = __floats2bfloat162_rn(
                e0 - __bfloat162float(h01.x), e1 - __bfloat162float(h01.y));
            __nv_bfloat162 lo23 = __floats2bfloat162_rn(
                e2 - __bfloat162float(h23.x), e3 - __bfloat162float(h23.y));
            ph01[nt] = *(uint32_t*)&h01;
            ph23[nt] = *(uint32_t*)&h23;
            pl01[nt] = *(uint32_t*)&lo01;
            pl23[nt] = *(uint32_t*)&lo23;
        }
        rs0 += __shfl_xor_sync(0xffffffffu, rs0, 1);
        rs0 += __shfl_xor_sync(0xffffffffu, rs0, 2);
        rs1 += __shfl_xor_sync(0xffffffffu, rs1, 1);
        rs1 += __shfl_xor_sync(0xffffffffu, rs1, 2);
        l0 = l0 * corr0 + rs0;
        l1 = l1 * corr1 + rs1;

        #pragma unroll
        for (int nto = 0; nto < 16; nto++) {
            oacc[nto][0] *= corr0; oacc[nto][1] *= corr0;
            oacc[nto][2] *= corr1; oacc[nto][3] *= corr1;
        }

        #pragma unroll
        for (int j = 0; j < 4; j++) {
            uint32_t a0h = ph01[2 * j],     a1h = ph23[2 * j];
            uint32_t a2h = ph01[2 * j + 1], a3h = ph23[2 * j + 1];
            uint32_t a0l = pl01[2 * j],     a1l = pl23[2 * j];
            uint32_t a2l = pl01[2 * j + 1], a3l = pl23[2 * j + 1];
            #pragma unroll
            for (int ntp = 0; ntp < 8; ntp++) {
                uint32_t vaddr = (vboffE + ntp * 16 * FVS + j * 16) * 2;
                uint32_t vh0, vh1, vh2, vh3, vl0, vl1, vl2, vl3;
                LDSM4(vh0, vh1, vh2, vh3, uVh2 + vaddr);
                LDSM4(vl0, vl1, vl2, vl3, uVl2 + vaddr);
                MMA16816(oacc[2 * ntp], a0h, a1h, a2h, a3h, vh0, vh1);
                MMA16816(oacc[2 * ntp], a0h, a1h, a2h, a3h, vl0, vl1);
                MMA16816(oacc[2 * ntp], a0l, a1l, a2l, a3l, vh0, vh1);
                MMA16816(oacc[2 * ntp + 1], a0h, a1h, a2h, a3h, vh2, vh3);
                MMA16816(oacc[2 * ntp + 1], a0h, a1h, a2h, a3h, vl2, vl3);
                MMA16816(oacc[2 * ntp + 1], a0l, a1l, a2l, a3l, vh2, vh3);
            }
        }
        __syncthreads();
    }

    // ---- epilogue: add adapter contribution, emit bf16 hi/lo split ----
    float i0 = 1.f / l0, i1 = 1.f / l1;
    #pragma unroll
    for (int nto = 0; nto < 16; nto++) {
        int col = h * HDc + nto * 8 + 2 * tig;
        size_t o0 = ((size_t)(b * Sc + row0)) * Dc + col;
        size_t o1 = ((size_t)(b * Sc + row1)) * Dc + col;
        float2 ad0 = *(const float2*)&g_attn[o0];
        float2 ad1 = *(const float2*)&g_attn[o1];
        float f00 = oacc[nto][0] * i0 + ad0.x;
        float f01 = oacc[nto][1] * i0 + ad0.y;
        float f10 = oacc[nto][2] * i1 + ad1.x;
        float f11 = oacc[nto][3] * i1 + ad1.y;
        __nv_bfloat162 h0 = bsplit_hi(f00, f01);
        __nv_bfloat162 h1 = bsplit_hi(f10, f11);
        ((__nv_bfloat162*)g_xh)[o0 >> 1] = h0;
        ((__nv_bfloat162*)g_xh)[o1 >> 1] = h1;
        ((__nv_bfloat162*)g_xl)[o0 >> 1] = bsplit_lo(f00, f01, h0);
        ((__nv_bfloat162*)g_xl)[o1 >> 1] = bsplit_lo(f10, f11, h1);
    }
}

// ---------------------------------------------------------------------------
// Adapter projection, deterministic 2-pass k-split
// ---------------------------------------------------------------------------
__global__ __launch_bounds__(256) void adapter_proj_kernel(
    const float* __restrict__ A, const float* __restrict__ W,
    float* __restrict__ P)
{
    const int ks = blockIdx.x;
    const int l  = blockIdx.y;
    const int t  = threadIdx.x;
    float acc[8];
    #pragma unroll
    for (int i = 0; i < 8; i++) acc[i] = 0.f;
    for (int k = ks * 128; k < ks * 128 + 128; k++) {
        float a = A[l * Dc + k];
        const float* wr = &W[(size_t)k * Dc + t * 8];
        float4 w0 = *(const float4*)wr;
        float4 w1 = *(const float4*)(wr + 4);
        acc[0] += a * w0.x; acc[1] += a * w0.y;
        acc[2] += a * w0.z; acc[3] += a * w0.w;
        acc[4] += a * w1.x; acc[5] += a * w1.y;
        acc[6] += a * w1.z; acc[7] += a * w1.w;
    }
    float* o = &P[((size_t)l * 16 + ks) * Dc + t * 8];
    *(float4*)o       = make_float4(acc[0], acc[1], acc[2], acc[3]);
    *(float4*)(o + 4) = make_float4(acc[4], acc[5], acc[6], acc[7]);
}

__global__ __launch_bounds__(256) void adapter_reduce_kernel(
    const float* __restrict__ P, float* __restrict__ C)
{
    int idx = blockIdx.x * 256 + threadIdx.x;
    int l = idx >> 11, n = idx & 2047;
    float s = 0.f;
    #pragma unroll
    for (int ks = 0; ks < 16; ks++)
        s += P[((size_t)l * 16 + ks) * Dc + n];
    C[idx] = s;
}

// ---------------------------------------------------------------------------
// Adapter attention: one warp per (b,s,h). Writes (not RMW):
//   g_attn = gate[h] * softmax(q·akᵀ) av       (q reconstructed from qh+ql)
// ---------------------------------------------------------------------------
__global__ __launch_bounds__(256) void adapter_attn_kernel(
    const float* __restrict__ gate)
{
    int gw = (blockIdx.x * blockDim.x + threadIdx.x) >> 5;
    int lane = threadIdx.x & 31;
    if (gw >= Bc * Sc * Hc) return;
    int h = gw % Hc;
    int s = (gw / Hc) % Sc;
    int b = gw / (Hc * Sc);

    size_t qoff = ((size_t)(b * Sc + s)) * Dc + h * HDc + lane * 4;
    __nv_bfloat162 qh01 = ((const __nv_bfloat162*)g_qh)[qoff >> 1];
    __nv_bfloat162 qh23 = ((const __nv_bfloat162*)g_qh)[(qoff >> 1) + 1];
    __nv_bfloat162 ql01 = ((const __nv_bfloat162*)g_ql)[qoff >> 1];
    __nv_bfloat162 ql23 = ((const __nv_bfloat162*)g_ql)[(qoff >> 1) + 1];
    float4 q4;
    q4.x = __bfloat162float(qh01.x) + __bfloat162float(ql01.x);
    q4.y = __bfloat162float(qh01.y) + __bfloat162float(ql01.y);
    q4.z = __bfloat162float(qh23.x) + __bfloat162float(ql23.x);
    q4.w = __bfloat162float(qh23.y) + __bfloat162float(ql23.y);

    float scv[Lc];
    #pragma unroll
    for (int l = 0; l < Lc; l++) {
        float4 a4 = *(const float4*)(g_ak + (size_t)l * Dc + h * HDc + lane * 4);
        float p = q4.x * a4.x + q4.y * a4.y + q4.z * a4.z + q4.w * a4.w;
        #pragma unroll
        for (int o = 16; o > 0; o >>= 1)
            p += __shfl_xor_sync(0xffffffffu, p, o);
        scv[l] = p * SCALE;
    }
    float m = scv[0];
    #pragma unroll
    for (int l = 1; l < Lc; l++) m = fmaxf(m, scv[l]);
    float sum = 0.f;
    float e[Lc];
    #pragma unroll
    for (int l = 0; l < Lc; l++) { e[l] = expf(scv[l] - m); sum += e[l]; }
    float g = gate[h] / sum;

    float4 acc = make_float4(0.f, 0.f, 0.f, 0.f);
    #pragma unroll
    for (int l = 0; l < Lc; l++) {
        float4 a4 = *(const float4*)(g_av + (size_t)l * Dc + h * HDc + lane * 4);
        acc.x += e[l] * a4.x;
        acc.y += e[l] * a4.y;
        acc.z += e[l] * a4.z;
        acc.w += e[l] * a4.w;
    }
    float4 o4;
    o4.x = g * acc.x; o4.y = g * acc.y;
    o4.z = g * acc.z; o4.w = g * acc.w;
    *(float4*)(g_attn + qoff) = o4;
}

// ---------------------------------------------------------------------------
extern "C" void kernel_launch(void* const* d_in, const int* in_sizes, int n_in,
                              void* d_out, int out_size)
{
    const float* x       = (const float*)d_in[0];
    const float* wq      = (const float*)d_in[1];
    const float* wk      = (const float*)d_in[2];
    const float* wv      = (const float*)d_in[3];
    const float* wo      = (const float*)d_in[4];
    const float* adapter = (const float*)d_in[5];
    const float* gate    = (const float*)d_in[6];
    const float* fcos    = (const float*)d_in[7];
    const float* fsin    = (const float*)d_in[8];
    float* out = (float*)d_out;

    float *v, *ak, *av, *part;
    __nv_bfloat16 *xh, *xl, *wth, *wtl, *qh, *ql, *kh, *kl, *vth, *vtl;
    cudaGetSymbolAddress((void**)&v,    g_v);
    cudaGetSymbolAddress((void**)&ak,   g_ak);
    cudaGetSymbolAddress((void**)&av,   g_av);
    cudaGetSymbolAddress((void**)&part, g_partial);
    cudaGetSymbolAddress((void**)&xh,   g_xh);
    cudaGetSymbolAddress((void**)&xl,   g_xl);
    cudaGetSymbolAddress((void**)&wth,  g_wth);
    cudaGetSymbolAddress((void**)&wtl,  g_wtl);
    cudaGetSymbolAddress((void**)&qh,   g_qh);
    cudaGetSymbolAddress((void**)&ql,   g_ql);
    cudaGetSymbolAddress((void**)&kh,   g_kh);
    cudaGetSymbolAddress((void**)&kl,   g_kl);
    cudaGetSymbolAddress((void**)&vth,  g_vth);
    cudaGetSymbolAddress((void**)&vtl,  g_vtl);

    const int M = Bc * Sc;   // 4096

    cudaFuncSetAttribute(mma_gemm_kernel,
                         cudaFuncAttributeMaxDynamicSharedMemorySize,
                         GEMM_SMEM);
    cudaFuncSetAttribute(flash_mma_kernel,
                         cudaFuncAttributeMaxDynamicSharedMemorySize,
                         FLASH_SMEM);

    // split x -> bf16 hi/lo
    split_kernel<<<(M * Dc / 4) / 256, 256>>>(x, xh, xl);

    // stacked W^T for fused QKV projection
    wtrans3_kernel<<<dim3(Dc / 32, Dc / 32, 3), 256>>>(wq, wk, wv, wth, wtl);

    // fused QKV GEMM (N=6144): RoPE+split epilogue for Q/K, fp32 V
    mma_gemm_kernel<<<dim3(3 * Dc / 128, M / 128), 256, GEMM_SMEM>>>(
        xh, xl, wth, wtl, fcos, fsin, qh, ql, kh, kl, v, nullptr, 0, Dc);

    vtrans_kernel<<<dim3(Sc / 32, HDc / 32, Bc * Hc), 256>>>(v, vth, vtl);

    adapter_proj_kernel<<<dim3(16, Lc), 256>>>(adapter, wk, part);
    adapter_reduce_kernel<<<(Lc * Dc) / 256, 256>>>(part, ak);
    adapter_proj_kernel<<<dim3(16, Lc), 256>>>(adapter, wv, part);
    adapter_reduce_kernel<<<(Lc * Dc) / 256, 256>>>(part, av);

    // adapter contribution first (written, not accumulated)
    adapter_attn_kernel<<<(Bc * Sc * Hc * 32) / 256, 256>>>(gate);

    // flash adds adapter term in epilogue and emits xh/xl split
    flash_mma_kernel<<<dim3(Sc / 128, Hc, Bc), 256, FLASH_SMEM>>>();

    // output projection
    wtrans3_kernel<<<dim3(Dc / 32, Dc / 32, 1), 256>>>(wo, wo, wo, wth, wtl);
    mma_gemm_kernel<<<dim3(Dc / 128, M / 128), 256, GEMM_SMEM>>>(
        xh, xl, wth, wtl, fcos, fsin, nullptr, nullptr, nullptr, nullptr,
        nullptr, out, 1, Dc);
}